// round 1
// baseline (speedup 1.0000x reference)
#include <cuda_runtime.h>
#include <math.h>

// Problem constants
#define B_  2
#define KQ  1024
#define SQ  4096
#define D_  1024
#define H_  16
#define HD_ 64
#define EPSV 1e-5f

// ---------------- scratch (static device globals; no allocation) ----------------
__device__ float g_ln1[B_*KQ*D_];          // LN(q), later reused for LN_f
__device__ float g_ln2[B_*SQ*D_];          // LN(kv)
__device__ float g_Qp [B_*KQ*D_];
__device__ float g_Kp [B_*SQ*D_];
__device__ float g_Vp [B_*SQ*D_];
__device__ float g_att[B_*KQ*D_];
__device__ float g_x  [B_*KQ*D_];
__device__ float g_h1 [B_*KQ*2*D_];

// ---------------- LayerNorm: one block per row, D=1024, 256 threads ----------------
__global__ void ln_k(const float* __restrict__ x, const float* __restrict__ w,
                     const float* __restrict__ bb, float* __restrict__ y) {
    __shared__ float r0[8], r1[8];
    __shared__ float mu_s, rs_s;
    int row = blockIdx.x;
    const float* xr = x + (size_t)row * D_;
    float* yr = y + (size_t)row * D_;
    int t = threadIdx.x;
    float v[4]; float s = 0.f, s2 = 0.f;
#pragma unroll
    for (int i = 0; i < 4; i++) { float a = xr[t + i*256]; v[i] = a; s += a; s2 += a*a; }
    int lane = t & 31, wp = t >> 5;
#pragma unroll
    for (int o = 16; o; o >>= 1) {
        s  += __shfl_xor_sync(0xffffffffu, s,  o);
        s2 += __shfl_xor_sync(0xffffffffu, s2, o);
    }
    if (lane == 0) { r0[wp] = s; r1[wp] = s2; }
    __syncthreads();
    if (t == 0) {
        float ts = 0.f, t2 = 0.f;
        for (int i = 0; i < 8; i++) { ts += r0[i]; t2 += r1[i]; }
        float mu = ts * (1.f / D_);
        float var = t2 * (1.f / D_) - mu * mu;
        mu_s = mu; rs_s = rsqrtf(var + EPSV);
    }
    __syncthreads();
    float mu = mu_s, rs = rs_s;
#pragma unroll
    for (int i = 0; i < 4; i++) {
        int c = t + i*256;
        yr[c] = (v[i] - mu) * rs * w[c] + bb[c];
    }
}

// ---------------- GEMM: C[M,N] = A[M,Kd] @ W[Kd,N] + bias (+gelu / +residual) ----
__device__ __forceinline__ float gelu_f(float x) {
    return 0.5f * x * (1.f + erff(x * 0.70710678118654752f));
}

// MODE 0: bias only. MODE 1: bias + exact GELU. MODE 2: bias + residual add.
template<int MODE>
__global__ void gemm_k(const float* __restrict__ A, const float* __restrict__ W,
                       const float* __restrict__ bias, const float* __restrict__ R,
                       float* __restrict__ C, int M, int N, int Kd) {
    __shared__ float As[16][128];
    __shared__ float Bs[16][128];
    int tid = threadIdx.x;
    int tx = tid & 15, ty = tid >> 4;
    int bm = blockIdx.y, bn = blockIdx.x;
    const float* Ab = A + (size_t)bm * 128 * Kd;
    const float* Wb = W + bn * 128;
    float acc[8][8] = {};
    for (int k0 = 0; k0 < Kd; k0 += 16) {
#pragma unroll
        for (int i = 0; i < 2; i++) {
            int idx = tid + i*256;
            int r  = idx >> 2, kq = (idx & 3) << 2;
            float4 a = *(const float4*)(Ab + (size_t)r*Kd + k0 + kq);
            As[kq+0][r] = a.x; As[kq+1][r] = a.y; As[kq+2][r] = a.z; As[kq+3][r] = a.w;
            int kr = idx >> 5, c4 = (idx & 31) << 2;
            *(float4*)&Bs[kr][c4] = *(const float4*)(Wb + (size_t)(k0+kr)*N + c4);
        }
        __syncthreads();
#pragma unroll
        for (int k = 0; k < 16; k++) {
            float4 a0 = *(float4*)&As[k][ty*8];
            float4 a1 = *(float4*)&As[k][ty*8+4];
            float4 b0 = *(float4*)&Bs[k][tx*8];
            float4 b1 = *(float4*)&Bs[k][tx*8+4];
            float ra[8] = {a0.x,a0.y,a0.z,a0.w,a1.x,a1.y,a1.z,a1.w};
            float rb[8] = {b0.x,b0.y,b0.z,b0.w,b1.x,b1.y,b1.z,b1.w};
#pragma unroll
            for (int i = 0; i < 8; i++)
#pragma unroll
                for (int j = 0; j < 8; j++)
                    acc[i][j] = fmaf(ra[i], rb[j], acc[i][j]);
        }
        __syncthreads();
    }
#pragma unroll
    for (int i = 0; i < 8; i++) {
        int r = bm*128 + ty*8 + i;
#pragma unroll
        for (int j = 0; j < 8; j++) {
            int c = bn*128 + tx*8 + j;
            float v = acc[i][j] + bias[c];
            if (MODE == 1) v = gelu_f(v);
            if (MODE == 2) v += R[(size_t)r*N + c];
            C[(size_t)r*N + c] = v;
        }
    }
}

// ---------------- Flash attention with fused biases + gate ----------------
// Grid: (K/64, H, B). Block: 256 threads. Tiles: 64 q x 64 s, HD=64.
__device__ __forceinline__ float softplus_f(float x) {
    return fmaxf(x, 0.f) + log1pf(__expf(-fabsf(x)));
}

#define AP 68   // smem row pitch (pad 64 -> 68 floats, keeps 16B alignment)

__global__ void attn_k(const float* __restrict__ Qm, const float* __restrict__ Km,
                       const float* __restrict__ Vm, const float* __restrict__ abp,
                       const float* __restrict__ obp, const float* __restrict__ dens,
                       const float* __restrict__ p_dist, const float* __restrict__ p_obs,
                       const float* __restrict__ p_dens, float* __restrict__ Om) {
    extern __shared__ float sm[];
    float* Qs  = sm;                 // [64][AP]
    float* Ks  = Qs + 64*AP;
    float* Vs  = Ks + 64*AP;
    float* Ps  = Vs + 64*AP;
    float* m_s = Ps + 64*AP;
    float* l_s = m_s + 64;
    float* al_s = l_s + 64;
    float* gt_s = al_s + 64;

    int qt = blockIdx.x, h = blockIdx.y, b = blockIdx.z;
    int q0 = qt * 64;
    int tid = threadIdx.x;
    int tx = tid & 15, ty = tid >> 4;
    int lane = tid & 31, wp = tid >> 5;

    float spd = softplus_f(p_dist[0]);
    float spo = softplus_f(p_obs[0]);
    const float scale = 0.125f;  // HD^-0.5

    // load Q tile [64 rows][64 d] (head slice, float4)
#pragma unroll
    for (int it = 0; it < 4; it++) {
        int idx = tid + it*256;
        int r = idx >> 4, d4 = (idx & 15) << 2;
        *(float4*)&Qs[r*AP + d4] =
            *(const float4*)(Qm + (size_t)(b*KQ + q0 + r)*D_ + h*64 + d4);
    }
    if (tid < 64) {
        m_s[tid] = -1e30f; l_s[tid] = 0.f;
        gt_s[tid] = 1.f + tanhf(p_dens[0]) * dens[b*KQ + q0 + tid];
    }
    float o[4][4] = {};
    __syncthreads();

    for (int s0 = 0; s0 < SQ; s0 += 64) {
        // load K,V tiles
#pragma unroll
        for (int it = 0; it < 4; it++) {
            int idx = tid + it*256;
            int r = idx >> 4, d4 = (idx & 15) << 2;
            size_t g = (size_t)(b*SQ + s0 + r)*D_ + h*64 + d4;
            *(float4*)&Ks[r*AP + d4] = *(const float4*)(Km + g);
            *(float4*)&Vs[r*AP + d4] = *(const float4*)(Vm + g);
        }
        __syncthreads();

        // S = Q K^T : thread owns rows ty*4..+3, cols tx*4..+3
        float sc[4][4] = {};
#pragma unroll
        for (int d0 = 0; d0 < 64; d0 += 4) {
            float4 q4[4], k4[4];
#pragma unroll
            for (int i = 0; i < 4; i++) q4[i] = *(float4*)&Qs[(ty*4+i)*AP + d0];
#pragma unroll
            for (int j = 0; j < 4; j++) k4[j] = *(float4*)&Ks[(tx*4+j)*AP + d0];
#pragma unroll
            for (int i = 0; i < 4; i++)
#pragma unroll
                for (int j = 0; j < 4; j++)
                    sc[i][j] += q4[i].x*k4[j].x + q4[i].y*k4[j].y
                              + q4[i].z*k4[j].z + q4[i].w*k4[j].w;
        }

        // fused biases + gate -> Ps
#pragma unroll
        for (int i = 0; i < 4; i++) {
            int r = ty*4 + i;
            size_t bi = (size_t)(b*KQ + q0 + r)*SQ + s0 + tx*4;
            float4 a4 = *(const float4*)(abp + bi);
            float4 o4 = *(const float4*)(obp + bi);
            float g = gt_s[r];
            float4 pv;
            pv.x = (sc[i][0]*scale + spd*a4.x + spo*o4.x) * g;
            pv.y = (sc[i][1]*scale + spd*a4.y + spo*o4.y) * g;
            pv.z = (sc[i][2]*scale + spd*a4.z + spo*o4.z) * g;
            pv.w = (sc[i][3]*scale + spd*a4.w + spo*o4.w) * g;
            *(float4*)&Ps[r*AP + tx*4] = pv;
        }
        __syncthreads();

        // online softmax update: warp wp owns rows wp*8..+7
#pragma unroll
        for (int rr = 0; rr < 8; rr++) {
            int r = wp*8 + rr;
            float v0 = Ps[r*AP + lane], v1 = Ps[r*AP + 32 + lane];
            float mx = fmaxf(v0, v1);
#pragma unroll
            for (int o2 = 16; o2; o2 >>= 1)
                mx = fmaxf(mx, __shfl_xor_sync(0xffffffffu, mx, o2));
            float mold = m_s[r];
            float mnew = fmaxf(mold, mx);
            float e0 = __expf(v0 - mnew), e1 = __expf(v1 - mnew);
            Ps[r*AP + lane] = e0; Ps[r*AP + 32 + lane] = e1;
            float sum = e0 + e1;
#pragma unroll
            for (int o2 = 16; o2; o2 >>= 1)
                sum += __shfl_xor_sync(0xffffffffu, sum, o2);
            if (lane == 0) {
                float a = __expf(mold - mnew);
                al_s[r] = a;
                l_s[r] = l_s[r]*a + sum;
                m_s[r] = mnew;
            }
        }
        __syncthreads();

        // rescale O and accumulate O += P @ V
        float av[4];
#pragma unroll
        for (int i = 0; i < 4; i++) av[i] = al_s[ty*4 + i];
#pragma unroll
        for (int i = 0; i < 4; i++)
#pragma unroll
            for (int j = 0; j < 4; j++) o[i][j] *= av[i];

#pragma unroll
        for (int k0 = 0; k0 < 64; k0 += 4) {
            float4 p4[4], v4[4];
#pragma unroll
            for (int i = 0; i < 4; i++) p4[i] = *(float4*)&Ps[(ty*4+i)*AP + k0];
#pragma unroll
            for (int z = 0; z < 4; z++) v4[z] = *(float4*)&Vs[(k0+z)*AP + tx*4];
            float vr[4][4];
#pragma unroll
            for (int z = 0; z < 4; z++) {
                vr[z][0] = v4[z].x; vr[z][1] = v4[z].y; vr[z][2] = v4[z].z; vr[z][3] = v4[z].w;
            }
#pragma unroll
            for (int i = 0; i < 4; i++) {
                float pr[4] = {p4[i].x, p4[i].y, p4[i].z, p4[i].w};
#pragma unroll
                for (int z = 0; z < 4; z++)
#pragma unroll
                    for (int j = 0; j < 4; j++)
                        o[i][j] = fmaf(pr[z], vr[z][j], o[i][j]);
            }
        }
        __syncthreads();
    }

    // normalize + write (b,k,h,d) -> row-major [B*K, D] with head slice
#pragma unroll
    for (int i = 0; i < 4; i++) {
        int r = ty*4 + i;
        float inv = 1.f / l_s[r];
#pragma unroll
        for (int j = 0; j < 4; j++)
            Om[(size_t)(b*KQ + q0 + r)*D_ + h*64 + tx*4 + j] = o[i][j] * inv;
    }
}

#define ATT_SMEM ((4*64*AP + 4*64) * (int)sizeof(float))

// ---------------- launch ----------------
extern "C" void kernel_launch(void* const* d_in, const int* in_sizes, int n_in,
                              void* d_out, int out_size) {
    const float* q        = (const float*)d_in[0];
    const float* kv       = (const float*)d_in[1];
    const float* attn_b   = (const float*)d_in[2];
    const float* obs_b    = (const float*)d_in[3];
    const float* density  = (const float*)d_in[4];
    const float* ln_q_w   = (const float*)d_in[5];
    const float* ln_q_b   = (const float*)d_in[6];
    const float* ln_kv_w  = (const float*)d_in[7];
    const float* ln_kv_b  = (const float*)d_in[8];
    const float* wq = (const float*)d_in[9];  const float* bq = (const float*)d_in[10];
    const float* wk = (const float*)d_in[11]; const float* bk = (const float*)d_in[12];
    const float* wv = (const float*)d_in[13]; const float* bv = (const float*)d_in[14];
    const float* wo = (const float*)d_in[15]; const float* bo = (const float*)d_in[16];
    const float* dist_raw = (const float*)d_in[17];
    const float* obs_raw  = (const float*)d_in[18];
    const float* dens_raw = (const float*)d_in[19];
    const float* ln_f_w = (const float*)d_in[20]; const float* ln_f_b = (const float*)d_in[21];
    const float* w1 = (const float*)d_in[22]; const float* b1 = (const float*)d_in[23];
    const float* w2 = (const float*)d_in[24]; const float* b2 = (const float*)d_in[25];
    float* out = (float*)d_out;

    float *ln1, *ln2, *Qp, *Kp, *Vp, *att, *x, *h1;
    cudaGetSymbolAddress((void**)&ln1, g_ln1);
    cudaGetSymbolAddress((void**)&ln2, g_ln2);
    cudaGetSymbolAddress((void**)&Qp,  g_Qp);
    cudaGetSymbolAddress((void**)&Kp,  g_Kp);
    cudaGetSymbolAddress((void**)&Vp,  g_Vp);
    cudaGetSymbolAddress((void**)&att, g_att);
    cudaGetSymbolAddress((void**)&x,   g_x);
    cudaGetSymbolAddress((void**)&h1,  g_h1);

    // 1) LayerNorms
    ln_k<<<B_*KQ, 256>>>(q,  ln_q_w,  ln_q_b,  ln1);
    ln_k<<<B_*SQ, 256>>>(kv, ln_kv_w, ln_kv_b, ln2);

    // 2) Q/K/V projections
    gemm_k<0><<<dim3(8, 16), 256>>>(ln1, wq, bq, nullptr, Qp, B_*KQ, D_, D_);
    gemm_k<0><<<dim3(8, 64), 256>>>(ln2, wk, bk, nullptr, Kp, B_*SQ, D_, D_);
    gemm_k<0><<<dim3(8, 64), 256>>>(ln2, wv, bv, nullptr, Vp, B_*SQ, D_, D_);

    // 3) fused attention (biases + gate + online softmax)
    cudaFuncSetAttribute(attn_k, cudaFuncAttributeMaxDynamicSharedMemorySize, ATT_SMEM);
    attn_k<<<dim3(KQ/64, H_, B_), 256, ATT_SMEM>>>(
        Qp, Kp, Vp, attn_b, obs_b, density, dist_raw, obs_raw, dens_raw, att);

    // 4) O projection + residual: x = q + att @ wo + bo
    gemm_k<2><<<dim3(8, 16), 256>>>(att, wo, bo, q, x, B_*KQ, D_, D_);

    // 5) final LN + MLP (GELU fused; residual fused into last GEMM -> d_out)
    ln_k<<<B_*KQ, 256>>>(x, ln_f_w, ln_f_b, ln1);
    gemm_k<1><<<dim3(16, 16), 256>>>(ln1, w1, b1, nullptr, h1, B_*KQ, 2*D_, D_);
    gemm_k<2><<<dim3(8, 16), 256>>>(h1, w2, b2, x, out, B_*KQ, D_, 2*D_);
}

// round 4
// speedup vs baseline: 1.2941x; 1.2941x over previous
#include <cuda_runtime.h>
#include <cuda_bf16.h>
#include <math.h>
#include <cstdint>

typedef __nv_bfloat16 bf16;

// Problem constants
#define B_  2
#define KQ  1024
#define SQ  4096
#define D_  1024
#define H_  16
#define HD_ 64
#define EPSV 1e-5f

// ================= scratch (static device globals) =================
__device__ float g_Qp [B_*KQ*D_];
__device__ float g_Kp [B_*SQ*D_];
__device__ float g_Vp [B_*SQ*D_];
__device__ float g_x  [B_*KQ*D_];
__device__ float g_biasc[B_*KQ*SQ];

__device__ bf16 g_lnq_h[B_*KQ*D_],  g_lnq_l[B_*KQ*D_];
__device__ bf16 g_lnkv_h[B_*SQ*D_], g_lnkv_l[B_*SQ*D_];
__device__ bf16 g_att_h[B_*KQ*D_],  g_att_l[B_*KQ*D_];
__device__ bf16 g_h1_h[B_*KQ*2*D_], g_h1_l[B_*KQ*2*D_];
__device__ bf16 g_wqt_h[D_*D_],   g_wqt_l[D_*D_];
__device__ bf16 g_wkt_h[D_*D_],   g_wkt_l[D_*D_];
__device__ bf16 g_wvt_h[D_*D_],   g_wvt_l[D_*D_];
__device__ bf16 g_wot_h[D_*D_],   g_wot_l[D_*D_];
__device__ bf16 g_w1t_h[2*D_*D_], g_w1t_l[2*D_*D_];
__device__ bf16 g_w2t_h[2*D_*D_], g_w2t_l[2*D_*D_];

__device__ __forceinline__ float softplus_f(float x) {
    return fmaxf(x, 0.f) + log1pf(__expf(-fabsf(x)));
}
__device__ __forceinline__ float gelu_f(float x) {
    return 0.5f * x * (1.f + erff(x * 0.70710678118654752f));
}
__device__ __forceinline__ void split_store(bf16* hi, bf16* lo, size_t idx, float v) {
    bf16 h = __float2bfloat16(v);
    hi[idx] = h;
    lo[idx] = __float2bfloat16(v - __bfloat162float(h));
}
__device__ __forceinline__ uint32_t smem_to_u32(const void* p) {
    uint32_t a;
    asm("{ .reg .u64 t; cvta.to.shared.u64 t, %1; cvt.u32.u64 %0, t; }" : "=r"(a) : "l"(p));
    return a;
}

// cp.async helpers (sm_80 baseline)
#define CP_ASYNC16(dst, src) \
    asm volatile("cp.async.cg.shared.global [%0], [%1], 16;" :: "r"(dst), "l"(src))
#define CP_COMMIT() asm volatile("cp.async.commit_group;" ::: "memory")
#define CP_WAIT1()  asm volatile("cp.async.wait_group 1;" ::: "memory")
#define CP_WAIT0()  asm volatile("cp.async.wait_group 0;" ::: "memory")

// ldmatrix x4 (sm_75 baseline)
#define LDSM_X4(r0, r1, r2, r3, addr) \
    asm volatile("ldmatrix.sync.aligned.m8n8.x4.shared.b16 {%0,%1,%2,%3}, [%4];" \
        : "=r"(r0), "=r"(r1), "=r"(r2), "=r"(r3) : "r"(addr))

// mma m16n8k16 bf16 (sm_80 baseline)
#define MMA_16816(c, a, b) \
    asm volatile("mma.sync.aligned.m16n8k16.row.col.f32.bf16.bf16.f32 " \
        "{%0,%1,%2,%3}, {%4,%5,%6,%7}, {%8,%9}, {%0,%1,%2,%3};" \
        : "+f"((c)[0]), "+f"((c)[1]), "+f"((c)[2]), "+f"((c)[3]) \
        : "r"((a)[0]), "r"((a)[1]), "r"((a)[2]), "r"((a)[3]), "r"((b)[0]), "r"((b)[1]))

// ================= LayerNorm -> hi/lo bf16 =================
__global__ void ln_k(const float* __restrict__ x, const float* __restrict__ w,
                     const float* __restrict__ bb, bf16* __restrict__ yh, bf16* __restrict__ yl) {
    __shared__ float r0[8], r1[8];
    __shared__ float mu_s, rs_s;
    int row = blockIdx.x;
    const float* xr = x + (size_t)row * D_;
    int t = threadIdx.x;
    float v[4]; float s = 0.f, s2 = 0.f;
#pragma unroll
    for (int i = 0; i < 4; i++) { float a = xr[t + i*256]; v[i] = a; s += a; s2 += a*a; }
    int lane = t & 31, wp = t >> 5;
#pragma unroll
    for (int o = 16; o; o >>= 1) {
        s  += __shfl_xor_sync(0xffffffffu, s,  o);
        s2 += __shfl_xor_sync(0xffffffffu, s2, o);
    }
    if (lane == 0) { r0[wp] = s; r1[wp] = s2; }
    __syncthreads();
    if (t == 0) {
        float ts = 0.f, t2 = 0.f;
        for (int i = 0; i < 8; i++) { ts += r0[i]; t2 += r1[i]; }
        float mu = ts * (1.f / D_);
        float var = t2 * (1.f / D_) - mu * mu;
        mu_s = mu; rs_s = rsqrtf(var + EPSV);
    }
    __syncthreads();
    float mu = mu_s, rs = rs_s;
#pragma unroll
    for (int i = 0; i < 4; i++) {
        int c = t + i*256;
        float yv = (v[i] - mu) * rs * w[c] + bb[c];
        split_store(yh, yl, (size_t)row * D_ + c, yv);
    }
}

// ================= weight transpose + split: Wt[n][k] = W[k][n] =================
struct WArgs {
    const float* src[6];
    bf16* dh[6]; bf16* dl[6];
    int K[6]; int N[6];
};
__global__ void convw_k(WArgs a) {
    int w = blockIdx.z;
    int Kd = a.K[w], Nd = a.N[w];
    int n0 = blockIdx.x * 32, k0 = blockIdx.y * 32;
    if (n0 >= Nd || k0 >= Kd) return;
    __shared__ float t[32][33];
    int tx = threadIdx.x, ty = threadIdx.y;
    const float* s = a.src[w];
#pragma unroll
    for (int i = 0; i < 4; i++)
        t[ty + i*8][tx] = s[(size_t)(k0 + ty + i*8) * Nd + n0 + tx];
    __syncthreads();
#pragma unroll
    for (int i = 0; i < 4; i++) {
        float v = t[tx][ty + i*8];
        split_store(a.dh[w], a.dl[w], (size_t)(n0 + ty + i*8) * Kd + k0 + tx, v);
    }
}

// ================= combined bias prepass =================
__global__ void biasprep_k(const float* __restrict__ ab, const float* __restrict__ ob,
                           const float* __restrict__ pd, const float* __restrict__ po,
                           float* __restrict__ out) {
    int i = blockIdx.x * blockDim.x + threadIdx.x;
    float spd = softplus_f(pd[0]);
    float spo = softplus_f(po[0]);
    float4 a = ((const float4*)ab)[i];
    float4 o = ((const float4*)ob)[i];
    float4 r;
    r.x = spd*a.x + spo*o.x; r.y = spd*a.y + spo*o.y;
    r.z = spd*a.z + spo*o.z; r.w = spd*a.w + spo*o.w;
    ((float4*)out)[i] = r;
}

// ================= HMMA split-bf16 GEMM =================
// C[M,N] = A @ W + bias.  A = Ahi+Alo bf16 pair [M,Kd] row-major.
// W transposed+split: Bhi/Blo = Wt [N,Kd] row-major (k contiguous = col-major k x n).
// 3 accumulate passes: hi*hi, hi*lo, lo*hi.
// MODE 0: -> Cf fp32.  MODE 1: gelu -> Chi/Clo bf16.  MODE 2: +R -> Cf fp32.
// Block 256 thr (8 warps, 4x2), BM=128, BN=128, BK=32. Warp tile 32x64.
#define GPAD 40   // smem row pitch in bf16 (80 B) — conflict-free for ldmatrix

template<int MODE>
__global__ void __launch_bounds__(256) gemm_mma_k(
        const bf16* __restrict__ Ahi, const bf16* __restrict__ Alo,
        const bf16* __restrict__ Bhi, const bf16* __restrict__ Blo,
        const float* __restrict__ bias, const float* __restrict__ R,
        float* __restrict__ Cf, bf16* __restrict__ Chi, bf16* __restrict__ Clo,
        int M, int N, int Kd) {
    __shared__ bf16 As[2][128*GPAD];
    __shared__ bf16 Bs[2][128*GPAD];
    int tid = threadIdx.x, lane = tid & 31, wid = tid >> 5;
    int wm = wid & 3, wn = wid >> 2;
    int n0 = blockIdx.x * 128, m0 = blockIdx.y * 128;
    uint32_t sA = smem_to_u32(As);
    uint32_t sB = smem_to_u32(Bs);

    float c[2][8][4];
#pragma unroll
    for (int i = 0; i < 2; i++)
#pragma unroll
        for (int j = 0; j < 8; j++)
#pragma unroll
            for (int q = 0; q < 4; q++) c[i][j][q] = 0.f;

    int nch = Kd >> 5;
    int total = 3 * nch;
    int lr = tid >> 2;               // 0..63
    int ls = (tid & 3) << 3;         // 0,8,16,24

    // ---- prefetch chunk `ch` into buffer `buf` ----
    auto prefetch = [&](int ch, int buf) {
        int pass = ch / nch;
        int kc = (ch - pass * nch) << 5;
        const bf16* Ag = (pass == 2) ? Alo : Ahi;
        const bf16* Bg = (pass == 1) ? Blo : Bhi;
        uint32_t da = sA + (uint32_t)(buf * 128*GPAD) * 2;
        uint32_t db = sB + (uint32_t)(buf * 128*GPAD) * 2;
        CP_ASYNC16(da + (lr*GPAD + ls)*2,        Ag + (size_t)(m0 + lr)      * Kd + kc + ls);
        CP_ASYNC16(da + ((lr+64)*GPAD + ls)*2,   Ag + (size_t)(m0 + lr + 64) * Kd + kc + ls);
        CP_ASYNC16(db + (lr*GPAD + ls)*2,        Bg + (size_t)(n0 + lr)      * Kd + kc + ls);
        CP_ASYNC16(db + ((lr+64)*GPAD + ls)*2,   Bg + (size_t)(n0 + lr + 64) * Kd + kc + ls);
    };

    prefetch(0, 0);
    CP_COMMIT();

    for (int it = 0; it < total; ++it) {
        int cur = it & 1;
        if (it + 1 < total) { prefetch(it + 1, cur ^ 1); CP_COMMIT(); CP_WAIT1(); }
        else                { CP_WAIT0(); }
        __syncthreads();

        uint32_t baseA = sA + (uint32_t)(cur * 128*GPAD) * 2;
        uint32_t baseB = sB + (uint32_t)(cur * 128*GPAD) * 2;
#pragma unroll
        for (int kk = 0; kk < 32; kk += 16) {
            uint32_t a[2][4];
#pragma unroll
            for (int mi = 0; mi < 2; mi++) {
                int row = wm*32 + mi*16 + ((lane >> 3) & 1)*8 + (lane & 7);
                int col = kk + (lane >> 4)*8;
                uint32_t addr = baseA + (uint32_t)(row*GPAD + col)*2;
                LDSM_X4(a[mi][0], a[mi][1], a[mi][2], a[mi][3], addr);
            }
            uint32_t b[8][2];
#pragma unroll
            for (int g = 0; g < 4; g++) {
                int row = wn*64 + g*16 + (lane >> 4)*8 + (lane & 7);
                int col = kk + ((lane >> 3) & 1)*8;
                uint32_t addr = baseB + (uint32_t)(row*GPAD + col)*2;
                uint32_t r0, r1, r2, r3;
                LDSM_X4(r0, r1, r2, r3, addr);
                b[2*g][0] = r0; b[2*g][1] = r1;
                b[2*g+1][0] = r2; b[2*g+1][1] = r3;
            }
#pragma unroll
            for (int mi = 0; mi < 2; mi++)
#pragma unroll
                for (int ni = 0; ni < 8; ni++)
                    MMA_16816(c[mi][ni], a[mi], b[ni]);
        }
        __syncthreads();
    }

    // ---- epilogue ----
#pragma unroll
    for (int mi = 0; mi < 2; mi++) {
#pragma unroll
        for (int half = 0; half < 2; half++) {
            int row = m0 + wm*32 + mi*16 + half*8 + (lane >> 2);
#pragma unroll
            for (int ni = 0; ni < 8; ni++) {
                int col = n0 + wn*64 + ni*8 + (lane & 3)*2;
                float v0 = c[mi][ni][half*2 + 0] + bias[col];
                float v1 = c[mi][ni][half*2 + 1] + bias[col + 1];
                size_t idx = (size_t)row * N + col;
                if (MODE == 1) {
                    v0 = gelu_f(v0); v1 = gelu_f(v1);
                    split_store(Chi, Clo, idx, v0);
                    split_store(Chi, Clo, idx + 1, v1);
                } else {
                    if (MODE == 2) {
                        float2 r2 = *(const float2*)(R + idx);
                        v0 += r2.x; v1 += r2.y;
                    }
                    float2 o2; o2.x = v0; o2.y = v1;
                    *(float2*)(Cf + idx) = o2;
                }
            }
        }
    }
}

// ================= Flash attention (combined bias, hi/lo bf16 out) =================
#define AP 68

__global__ void attn_k(const float* __restrict__ Qm, const float* __restrict__ Km,
                       const float* __restrict__ Vm, const float* __restrict__ bcp,
                       const float* __restrict__ dens, const float* __restrict__ p_dens,
                       bf16* __restrict__ Oh, bf16* __restrict__ Ol) {
    extern __shared__ float sm[];
    float* Qs  = sm;
    float* Ks  = Qs + 64*AP;
    float* Vs  = Ks + 64*AP;
    float* Ps  = Vs + 64*AP;
    float* m_s = Ps + 64*AP;
    float* l_s = m_s + 64;
    float* al_s = l_s + 64;
    float* gt_s = al_s + 64;

    int qt = blockIdx.x, h = blockIdx.y, b = blockIdx.z;
    int q0 = qt * 64;
    int tid = threadIdx.x;
    int tx = tid & 15, ty = tid >> 4;
    int lane = tid & 31, wp = tid >> 5;
    const float scale = 0.125f;

#pragma unroll
    for (int it = 0; it < 4; it++) {
        int idx = tid + it*256;
        int r = idx >> 4, d4 = (idx & 15) << 2;
        *(float4*)&Qs[r*AP + d4] =
            *(const float4*)(Qm + (size_t)(b*KQ + q0 + r)*D_ + h*64 + d4);
    }
    if (tid < 64) {
        m_s[tid] = -1e30f; l_s[tid] = 0.f;
        gt_s[tid] = 1.f + tanhf(p_dens[0]) * dens[b*KQ + q0 + tid];
    }
    float o[4][4] = {};
    __syncthreads();

    for (int s0 = 0; s0 < SQ; s0 += 64) {
#pragma unroll
        for (int it = 0; it < 4; it++) {
            int idx = tid + it*256;
            int r = idx >> 4, d4 = (idx & 15) << 2;
            size_t g = (size_t)(b*SQ + s0 + r)*D_ + h*64 + d4;
            *(float4*)&Ks[r*AP + d4] = *(const float4*)(Km + g);
            *(float4*)&Vs[r*AP + d4] = *(const float4*)(Vm + g);
        }
        __syncthreads();

        float sc[4][4] = {};
#pragma unroll
        for (int d0 = 0; d0 < 64; d0 += 4) {
            float4 q4[4], k4[4];
#pragma unroll
            for (int i = 0; i < 4; i++) q4[i] = *(float4*)&Qs[(ty*4+i)*AP + d0];
#pragma unroll
            for (int j = 0; j < 4; j++) k4[j] = *(float4*)&Ks[(tx*4+j)*AP + d0];
#pragma unroll
            for (int i = 0; i < 4; i++)
#pragma unroll
                for (int j = 0; j < 4; j++)
                    sc[i][j] += q4[i].x*k4[j].x + q4[i].y*k4[j].y
                              + q4[i].z*k4[j].z + q4[i].w*k4[j].w;
        }

#pragma unroll
        for (int i = 0; i < 4; i++) {
            int r = ty*4 + i;
            size_t bi = (size_t)(b*KQ + q0 + r)*SQ + s0 + tx*4;
            float4 b4 = *(const float4*)(bcp + bi);
            float g = gt_s[r];
            float4 pv;
            pv.x = (sc[i][0]*scale + b4.x) * g;
            pv.y = (sc[i][1]*scale + b4.y) * g;
            pv.z = (sc[i][2]*scale + b4.z) * g;
            pv.w = (sc[i][3]*scale + b4.w) * g;
            *(float4*)&Ps[r*AP + tx*4] = pv;
        }
        __syncthreads();

#pragma unroll
        for (int rr = 0; rr < 8; rr++) {
            int r = wp*8 + rr;
            float v0 = Ps[r*AP + lane], v1 = Ps[r*AP + 32 + lane];
            float mx = fmaxf(v0, v1);
#pragma unroll
            for (int o2 = 16; o2; o2 >>= 1)
                mx = fmaxf(mx, __shfl_xor_sync(0xffffffffu, mx, o2));
            float mold = m_s[r];
            float mnew = fmaxf(mold, mx);
            float e0 = __expf(v0 - mnew), e1 = __expf(v1 - mnew);
            Ps[r*AP + lane] = e0; Ps[r*AP + 32 + lane] = e1;
            float sum = e0 + e1;
#pragma unroll
            for (int o2 = 16; o2; o2 >>= 1)
                sum += __shfl_xor_sync(0xffffffffu, sum, o2);
            if (lane == 0) {
                float a = __expf(mold - mnew);
                al_s[r] = a;
                l_s[r] = l_s[r]*a + sum;
                m_s[r] = mnew;
            }
        }
        __syncthreads();

        float av[4];
#pragma unroll
        for (int i = 0; i < 4; i++) av[i] = al_s[ty*4 + i];
#pragma unroll
        for (int i = 0; i < 4; i++)
#pragma unroll
            for (int j = 0; j < 4; j++) o[i][j] *= av[i];

#pragma unroll
        for (int k0 = 0; k0 < 64; k0 += 4) {
            float4 p4[4], v4[4];
#pragma unroll
            for (int i = 0; i < 4; i++) p4[i] = *(float4*)&Ps[(ty*4+i)*AP + k0];
#pragma unroll
            for (int z = 0; z < 4; z++) v4[z] = *(float4*)&Vs[(k0+z)*AP + tx*4];
            float vr[4][4];
#pragma unroll
            for (int z = 0; z < 4; z++) {
                vr[z][0] = v4[z].x; vr[z][1] = v4[z].y; vr[z][2] = v4[z].z; vr[z][3] = v4[z].w;
            }
#pragma unroll
            for (int i = 0; i < 4; i++) {
                float pr[4] = {p4[i].x, p4[i].y, p4[i].z, p4[i].w};
#pragma unroll
                for (int z = 0; z < 4; z++)
#pragma unroll
                    for (int j = 0; j < 4; j++)
                        o[i][j] = fmaf(pr[z], vr[z][j], o[i][j]);
            }
        }
        __syncthreads();
    }

#pragma unroll
    for (int i = 0; i < 4; i++) {
        int r = ty*4 + i;
        float inv = 1.f / l_s[r];
#pragma unroll
        for (int j = 0; j < 4; j++) {
            size_t idx = (size_t)(b*KQ + q0 + r)*D_ + h*64 + tx*4 + j;
            split_store(Oh, Ol, idx, o[i][j] * inv);
        }
    }
}

#define ATT_SMEM ((4*64*AP + 4*64) * (int)sizeof(float))

// ================= launch =================
extern "C" void kernel_launch(void* const* d_in, const int* in_sizes, int n_in,
                              void* d_out, int out_size) {
    const float* q        = (const float*)d_in[0];
    const float* kv       = (const float*)d_in[1];
    const float* attn_b   = (const float*)d_in[2];
    const float* obs_b    = (const float*)d_in[3];
    const float* density  = (const float*)d_in[4];
    const float* ln_q_w   = (const float*)d_in[5];
    const float* ln_q_b   = (const float*)d_in[6];
    const float* ln_kv_w  = (const float*)d_in[7];
    const float* ln_kv_b  = (const float*)d_in[8];
    const float* wq = (const float*)d_in[9];  const float* bq = (const float*)d_in[10];
    const float* wk = (const float*)d_in[11]; const float* bk = (const float*)d_in[12];
    const float* wv = (const float*)d_in[13]; const float* bv = (const float*)d_in[14];
    const float* wo = (const float*)d_in[15]; const float* bo = (const float*)d_in[16];
    const float* dist_raw = (const float*)d_in[17];
    const float* obs_raw  = (const float*)d_in[18];
    const float* dens_raw = (const float*)d_in[19];
    const float* ln_f_w = (const float*)d_in[20]; const float* ln_f_b = (const float*)d_in[21];
    const float* w1 = (const float*)d_in[22]; const float* b1 = (const float*)d_in[23];
    const float* w2 = (const float*)d_in[24]; const float* b2 = (const float*)d_in[25];
    float* out = (float*)d_out;

    float *Qp, *Kp, *Vp, *x, *biasc;
    cudaGetSymbolAddress((void**)&Qp,  g_Qp);
    cudaGetSymbolAddress((void**)&Kp,  g_Kp);
    cudaGetSymbolAddress((void**)&Vp,  g_Vp);
    cudaGetSymbolAddress((void**)&x,   g_x);
    cudaGetSymbolAddress((void**)&biasc, g_biasc);
    bf16 *lnq_h, *lnq_l, *lnkv_h, *lnkv_l, *att_h, *att_l, *h1_h, *h1_l;
    cudaGetSymbolAddress((void**)&lnq_h, g_lnq_h);   cudaGetSymbolAddress((void**)&lnq_l, g_lnq_l);
    cudaGetSymbolAddress((void**)&lnkv_h, g_lnkv_h); cudaGetSymbolAddress((void**)&lnkv_l, g_lnkv_l);
    cudaGetSymbolAddress((void**)&att_h, g_att_h);   cudaGetSymbolAddress((void**)&att_l, g_att_l);
    cudaGetSymbolAddress((void**)&h1_h, g_h1_h);     cudaGetSymbolAddress((void**)&h1_l, g_h1_l);
    bf16 *wt_h[6], *wt_l[6];
    cudaGetSymbolAddress((void**)&wt_h[0], g_wqt_h); cudaGetSymbolAddress((void**)&wt_l[0], g_wqt_l);
    cudaGetSymbolAddress((void**)&wt_h[1], g_wkt_h); cudaGetSymbolAddress((void**)&wt_l[1], g_wkt_l);
    cudaGetSymbolAddress((void**)&wt_h[2], g_wvt_h); cudaGetSymbolAddress((void**)&wt_l[2], g_wvt_l);
    cudaGetSymbolAddress((void**)&wt_h[3], g_wot_h); cudaGetSymbolAddress((void**)&wt_l[3], g_wot_l);
    cudaGetSymbolAddress((void**)&wt_h[4], g_w1t_h); cudaGetSymbolAddress((void**)&wt_l[4], g_w1t_l);
    cudaGetSymbolAddress((void**)&wt_h[5], g_w2t_h); cudaGetSymbolAddress((void**)&wt_l[5], g_w2t_l);

    cudaFuncSetAttribute(attn_k, cudaFuncAttributeMaxDynamicSharedMemorySize, ATT_SMEM);

    // [0] weight transpose+split (all 6 weights)
    WArgs wa;
    wa.src[0] = wq; wa.src[1] = wk; wa.src[2] = wv; wa.src[3] = wo; wa.src[4] = w1; wa.src[5] = w2;
    for (int i = 0; i < 6; i++) { wa.dh[i] = wt_h[i]; wa.dl[i] = wt_l[i]; }
    wa.K[0]=1024; wa.K[1]=1024; wa.K[2]=1024; wa.K[3]=1024; wa.K[4]=1024; wa.K[5]=2048;
    wa.N[0]=1024; wa.N[1]=1024; wa.N[2]=1024; wa.N[3]=1024; wa.N[4]=2048; wa.N[5]=1024;
    convw_k<<<dim3(64, 64, 6), dim3(32, 8)>>>(wa);

    // [1][2] LayerNorms -> hi/lo bf16
    ln_k<<<B_*KQ, 256>>>(q,  ln_q_w,  ln_q_b,  lnq_h,  lnq_l);
    ln_k<<<B_*SQ, 256>>>(kv, ln_kv_w, ln_kv_b, lnkv_h, lnkv_l);

    // [3][4][5] Q/K/V projections (HMMA) -> fp32
    gemm_mma_k<0><<<dim3(8, 16), 256>>>(lnq_h,  lnq_l,  wt_h[0], wt_l[0], bq, nullptr,
                                        Qp, nullptr, nullptr, B_*KQ, D_, D_);
    gemm_mma_k<0><<<dim3(8, 64), 256>>>(lnkv_h, lnkv_l, wt_h[1], wt_l[1], bk, nullptr,
                                        Kp, nullptr, nullptr, B_*SQ, D_, D_);
    gemm_mma_k<0><<<dim3(8, 64), 256>>>(lnkv_h, lnkv_l, wt_h[2], wt_l[2], bv, nullptr,
                                        Vp, nullptr, nullptr, B_*SQ, D_, D_);

    // [6] combined bias prepass
    biasprep_k<<<(B_*KQ*SQ)/4/256, 256>>>(attn_b, obs_b, dist_raw, obs_raw, biasc);

    // [7] fused attention -> att hi/lo bf16
    attn_k<<<dim3(KQ/64, H_, B_), 256, ATT_SMEM>>>(Qp, Kp, Vp, biasc, density, dens_raw,
                                                   att_h, att_l);

    // [8] O projection + residual: x = q + att @ wo + bo
    gemm_mma_k<2><<<dim3(8, 16), 256>>>(att_h, att_l, wt_h[3], wt_l[3], bo, q,
                                        x, nullptr, nullptr, B_*KQ, D_, D_);

    // [9] final LN (reuse lnq buffers)
    ln_k<<<B_*KQ, 256>>>(x, ln_f_w, ln_f_b, lnq_h, lnq_l);

    // [10] MLP1 with GELU -> h1 hi/lo bf16
    gemm_mma_k<1><<<dim3(16, 16), 256>>>(lnq_h, lnq_l, wt_h[4], wt_l[4], b1, nullptr,
                                         nullptr, h1_h, h1_l, B_*KQ, 2*D_, D_);

    // [11] MLP2 + residual -> out
    gemm_mma_k<2><<<dim3(8, 16), 256>>>(h1_h, h1_l, wt_h[5], wt_l[5], b2, x,
                                        out, nullptr, nullptr, B_*KQ, D_, 2*D_);
}

// round 5
// speedup vs baseline: 2.6320x; 2.0338x over previous
#include <cuda_runtime.h>
#include <cuda_bf16.h>
#include <math.h>
#include <cstdint>

typedef __nv_bfloat16 bf16;

// Problem constants
#define B_  2
#define KQ  1024
#define SQ  4096
#define D_  1024
#define H_  16
#define HD_ 64
#define EPSV 1e-5f

// ================= scratch (static device globals) =================
__device__ float g_x  [B_*KQ*D_];
__device__ float g_biasc[B_*KQ*SQ];

__device__ bf16 g_lnq_h[B_*KQ*D_],  g_lnq_l[B_*KQ*D_];
__device__ bf16 g_lnkv_h[B_*SQ*D_], g_lnkv_l[B_*SQ*D_];
__device__ bf16 g_Qh[B_*KQ*D_],  g_Ql[B_*KQ*D_];
__device__ bf16 g_Kh[B_*SQ*D_],  g_Kl[B_*SQ*D_];
__device__ bf16 g_Vh[B_*SQ*D_],  g_Vl[B_*SQ*D_];
__device__ bf16 g_att_h[B_*KQ*D_],  g_att_l[B_*KQ*D_];
__device__ bf16 g_h1_h[B_*KQ*2*D_], g_h1_l[B_*KQ*2*D_];
__device__ bf16 g_wqt_h[D_*D_],   g_wqt_l[D_*D_];
__device__ bf16 g_wkt_h[D_*D_],   g_wkt_l[D_*D_];
__device__ bf16 g_wvt_h[D_*D_],   g_wvt_l[D_*D_];
__device__ bf16 g_wot_h[D_*D_],   g_wot_l[D_*D_];
__device__ bf16 g_w1t_h[2*D_*D_], g_w1t_l[2*D_*D_];
__device__ bf16 g_w2t_h[2*D_*D_], g_w2t_l[2*D_*D_];

__device__ __forceinline__ float softplus_f(float x) {
    return fmaxf(x, 0.f) + log1pf(__expf(-fabsf(x)));
}
__device__ __forceinline__ float gelu_f(float x) {
    return 0.5f * x * (1.f + erff(x * 0.70710678118654752f));
}
__device__ __forceinline__ void split_store(bf16* hi, bf16* lo, size_t idx, float v) {
    bf16 h = __float2bfloat16(v);
    hi[idx] = h;
    lo[idx] = __float2bfloat16(v - __bfloat162float(h));
}
__device__ __forceinline__ uint32_t smem_to_u32(const void* p) {
    uint32_t a;
    asm("{ .reg .u64 t; cvta.to.shared.u64 t, %1; cvt.u32.u64 %0, t; }" : "=r"(a) : "l"(p));
    return a;
}

// FMA-pipe exp (no MUFU): e^x for x <= 0, clamped at -87
__device__ __forceinline__ float exp_fast(float x) {
    float y = fmaxf(x, -87.0f) * 1.44269504f;
    float r = rintf(y);
    float f = y - r;
    float p = 1.3333558146e-3f;
    p = fmaf(p, f, 9.6181291076e-3f);
    p = fmaf(p, f, 5.5504108665e-2f);
    p = fmaf(p, f, 2.4022650696e-1f);
    p = fmaf(p, f, 6.9314718056e-1f);
    p = fmaf(p, f, 1.0f);
    return __int_as_float(((int)r + 127) << 23) * p;
}

__device__ __forceinline__ uint32_t cvt2_bf16(float lo, float hi) {
    uint32_t r; asm("cvt.rn.bf16x2.f32 %0, %1, %2;" : "=r"(r) : "f"(hi), "f"(lo)); return r;
}
__device__ __forceinline__ float lo_bf16f(uint32_t p) { return __uint_as_float(p << 16); }
__device__ __forceinline__ float hi_bf16f(uint32_t p) { return __uint_as_float(p & 0xFFFF0000u); }

// cp.async helpers
#define CP_ASYNC16(dst, src) \
    asm volatile("cp.async.cg.shared.global [%0], [%1], 16;" :: "r"(dst), "l"(src))
#define CP_COMMIT() asm volatile("cp.async.commit_group;" ::: "memory")
#define CP_WAIT1()  asm volatile("cp.async.wait_group 1;" ::: "memory")
#define CP_WAIT0()  asm volatile("cp.async.wait_group 0;" ::: "memory")

#define LDSM_X4(r0, r1, r2, r3, addr) \
    asm volatile("ldmatrix.sync.aligned.m8n8.x4.shared.b16 {%0,%1,%2,%3}, [%4];" \
        : "=r"(r0), "=r"(r1), "=r"(r2), "=r"(r3) : "r"(addr))
#define LDSM_X4_T(r0, r1, r2, r3, addr) \
    asm volatile("ldmatrix.sync.aligned.m8n8.x4.trans.shared.b16 {%0,%1,%2,%3}, [%4];" \
        : "=r"(r0), "=r"(r1), "=r"(r2), "=r"(r3) : "r"(addr))

#define MMA_16816(c, a, b) \
    asm volatile("mma.sync.aligned.m16n8k16.row.col.f32.bf16.bf16.f32 " \
        "{%0,%1,%2,%3}, {%4,%5,%6,%7}, {%8,%9}, {%0,%1,%2,%3};" \
        : "+f"((c)[0]), "+f"((c)[1]), "+f"((c)[2]), "+f"((c)[3]) \
        : "r"((a)[0]), "r"((a)[1]), "r"((a)[2]), "r"((a)[3]), "r"((b)[0]), "r"((b)[1]))

// ================= LayerNorm -> hi/lo bf16 =================
__global__ void ln_k(const float* __restrict__ x, const float* __restrict__ w,
                     const float* __restrict__ bb, bf16* __restrict__ yh, bf16* __restrict__ yl) {
    __shared__ float r0[8], r1[8];
    __shared__ float mu_s, rs_s;
    int row = blockIdx.x;
    const float* xr = x + (size_t)row * D_;
    int t = threadIdx.x;
    float v[4]; float s = 0.f, s2 = 0.f;
#pragma unroll
    for (int i = 0; i < 4; i++) { float a = xr[t + i*256]; v[i] = a; s += a; s2 += a*a; }
    int lane = t & 31, wp = t >> 5;
#pragma unroll
    for (int o = 16; o; o >>= 1) {
        s  += __shfl_xor_sync(0xffffffffu, s,  o);
        s2 += __shfl_xor_sync(0xffffffffu, s2, o);
    }
    if (lane == 0) { r0[wp] = s; r1[wp] = s2; }
    __syncthreads();
    if (t == 0) {
        float ts = 0.f, t2 = 0.f;
        for (int i = 0; i < 8; i++) { ts += r0[i]; t2 += r1[i]; }
        float mu = ts * (1.f / D_);
        float var = t2 * (1.f / D_) - mu * mu;
        mu_s = mu; rs_s = rsqrtf(var + EPSV);
    }
    __syncthreads();
    float mu = mu_s, rs = rs_s;
#pragma unroll
    for (int i = 0; i < 4; i++) {
        int c = t + i*256;
        float yv = (v[i] - mu) * rs * w[c] + bb[c];
        split_store(yh, yl, (size_t)row * D_ + c, yv);
    }
}

// ================= weight transpose + split =================
struct WArgs {
    const float* src[6];
    bf16* dh[6]; bf16* dl[6];
    int K[6]; int N[6];
};
__global__ void convw_k(WArgs a) {
    int w = blockIdx.z;
    int Kd = a.K[w], Nd = a.N[w];
    int n0 = blockIdx.x * 32, k0 = blockIdx.y * 32;
    if (n0 >= Nd || k0 >= Kd) return;
    __shared__ float t[32][33];
    int tx = threadIdx.x, ty = threadIdx.y;
    const float* s = a.src[w];
#pragma unroll
    for (int i = 0; i < 4; i++)
        t[ty + i*8][tx] = s[(size_t)(k0 + ty + i*8) * Nd + n0 + tx];
    __syncthreads();
#pragma unroll
    for (int i = 0; i < 4; i++) {
        float v = t[tx][ty + i*8];
        split_store(a.dh[w], a.dl[w], (size_t)(n0 + ty + i*8) * Kd + k0 + tx, v);
    }
}

// ================= combined bias prepass =================
__global__ void biasprep_k(const float* __restrict__ ab, const float* __restrict__ ob,
                           const float* __restrict__ pd, const float* __restrict__ po,
                           float* __restrict__ out) {
    int i = blockIdx.x * blockDim.x + threadIdx.x;
    float spd = softplus_f(pd[0]);
    float spo = softplus_f(po[0]);
    float4 a = ((const float4*)ab)[i];
    float4 o = ((const float4*)ob)[i];
    float4 r;
    r.x = spd*a.x + spo*o.x; r.y = spd*a.y + spo*o.y;
    r.z = spd*a.z + spo*o.z; r.w = spd*a.w + spo*o.w;
    ((float4*)out)[i] = r;
}

// ================= HMMA split-bf16 GEMM =================
// MODE 0: fp32 out. 1: gelu->split bf16. 2: +R fp32. 3: split bf16 (no act).
#define GPAD 40

template<int MODE>
__global__ void __launch_bounds__(256) gemm_mma_k(
        const bf16* __restrict__ Ahi, const bf16* __restrict__ Alo,
        const bf16* __restrict__ Bhi, const bf16* __restrict__ Blo,
        const float* __restrict__ bias, const float* __restrict__ R,
        float* __restrict__ Cf, bf16* __restrict__ Chi, bf16* __restrict__ Clo,
        int M, int N, int Kd) {
    __shared__ bf16 As[2][128*GPAD];
    __shared__ bf16 Bs[2][128*GPAD];
    int tid = threadIdx.x, lane = tid & 31, wid = tid >> 5;
    int wm = wid & 3, wn = wid >> 2;
    int n0 = blockIdx.x * 128, m0 = blockIdx.y * 128;
    uint32_t sA = smem_to_u32(As);
    uint32_t sB = smem_to_u32(Bs);

    float c[2][8][4];
#pragma unroll
    for (int i = 0; i < 2; i++)
#pragma unroll
        for (int j = 0; j < 8; j++)
#pragma unroll
            for (int q = 0; q < 4; q++) c[i][j][q] = 0.f;

    int nch = Kd >> 5;
    int total = 3 * nch;
    int lr = tid >> 2;
    int ls = (tid & 3) << 3;

    auto prefetch = [&](int ch, int buf) {
        int pass = ch / nch;
        int kc = (ch - pass * nch) << 5;
        const bf16* Ag = (pass == 2) ? Alo : Ahi;
        const bf16* Bg = (pass == 1) ? Blo : Bhi;
        uint32_t da = sA + (uint32_t)(buf * 128*GPAD) * 2;
        uint32_t db = sB + (uint32_t)(buf * 128*GPAD) * 2;
        CP_ASYNC16(da + (lr*GPAD + ls)*2,        Ag + (size_t)(m0 + lr)      * Kd + kc + ls);
        CP_ASYNC16(da + ((lr+64)*GPAD + ls)*2,   Ag + (size_t)(m0 + lr + 64) * Kd + kc + ls);
        CP_ASYNC16(db + (lr*GPAD + ls)*2,        Bg + (size_t)(n0 + lr)      * Kd + kc + ls);
        CP_ASYNC16(db + ((lr+64)*GPAD + ls)*2,   Bg + (size_t)(n0 + lr + 64) * Kd + kc + ls);
    };

    prefetch(0, 0);
    CP_COMMIT();

    for (int it = 0; it < total; ++it) {
        int cur = it & 1;
        if (it + 1 < total) { prefetch(it + 1, cur ^ 1); CP_COMMIT(); CP_WAIT1(); }
        else                { CP_WAIT0(); }
        __syncthreads();

        uint32_t baseA = sA + (uint32_t)(cur * 128*GPAD) * 2;
        uint32_t baseB = sB + (uint32_t)(cur * 128*GPAD) * 2;
#pragma unroll
        for (int kk = 0; kk < 32; kk += 16) {
            uint32_t a[2][4];
#pragma unroll
            for (int mi = 0; mi < 2; mi++) {
                int row = wm*32 + mi*16 + ((lane >> 3) & 1)*8 + (lane & 7);
                int col = kk + (lane >> 4)*8;
                uint32_t addr = baseA + (uint32_t)(row*GPAD + col)*2;
                LDSM_X4(a[mi][0], a[mi][1], a[mi][2], a[mi][3], addr);
            }
            uint32_t b[8][2];
#pragma unroll
            for (int g = 0; g < 4; g++) {
                int row = wn*64 + g*16 + (lane >> 4)*8 + (lane & 7);
                int col = kk + ((lane >> 3) & 1)*8;
                uint32_t addr = baseB + (uint32_t)(row*GPAD + col)*2;
                uint32_t r0, r1, r2, r3;
                LDSM_X4(r0, r1, r2, r3, addr);
                b[2*g][0] = r0; b[2*g][1] = r1;
                b[2*g+1][0] = r2; b[2*g+1][1] = r3;
            }
#pragma unroll
            for (int mi = 0; mi < 2; mi++)
#pragma unroll
                for (int ni = 0; ni < 8; ni++)
                    MMA_16816(c[mi][ni], a[mi], b[ni]);
        }
        __syncthreads();
    }

#pragma unroll
    for (int mi = 0; mi < 2; mi++) {
#pragma unroll
        for (int half = 0; half < 2; half++) {
            int row = m0 + wm*32 + mi*16 + half*8 + (lane >> 2);
#pragma unroll
            for (int ni = 0; ni < 8; ni++) {
                int col = n0 + wn*64 + ni*8 + (lane & 3)*2;
                float v0 = c[mi][ni][half*2 + 0] + bias[col];
                float v1 = c[mi][ni][half*2 + 1] + bias[col + 1];
                size_t idx = (size_t)row * N + col;
                if (MODE == 1 || MODE == 3) {
                    if (MODE == 1) { v0 = gelu_f(v0); v1 = gelu_f(v1); }
                    split_store(Chi, Clo, idx, v0);
                    split_store(Chi, Clo, idx + 1, v1);
                } else {
                    if (MODE == 2) {
                        float2 r2 = *(const float2*)(R + idx);
                        v0 += r2.x; v1 += r2.y;
                    }
                    float2 o2; o2.x = v0; o2.y = v1;
                    *(float2*)(Cf + idx) = o2;
                }
            }
        }
    }
}

// ================= Tensor-core flash attention =================
// 64 q x 64 s tiles, 8 warps (4 row-groups x 2 col-groups).
// QK^T and PV via m16n8k16 bf16 with hi/lo 3-pass split. FA2 register softmax.
#define NIT  (SQ/64)
#define PCH  144          // smem row pitch bytes (72 bf16)
#define QH_OFF 0
#define QL_OFF 9216
#define KV_OFF 18432
#define KVBUF  36864
#define ARRS   9216
#define RMAX_OFF 92160
#define RSUM_OFF 92672
#define GATE_OFF 93184
#define ATTN_SMEM 93440

__global__ void __launch_bounds__(256, 2) attn_mma_k(
        const bf16* __restrict__ Qhg, const bf16* __restrict__ Qlg,
        const bf16* __restrict__ Khg, const bf16* __restrict__ Klg,
        const bf16* __restrict__ Vhg, const bf16* __restrict__ Vlg,
        const float* __restrict__ bcp, const float* __restrict__ dens,
        const float* __restrict__ p_dens,
        bf16* __restrict__ Oh, bf16* __restrict__ Ol) {
    extern __shared__ char smem[];
    uint32_t sb = smem_to_u32(smem);
    int tid = threadIdx.x, lane = tid & 31, wid = tid >> 5;
    int wm = wid & 3, wn = wid >> 2;
    int qt = blockIdx.x, h = blockIdx.y, b = blockIdx.z;
    int q0 = qt * 64;
    size_t qrow0 = (size_t)(b * KQ + q0);
    size_t srow0 = (size_t)(b * SQ);
    int hoff = h * 64;

    // load Q tile (both hi/lo) into smem
#pragma unroll
    for (int i = 0; i < 2; i++) {
        int idx = tid + i*256;
        int r = idx >> 3, cc = (idx & 7)*8;
        *(uint4*)(smem + QH_OFF + r*PCH + cc*2) = *(const uint4*)(Qhg + (qrow0 + r)*D_ + hoff + cc);
        *(uint4*)(smem + QL_OFF + r*PCH + cc*2) = *(const uint4*)(Qlg + (qrow0 + r)*D_ + hoff + cc);
    }
    if (tid < 64) {
        float* gp = (float*)(smem + GATE_OFF);
        gp[tid] = 1.f + tanhf(p_dens[0]) * dens[b*KQ + q0 + tid];
    }

    auto pf = [&](int s0, int buf) {
        uint32_t base = sb + KV_OFF + buf*KVBUF;
        const bf16* gp0 = Khg; const bf16* gp1 = Klg;
        const bf16* gp2 = Vhg; const bf16* gp3 = Vlg;
#pragma unroll
        for (int j = 0; j < 2; j++) {
            int rem = tid + j*256;
            int row = rem >> 3, cc = (rem & 7)*8;
            size_t goff = (srow0 + s0 + row)*D_ + hoff + cc;
            uint32_t soff = row*PCH + cc*2;
            CP_ASYNC16(base + 0*ARRS + soff, gp0 + goff);
            CP_ASYNC16(base + 1*ARRS + soff, gp1 + goff);
            CP_ASYNC16(base + 2*ARRS + soff, gp2 + goff);
            CP_ASYNC16(base + 3*ARRS + soff, gp3 + goff);
        }
    };
    pf(0, 0);  CP_COMMIT();
    pf(64, 1); CP_COMMIT();

    float m0r = -1e30f, m1r = -1e30f, l0r = 0.f, l1r = 0.f;
    float o[8][4];
#pragma unroll
    for (int i = 0; i < 8; i++)
#pragma unroll
        for (int j = 0; j < 4; j++) o[i][j] = 0.f;
    float g0 = 0.f, g1 = 0.f;
    int r0 = wm*16 + (lane >> 2), r1 = r0 + 8;
    float* rmax = (float*)(smem + RMAX_OFF);
    float* rsum = (float*)(smem + RSUM_OFF);

    for (int it = 0; it < NIT; it++) {
        int cur = it & 1;
        if (it + 1 < NIT) CP_WAIT1(); else CP_WAIT0();
        __syncthreads();
        if (it == 0) {
            float* gp = (float*)(smem + GATE_OFF);
            g0 = gp[r0]; g1 = gp[r1];
        }
        uint32_t kvb = sb + KV_OFF + cur*KVBUF;

        // ---- S = Q K^T (3-pass split) ----
        float c[4][4];
#pragma unroll
        for (int i = 0; i < 4; i++)
#pragma unroll
            for (int j = 0; j < 4; j++) c[i][j] = 0.f;
#pragma unroll
        for (int ki = 0; ki < 4; ki++) {
            uint32_t a_h[4], a_l[4];
            uint32_t qaddr = sb + QH_OFF + (uint32_t)((wm*16 + (lane & 15))*PCH + (ki*16 + (lane >> 4)*8)*2);
            LDSM_X4(a_h[0], a_h[1], a_h[2], a_h[3], qaddr);
            LDSM_X4(a_l[0], a_l[1], a_l[2], a_l[3], qaddr + (QL_OFF - QH_OFF));
            uint32_t bh[2][4], bl[2][4];
#pragma unroll
            for (int hf = 0; hf < 2; hf++) {
                uint32_t kaddr = kvb + (uint32_t)((wn*32 + hf*16 + (lane & 15))*PCH + (ki*16 + (lane >> 4)*8)*2);
                LDSM_X4(bh[hf][0], bh[hf][1], bh[hf][2], bh[hf][3], kaddr);
                LDSM_X4(bl[hf][0], bl[hf][1], bl[hf][2], bl[hf][3], kaddr + ARRS);
            }
#pragma unroll
            for (int ni = 0; ni < 4; ni++) {
                uint32_t Bh[2] = { bh[ni>>1][ni&1], bh[ni>>1][(ni&1)+2] };
                uint32_t Bl[2] = { bl[ni>>1][ni&1], bl[ni>>1][(ni&1)+2] };
                MMA_16816(c[ni], a_h, Bh);
                MMA_16816(c[ni], a_h, Bl);
                MMA_16816(c[ni], a_l, Bh);
            }
        }

        // ---- scale + bias + gate ----
#pragma unroll
        for (int ni = 0; ni < 4; ni++) {
            int cbase = it*64 + wn*32 + ni*8 + (lane & 3)*2;
            float2 b0 = *(const float2*)(bcp + (qrow0 + r0)*SQ + cbase);
            float2 b1 = *(const float2*)(bcp + (qrow0 + r1)*SQ + cbase);
            c[ni][0] = (c[ni][0]*0.125f + b0.x) * g0;
            c[ni][1] = (c[ni][1]*0.125f + b0.y) * g0;
            c[ni][2] = (c[ni][2]*0.125f + b1.x) * g1;
            c[ni][3] = (c[ni][3]*0.125f + b1.y) * g1;
        }

        // ---- online softmax (register + smem cross-warp) ----
        float pm0 = fmaxf(fmaxf(c[0][0], c[0][1]), fmaxf(c[1][0], c[1][1]));
        pm0 = fmaxf(pm0, fmaxf(fmaxf(c[2][0], c[2][1]), fmaxf(c[3][0], c[3][1])));
        float pm1 = fmaxf(fmaxf(c[0][2], c[0][3]), fmaxf(c[1][2], c[1][3]));
        pm1 = fmaxf(pm1, fmaxf(fmaxf(c[2][2], c[2][3]), fmaxf(c[3][2], c[3][3])));
        pm0 = fmaxf(pm0, __shfl_xor_sync(0xffffffffu, pm0, 1));
        pm0 = fmaxf(pm0, __shfl_xor_sync(0xffffffffu, pm0, 2));
        pm1 = fmaxf(pm1, __shfl_xor_sync(0xffffffffu, pm1, 1));
        pm1 = fmaxf(pm1, __shfl_xor_sync(0xffffffffu, pm1, 2));
        if ((lane & 3) == 0) { rmax[wn*64 + r0] = pm0; rmax[wn*64 + r1] = pm1; }
        __syncthreads();
        float mn0 = fmaxf(m0r, fmaxf(rmax[r0], rmax[64 + r0]));
        float mn1 = fmaxf(m1r, fmaxf(rmax[r1], rmax[64 + r1]));
        float al0 = exp_fast(m0r - mn0), al1 = exp_fast(m1r - mn1);
        m0r = mn0; m1r = mn1;
        float s0 = 0.f, s1 = 0.f;
#pragma unroll
        for (int ni = 0; ni < 4; ni++) {
            c[ni][0] = exp_fast(c[ni][0] - mn0); s0 += c[ni][0];
            c[ni][1] = exp_fast(c[ni][1] - mn0); s0 += c[ni][1];
            c[ni][2] = exp_fast(c[ni][2] - mn1); s1 += c[ni][2];
            c[ni][3] = exp_fast(c[ni][3] - mn1); s1 += c[ni][3];
        }
        s0 += __shfl_xor_sync(0xffffffffu, s0, 1);
        s0 += __shfl_xor_sync(0xffffffffu, s0, 2);
        s1 += __shfl_xor_sync(0xffffffffu, s1, 1);
        s1 += __shfl_xor_sync(0xffffffffu, s1, 2);
        if ((lane & 3) == 0) { rsum[wn*64 + r0] = s0; rsum[wn*64 + r1] = s1; }
        __syncthreads();
        l0r = l0r*al0 + rsum[r0] + rsum[64 + r0];
        l1r = l1r*al1 + rsum[r1] + rsum[64 + r1];
#pragma unroll
        for (int d = 0; d < 8; d++) {
            o[d][0] *= al0; o[d][1] *= al0; o[d][2] *= al1; o[d][3] *= al1;
        }

        // ---- O += P V (3-pass split; P frags from regs, V via trans ldsm) ----
#pragma unroll
        for (int ch = 0; ch < 2; ch++) {
            uint32_t pa_h[4], pa_l[4];
#pragma unroll
            for (int q2 = 0; q2 < 2; q2++) {
                float* c4 = c[2*ch + q2];
                uint32_t h0 = cvt2_bf16(c4[0], c4[1]);
                uint32_t h1 = cvt2_bf16(c4[2], c4[3]);
                pa_h[q2*2]   = h0;
                pa_h[q2*2+1] = h1;
                pa_l[q2*2]   = cvt2_bf16(c4[0] - lo_bf16f(h0), c4[1] - hi_bf16f(h0));
                pa_l[q2*2+1] = cvt2_bf16(c4[2] - lo_bf16f(h1), c4[3] - hi_bf16f(h1));
            }
            // reorder to A-frag: a0=c[2ch]{01}, a1=c[2ch]{23}, a2=c[2ch+1]{01}, a3=c[2ch+1]{23}
            // (already in that order: pa[0]=h0 of q2=0, pa[1]=h1 of q2=0, pa[2], pa[3])
            int sl = wn*32 + ch*16;
#pragma unroll
            for (int db = 0; db < 4; db++) {
                uint32_t vaddr = kvb + 2*ARRS +
                    (uint32_t)((sl + ((lane >> 3) & 1)*8 + (lane & 7))*PCH + (db*16 + (lane >> 4)*8)*2);
                uint32_t vh4[4], vl4[4];
                LDSM_X4_T(vh4[0], vh4[1], vh4[2], vh4[3], vaddr);
                LDSM_X4_T(vl4[0], vl4[1], vl4[2], vl4[3], vaddr + ARRS);
#pragma unroll
                for (int s2 = 0; s2 < 2; s2++) {
                    uint32_t Bh[2] = { vh4[s2*2], vh4[s2*2+1] };
                    uint32_t Bl[2] = { vl4[s2*2], vl4[s2*2+1] };
                    MMA_16816(o[db*2+s2], pa_h, Bh);
                    MMA_16816(o[db*2+s2], pa_h, Bl);
                    MMA_16816(o[db*2+s2], pa_l, Bh);
                }
            }
        }
        __syncthreads();
        if (it + 2 < NIT) { pf((it + 2)*64, cur); CP_COMMIT(); }
    }

    // ---- cross warp-col reduction + write ----
    float* ox = (float*)(smem + KV_OFF);   // reuse KV area, pitch 65 floats
    if (wn == 1) {
#pragma unroll
        for (int db = 0; db < 8; db++) {
            int d = db*8 + (lane & 3)*2;
            ox[r0*65 + d] = o[db][0]; ox[r0*65 + d + 1] = o[db][1];
            ox[r1*65 + d] = o[db][2]; ox[r1*65 + d + 1] = o[db][3];
        }
    }
    __syncthreads();
    if (wn == 0) {
        float inv0 = 1.f / l0r, inv1 = 1.f / l1r;
#pragma unroll
        for (int db = 0; db < 8; db++) {
            int d = db*8 + (lane & 3)*2;
            float v00 = (o[db][0] + ox[r0*65 + d])     * inv0;
            float v01 = (o[db][1] + ox[r0*65 + d + 1]) * inv0;
            float v10 = (o[db][2] + ox[r1*65 + d])     * inv1;
            float v11 = (o[db][3] + ox[r1*65 + d + 1]) * inv1;
            split_store(Oh, Ol, (qrow0 + r0)*D_ + hoff + d,     v00);
            split_store(Oh, Ol, (qrow0 + r0)*D_ + hoff + d + 1, v01);
            split_store(Oh, Ol, (qrow0 + r1)*D_ + hoff + d,     v10);
            split_store(Oh, Ol, (qrow0 + r1)*D_ + hoff + d + 1, v11);
        }
    }
}

// ================= launch =================
extern "C" void kernel_launch(void* const* d_in, const int* in_sizes, int n_in,
                              void* d_out, int out_size) {
    const float* q        = (const float*)d_in[0];
    const float* kv       = (const float*)d_in[1];
    const float* attn_b   = (const float*)d_in[2];
    const float* obs_b    = (const float*)d_in[3];
    const float* density  = (const float*)d_in[4];
    const float* ln_q_w   = (const float*)d_in[5];
    const float* ln_q_b   = (const float*)d_in[6];
    const float* ln_kv_w  = (const float*)d_in[7];
    const float* ln_kv_b  = (const float*)d_in[8];
    const float* wq = (const float*)d_in[9];  const float* bq = (const float*)d_in[10];
    const float* wk = (const float*)d_in[11]; const float* bk = (const float*)d_in[12];
    const float* wv = (const float*)d_in[13]; const float* bv = (const float*)d_in[14];
    const float* wo = (const float*)d_in[15]; const float* bo = (const float*)d_in[16];
    const float* dist_raw = (const float*)d_in[17];
    const float* obs_raw  = (const float*)d_in[18];
    const float* dens_raw = (const float*)d_in[19];
    const float* ln_f_w = (const float*)d_in[20]; const float* ln_f_b = (const float*)d_in[21];
    const float* w1 = (const float*)d_in[22]; const float* b1 = (const float*)d_in[23];
    const float* w2 = (const float*)d_in[24]; const float* b2 = (const float*)d_in[25];
    float* out = (float*)d_out;

    float *x, *biasc;
    cudaGetSymbolAddress((void**)&x,   g_x);
    cudaGetSymbolAddress((void**)&biasc, g_biasc);
    bf16 *lnq_h, *lnq_l, *lnkv_h, *lnkv_l, *att_h, *att_l, *h1_h, *h1_l;
    bf16 *Qh, *Ql, *Kh, *Kl, *Vh, *Vl;
    cudaGetSymbolAddress((void**)&lnq_h, g_lnq_h);   cudaGetSymbolAddress((void**)&lnq_l, g_lnq_l);
    cudaGetSymbolAddress((void**)&lnkv_h, g_lnkv_h); cudaGetSymbolAddress((void**)&lnkv_l, g_lnkv_l);
    cudaGetSymbolAddress((void**)&Qh, g_Qh); cudaGetSymbolAddress((void**)&Ql, g_Ql);
    cudaGetSymbolAddress((void**)&Kh, g_Kh); cudaGetSymbolAddress((void**)&Kl, g_Kl);
    cudaGetSymbolAddress((void**)&Vh, g_Vh); cudaGetSymbolAddress((void**)&Vl, g_Vl);
    cudaGetSymbolAddress((void**)&att_h, g_att_h);   cudaGetSymbolAddress((void**)&att_l, g_att_l);
    cudaGetSymbolAddress((void**)&h1_h, g_h1_h);     cudaGetSymbolAddress((void**)&h1_l, g_h1_l);
    bf16 *wt_h[6], *wt_l[6];
    cudaGetSymbolAddress((void**)&wt_h[0], g_wqt_h); cudaGetSymbolAddress((void**)&wt_l[0], g_wqt_l);
    cudaGetSymbolAddress((void**)&wt_h[1], g_wkt_h); cudaGetSymbolAddress((void**)&wt_l[1], g_wkt_l);
    cudaGetSymbolAddress((void**)&wt_h[2], g_wvt_h); cudaGetSymbolAddress((void**)&wt_l[2], g_wvt_l);
    cudaGetSymbolAddress((void**)&wt_h[3], g_wot_h); cudaGetSymbolAddress((void**)&wt_l[3], g_wot_l);
    cudaGetSymbolAddress((void**)&wt_h[4], g_w1t_h); cudaGetSymbolAddress((void**)&wt_l[4], g_w1t_l);
    cudaGetSymbolAddress((void**)&wt_h[5], g_w2t_h); cudaGetSymbolAddress((void**)&wt_l[5], g_w2t_l);

    cudaFuncSetAttribute(attn_mma_k, cudaFuncAttributeMaxDynamicSharedMemorySize, ATTN_SMEM);

    // [0] weight transpose+split
    WArgs wa;
    wa.src[0] = wq; wa.src[1] = wk; wa.src[2] = wv; wa.src[3] = wo; wa.src[4] = w1; wa.src[5] = w2;
    for (int i = 0; i < 6; i++) { wa.dh[i] = wt_h[i]; wa.dl[i] = wt_l[i]; }
    wa.K[0]=1024; wa.K[1]=1024; wa.K[2]=1024; wa.K[3]=1024; wa.K[4]=1024; wa.K[5]=2048;
    wa.N[0]=1024; wa.N[1]=1024; wa.N[2]=1024; wa.N[3]=1024; wa.N[4]=2048; wa.N[5]=1024;
    convw_k<<<dim3(64, 64, 6), dim3(32, 8)>>>(wa);

    // [1][2] LayerNorms -> hi/lo bf16
    ln_k<<<B_*KQ, 256>>>(q,  ln_q_w,  ln_q_b,  lnq_h,  lnq_l);
    ln_k<<<B_*SQ, 256>>>(kv, ln_kv_w, ln_kv_b, lnkv_h, lnkv_l);

    // [3][4][5] Q/K/V projections -> split bf16 (MODE 3)
    gemm_mma_k<3><<<dim3(8, 16), 256>>>(lnq_h,  lnq_l,  wt_h[0], wt_l[0], bq, nullptr,
                                        nullptr, Qh, Ql, B_*KQ, D_, D_);
    gemm_mma_k<3><<<dim3(8, 64), 256>>>(lnkv_h, lnkv_l, wt_h[1], wt_l[1], bk, nullptr,
                                        nullptr, Kh, Kl, B_*SQ, D_, D_);
    gemm_mma_k<3><<<dim3(8, 64), 256>>>(lnkv_h, lnkv_l, wt_h[2], wt_l[2], bv, nullptr,
                                        nullptr, Vh, Vl, B_*SQ, D_, D_);

    // [6] combined bias prepass
    biasprep_k<<<(B_*KQ*SQ)/4/256, 256>>>(attn_b, obs_b, dist_raw, obs_raw, biasc);

    // [7] tensor-core flash attention -> att hi/lo bf16
    attn_mma_k<<<dim3(KQ/64, H_, B_), 256, ATTN_SMEM>>>(
        Qh, Ql, Kh, Kl, Vh, Vl, biasc, density, dens_raw, att_h, att_l);

    // [8] O projection + residual: x = q + att @ wo + bo
    gemm_mma_k<2><<<dim3(8, 16), 256>>>(att_h, att_l, wt_h[3], wt_l[3], bo, q,
                                        x, nullptr, nullptr, B_*KQ, D_, D_);

    // [9] final LN
    ln_k<<<B_*KQ, 256>>>(x, ln_f_w, ln_f_b, lnq_h, lnq_l);

    // [10] MLP1 with GELU -> h1 hi/lo bf16
    gemm_mma_k<1><<<dim3(16, 16), 256>>>(lnq_h, lnq_l, wt_h[4], wt_l[4], b1, nullptr,
                                         nullptr, h1_h, h1_l, B_*KQ, 2*D_, D_);

    // [11] MLP2 + residual -> out
    gemm_mma_k<2><<<dim3(8, 16), 256>>>(h1_h, h1_l, wt_h[5], wt_l[5], b2, x,
                                        out, nullptr, nullptr, B_*KQ, D_, 2*D_);
}

// round 6
// speedup vs baseline: 2.9214x; 1.1100x over previous
#include <cuda_runtime.h>
#include <cuda_bf16.h>
#include <math.h>
#include <cstdint>

typedef __nv_bfloat16 bf16;

// Problem constants
#define B_  2
#define KQ  1024
#define SQ  4096
#define D_  1024
#define H_  16
#define HD_ 64
#define EPSV 1e-5f

// ================= scratch (static device globals) =================
__device__ float g_x  [B_*KQ*D_];
__device__ float g_biasc[B_*KQ*SQ];

__device__ bf16 g_lnq_h[B_*KQ*D_],  g_lnq_l[B_*KQ*D_];
__device__ bf16 g_lnkv_h[B_*SQ*D_], g_lnkv_l[B_*SQ*D_];
__device__ bf16 g_Qh[B_*KQ*D_],  g_Ql[B_*KQ*D_];
__device__ bf16 g_Kh[B_*SQ*D_],  g_Kl[B_*SQ*D_];
__device__ bf16 g_Vh[B_*SQ*D_],  g_Vl[B_*SQ*D_];
__device__ bf16 g_att_h[B_*KQ*D_],  g_att_l[B_*KQ*D_];
__device__ bf16 g_h1_h[B_*KQ*2*D_], g_h1_l[B_*KQ*2*D_];
__device__ bf16 g_wqt_h[D_*D_],   g_wqt_l[D_*D_];
__device__ bf16 g_wkt_h[D_*D_],   g_wkt_l[D_*D_];
__device__ bf16 g_wvt_h[D_*D_],   g_wvt_l[D_*D_];
__device__ bf16 g_wot_h[D_*D_],   g_wot_l[D_*D_];
__device__ bf16 g_w1t_h[2*D_*D_], g_w1t_l[2*D_*D_];
__device__ bf16 g_w2t_h[2*D_*D_], g_w2t_l[2*D_*D_];

__device__ __forceinline__ float softplus_f(float x) {
    return fmaxf(x, 0.f) + log1pf(__expf(-fabsf(x)));
}
__device__ __forceinline__ float gelu_f(float x) {
    return 0.5f * x * (1.f + erff(x * 0.70710678118654752f));
}
__device__ __forceinline__ void split_store(bf16* hi, bf16* lo, size_t idx, float v) {
    bf16 h = __float2bfloat16(v);
    hi[idx] = h;
    lo[idx] = __float2bfloat16(v - __bfloat162float(h));
}
__device__ __forceinline__ uint32_t smem_to_u32(const void* p) {
    uint32_t a;
    asm("{ .reg .u64 t; cvta.to.shared.u64 t, %1; cvt.u32.u64 %0, t; }" : "=r"(a) : "l"(p));
    return a;
}

// FMA-pipe exp (no MUFU): e^x for x <= 0, clamped at -87
__device__ __forceinline__ float exp_fast(float x) {
    float y = fmaxf(x, -87.0f) * 1.44269504f;
    float r = rintf(y);
    float f = y - r;
    float p = 1.3333558146e-3f;
    p = fmaf(p, f, 9.6181291076e-3f);
    p = fmaf(p, f, 5.5504108665e-2f);
    p = fmaf(p, f, 2.4022650696e-1f);
    p = fmaf(p, f, 6.9314718056e-1f);
    p = fmaf(p, f, 1.0f);
    return __int_as_float(((int)r + 127) << 23) * p;
}

__device__ __forceinline__ uint32_t cvt2_bf16(float lo, float hi) {
    uint32_t r; asm("cvt.rn.bf16x2.f32 %0, %1, %2;" : "=r"(r) : "f"(hi), "f"(lo)); return r;
}
__device__ __forceinline__ float lo_bf16f(uint32_t p) { return __uint_as_float(p << 16); }
__device__ __forceinline__ float hi_bf16f(uint32_t p) { return __uint_as_float(p & 0xFFFF0000u); }

// cp.async helpers
#define CP_ASYNC16(dst, src) \
    asm volatile("cp.async.cg.shared.global [%0], [%1], 16;" :: "r"(dst), "l"(src))
#define CP_COMMIT() asm volatile("cp.async.commit_group;" ::: "memory")
#define CP_WAIT3()  asm volatile("cp.async.wait_group 3;" ::: "memory")
#define CP_WAIT2()  asm volatile("cp.async.wait_group 2;" ::: "memory")
#define CP_WAIT1()  asm volatile("cp.async.wait_group 1;" ::: "memory")
#define CP_WAIT0()  asm volatile("cp.async.wait_group 0;" ::: "memory")

#define LDSM_X4(r0, r1, r2, r3, addr) \
    asm volatile("ldmatrix.sync.aligned.m8n8.x4.shared.b16 {%0,%1,%2,%3}, [%4];" \
        : "=r"(r0), "=r"(r1), "=r"(r2), "=r"(r3) : "r"(addr))
#define LDSM_X4_T(r0, r1, r2, r3, addr) \
    asm volatile("ldmatrix.sync.aligned.m8n8.x4.trans.shared.b16 {%0,%1,%2,%3}, [%4];" \
        : "=r"(r0), "=r"(r1), "=r"(r2), "=r"(r3) : "r"(addr))

#define MMA_16816(c, a, b) \
    asm volatile("mma.sync.aligned.m16n8k16.row.col.f32.bf16.bf16.f32 " \
        "{%0,%1,%2,%3}, {%4,%5,%6,%7}, {%8,%9}, {%0,%1,%2,%3};" \
        : "+f"((c)[0]), "+f"((c)[1]), "+f"((c)[2]), "+f"((c)[3]) \
        : "r"((a)[0]), "r"((a)[1]), "r"((a)[2]), "r"((a)[3]), "r"((b)[0]), "r"((b)[1]))

// ================= LayerNorm -> hi/lo bf16 =================
__global__ void ln_k(const float* __restrict__ x, const float* __restrict__ w,
                     const float* __restrict__ bb, bf16* __restrict__ yh, bf16* __restrict__ yl) {
    __shared__ float r0[8], r1[8];
    __shared__ float mu_s, rs_s;
    int row = blockIdx.x;
    const float* xr = x + (size_t)row * D_;
    int t = threadIdx.x;
    float v[4]; float s = 0.f, s2 = 0.f;
#pragma unroll
    for (int i = 0; i < 4; i++) { float a = xr[t + i*256]; v[i] = a; s += a; s2 += a*a; }
    int lane = t & 31, wp = t >> 5;
#pragma unroll
    for (int o = 16; o; o >>= 1) {
        s  += __shfl_xor_sync(0xffffffffu, s,  o);
        s2 += __shfl_xor_sync(0xffffffffu, s2, o);
    }
    if (lane == 0) { r0[wp] = s; r1[wp] = s2; }
    __syncthreads();
    if (t == 0) {
        float ts = 0.f, t2 = 0.f;
        for (int i = 0; i < 8; i++) { ts += r0[i]; t2 += r1[i]; }
        float mu = ts * (1.f / D_);
        float var = t2 * (1.f / D_) - mu * mu;
        mu_s = mu; rs_s = rsqrtf(var + EPSV);
    }
    __syncthreads();
    float mu = mu_s, rs = rs_s;
#pragma unroll
    for (int i = 0; i < 4; i++) {
        int c = t + i*256;
        float yv = (v[i] - mu) * rs * w[c] + bb[c];
        split_store(yh, yl, (size_t)row * D_ + c, yv);
    }
}

// ================= weight transpose + split =================
struct WArgs {
    const float* src[6];
    bf16* dh[6]; bf16* dl[6];
    int K[6]; int N[6];
};
__global__ void convw_k(WArgs a) {
    int w = blockIdx.z;
    int Kd = a.K[w], Nd = a.N[w];
    int n0 = blockIdx.x * 32, k0 = blockIdx.y * 32;
    if (n0 >= Nd || k0 >= Kd) return;
    __shared__ float t[32][33];
    int tx = threadIdx.x, ty = threadIdx.y;
    const float* s = a.src[w];
#pragma unroll
    for (int i = 0; i < 4; i++)
        t[ty + i*8][tx] = s[(size_t)(k0 + ty + i*8) * Nd + n0 + tx];
    __syncthreads();
#pragma unroll
    for (int i = 0; i < 4; i++) {
        float v = t[tx][ty + i*8];
        split_store(a.dh[w], a.dl[w], (size_t)(n0 + ty + i*8) * Kd + k0 + tx, v);
    }
}

// ================= combined bias prepass =================
__global__ void biasprep_k(const float* __restrict__ ab, const float* __restrict__ ob,
                           const float* __restrict__ pd, const float* __restrict__ po,
                           float* __restrict__ out) {
    int i = blockIdx.x * blockDim.x + threadIdx.x;
    float spd = softplus_f(pd[0]);
    float spo = softplus_f(po[0]);
    float4 a = ((const float4*)ab)[i];
    float4 o = ((const float4*)ob)[i];
    float4 r;
    r.x = spd*a.x + spo*o.x; r.y = spd*a.y + spo*o.y;
    r.z = spd*a.z + spo*o.z; r.w = spd*a.w + spo*o.w;
    ((float4*)out)[i] = r;
}

// ================= HMMA split-bf16 GEMM (4-stage pipeline) =================
// MODE 0: fp32 out. 1: gelu->split bf16. 2: +R fp32. 3: split bf16 (no act).
#define GPAD 40
#define GSTG 4
#define GABUF (128*GPAD)                 // bf16 per stage per array
#define GB_OFF (GSTG*GABUF*2)            // byte offset of B stages
#define GT_SMEM2 (2*GSTG*GABUF*2)        // 81920 bytes

template<int MODE>
__global__ void __launch_bounds__(256, 2) gemm_mma_k(
        const bf16* __restrict__ Ahi, const bf16* __restrict__ Alo,
        const bf16* __restrict__ Bhi, const bf16* __restrict__ Blo,
        const float* __restrict__ bias, const float* __restrict__ R,
        float* __restrict__ Cf, bf16* __restrict__ Chi, bf16* __restrict__ Clo,
        int M, int N, int Kd) {
    extern __shared__ char gsm[];
    int tid = threadIdx.x, lane = tid & 31, wid = tid >> 5;
    int wm = wid & 3, wn = wid >> 2;
    int n0 = blockIdx.x * 128, m0 = blockIdx.y * 128;
    uint32_t sA = smem_to_u32(gsm);
    uint32_t sB = sA + GB_OFF;

    float c[2][8][4];
#pragma unroll
    for (int i = 0; i < 2; i++)
#pragma unroll
        for (int j = 0; j < 8; j++)
#pragma unroll
            for (int q = 0; q < 4; q++) c[i][j][q] = 0.f;

    int nch = Kd >> 5;
    int total = 3 * nch;
    int lr = tid >> 2;
    int ls = (tid & 3) << 3;

    auto prefetch = [&](int ch, int buf) {
        int pass = ch / nch;
        int kc = (ch - pass * nch) << 5;
        const bf16* Ag = (pass == 2) ? Alo : Ahi;
        const bf16* Bg = (pass == 1) ? Blo : Bhi;
        uint32_t da = sA + (uint32_t)(buf * GABUF) * 2;
        uint32_t db = sB + (uint32_t)(buf * GABUF) * 2;
        CP_ASYNC16(da + (lr*GPAD + ls)*2,        Ag + (size_t)(m0 + lr)      * Kd + kc + ls);
        CP_ASYNC16(da + ((lr+64)*GPAD + ls)*2,   Ag + (size_t)(m0 + lr + 64) * Kd + kc + ls);
        CP_ASYNC16(db + (lr*GPAD + ls)*2,        Bg + (size_t)(n0 + lr)      * Kd + kc + ls);
        CP_ASYNC16(db + ((lr+64)*GPAD + ls)*2,   Bg + (size_t)(n0 + lr + 64) * Kd + kc + ls);
    };

#pragma unroll
    for (int s = 0; s < GSTG; s++) { prefetch(s, s); CP_COMMIT(); }

    for (int it = 0; it < total; ++it) {
        int cur = it & (GSTG - 1);
        int rem = total - 1 - it;
        if (rem >= 3) CP_WAIT3();
        else if (rem == 2) CP_WAIT2();
        else if (rem == 1) CP_WAIT1();
        else CP_WAIT0();
        __syncthreads();

        uint32_t baseA = sA + (uint32_t)(cur * GABUF) * 2;
        uint32_t baseB = sB + (uint32_t)(cur * GABUF) * 2;
#pragma unroll
        for (int kk = 0; kk < 32; kk += 16) {
            uint32_t a[2][4];
#pragma unroll
            for (int mi = 0; mi < 2; mi++) {
                int row = wm*32 + mi*16 + ((lane >> 3) & 1)*8 + (lane & 7);
                int col = kk + (lane >> 4)*8;
                uint32_t addr = baseA + (uint32_t)(row*GPAD + col)*2;
                LDSM_X4(a[mi][0], a[mi][1], a[mi][2], a[mi][3], addr);
            }
            uint32_t b[8][2];
#pragma unroll
            for (int g = 0; g < 4; g++) {
                int row = wn*64 + g*16 + (lane >> 4)*8 + (lane & 7);
                int col = kk + ((lane >> 3) & 1)*8;
                uint32_t addr = baseB + (uint32_t)(row*GPAD + col)*2;
                uint32_t r0, r1, r2, r3;
                LDSM_X4(r0, r1, r2, r3, addr);
                b[2*g][0] = r0; b[2*g][1] = r1;
                b[2*g+1][0] = r2; b[2*g+1][1] = r3;
            }
#pragma unroll
            for (int mi = 0; mi < 2; mi++)
#pragma unroll
                for (int ni = 0; ni < 8; ni++)
                    MMA_16816(c[mi][ni], a[mi], b[ni]);
        }
        __syncthreads();
        if (it + GSTG < total) { prefetch(it + GSTG, cur); CP_COMMIT(); }
    }

#pragma unroll
    for (int mi = 0; mi < 2; mi++) {
#pragma unroll
        for (int half = 0; half < 2; half++) {
            int row = m0 + wm*32 + mi*16 + half*8 + (lane >> 2);
#pragma unroll
            for (int ni = 0; ni < 8; ni++) {
                int col = n0 + wn*64 + ni*8 + (lane & 3)*2;
                float v0 = c[mi][ni][half*2 + 0] + bias[col];
                float v1 = c[mi][ni][half*2 + 1] + bias[col + 1];
                size_t idx = (size_t)row * N + col;
                if (MODE == 1 || MODE == 3) {
                    if (MODE == 1) { v0 = gelu_f(v0); v1 = gelu_f(v1); }
                    split_store(Chi, Clo, idx, v0);
                    split_store(Chi, Clo, idx + 1, v1);
                } else {
                    if (MODE == 2) {
                        float2 r2 = *(const float2*)(R + idx);
                        v0 += r2.x; v1 += r2.y;
                    }
                    float2 o2; o2.x = v0; o2.y = v1;
                    *(float2*)(Cf + idx) = o2;
                }
            }
        }
    }
}

// ================= Tensor-core flash attention, 128-row q-tiles =================
// Grid (KQ/128, H, B) = 256 CTAs. 8 warps; warp w owns q-rows [w*16, w*16+16),
// full s=64 per iter. Softmax entirely in registers+shuffles (no cross-warp).
#define NIT   (SQ/64)
#define APCH  144                 // smem row pitch bytes (72 bf16; mult of 16)
#define AQ_H  0
#define AQ_L  (128*APCH)          // 18432
#define AKV   (2*128*APCH)        // 36864
#define AKVARR (64*APCH)          // 9216 per array
#define AKVBUF (4*AKVARR)         // 36864 per stage
#define AGATE (AKV + 2*AKVBUF)    // 110592
#define ATT_SMEM (AGATE + 512)    // 111104

__global__ void __launch_bounds__(256, 2) attn_mma_k(
        const bf16* __restrict__ Qhg, const bf16* __restrict__ Qlg,
        const bf16* __restrict__ Khg, const bf16* __restrict__ Klg,
        const bf16* __restrict__ Vhg, const bf16* __restrict__ Vlg,
        const float* __restrict__ bcp, const float* __restrict__ dens,
        const float* __restrict__ p_dens,
        bf16* __restrict__ Oh, bf16* __restrict__ Ol) {
    extern __shared__ char smem[];
    uint32_t sb = smem_to_u32(smem);
    int tid = threadIdx.x, lane = tid & 31, w = tid >> 5;
    int qt = blockIdx.x, h = blockIdx.y, b = blockIdx.z;
    int q0 = qt * 128;
    size_t qrow0 = (size_t)(b * KQ + q0);
    size_t srow0 = (size_t)(b * SQ);
    int hoff = h * 64;

    // load Q tile 128x64 (hi/lo)
#pragma unroll
    for (int i = 0; i < 4; i++) {
        int idx = tid + i*256;
        int r = idx >> 3, cc = idx & 7;
        *(uint4*)(smem + AQ_H + r*APCH + cc*16) = *(const uint4*)(Qhg + (qrow0 + r)*D_ + hoff + cc*8);
        *(uint4*)(smem + AQ_L + r*APCH + cc*16) = *(const uint4*)(Qlg + (qrow0 + r)*D_ + hoff + cc*8);
    }
    if (tid < 128) {
        float* gp = (float*)(smem + AGATE);
        gp[tid] = 1.f + tanhf(p_dens[0]) * dens[b*KQ + q0 + tid];
    }

    auto pf = [&](int s0, int buf) {
        uint32_t base = sb + AKV + buf*AKVBUF;
#pragma unroll
        for (int j = 0; j < 2; j++) {
            int rem = tid + j*256;
            int row = rem >> 3, cc = rem & 7;
            size_t goff = (srow0 + s0 + row)*D_ + hoff + cc*8;
            uint32_t soff = (uint32_t)(row*APCH + cc*16);
            CP_ASYNC16(base + 0*AKVARR + soff, Khg + goff);
            CP_ASYNC16(base + 1*AKVARR + soff, Klg + goff);
            CP_ASYNC16(base + 2*AKVARR + soff, Vhg + goff);
            CP_ASYNC16(base + 3*AKVARR + soff, Vlg + goff);
        }
    };
    pf(0, 0);  CP_COMMIT();
    pf(64, 1); CP_COMMIT();

    float m0r = -1e30f, m1r = -1e30f, l0r = 0.f, l1r = 0.f;
    float o[8][4];
#pragma unroll
    for (int i = 0; i < 8; i++)
#pragma unroll
        for (int j = 0; j < 4; j++) o[i][j] = 0.f;
    float g0 = 0.f, g1 = 0.f;
    int r0 = w*16 + (lane >> 2), r1 = r0 + 8;   // rows within 128-tile

    for (int it = 0; it < NIT; it++) {
        int cur = it & 1;
        if (it + 1 < NIT) CP_WAIT1(); else CP_WAIT0();
        __syncthreads();
        if (it == 0) {
            float* gp = (float*)(smem + AGATE);
            g0 = gp[r0]; g1 = gp[r1];
        }
        uint32_t kvb = sb + AKV + cur*AKVBUF;

        // ---- S = Q K^T (3-pass split): c[nf] covers s-cols nf*8..+8 ----
        float c[8][4];
#pragma unroll
        for (int i = 0; i < 8; i++)
#pragma unroll
            for (int j = 0; j < 4; j++) c[i][j] = 0.f;
#pragma unroll
        for (int ki = 0; ki < 4; ki++) {
            uint32_t a_h[4], a_l[4];
            uint32_t qaddr = sb + AQ_H + (uint32_t)((w*16 + (lane & 15))*APCH + (ki*16 + (lane >> 4)*8)*2);
            LDSM_X4(a_h[0], a_h[1], a_h[2], a_h[3], qaddr);
            LDSM_X4(a_l[0], a_l[1], a_l[2], a_l[3], qaddr + (AQ_L - AQ_H));
#pragma unroll
            for (int nf = 0; nf < 4; nf++) {
                uint32_t kaddr = kvb + (uint32_t)((nf*16 + (lane & 15))*APCH + (ki*16 + (lane >> 4)*8)*2);
                uint32_t bh4[4], bl4[4];
                LDSM_X4(bh4[0], bh4[1], bh4[2], bh4[3], kaddr);
                LDSM_X4(bl4[0], bl4[1], bl4[2], bl4[3], kaddr + AKVARR);
#pragma unroll
                for (int half = 0; half < 2; half++) {
                    uint32_t Bh[2] = { bh4[half], bh4[half+2] };
                    uint32_t Bl[2] = { bl4[half], bl4[half+2] };
                    int ni = nf*2 + half;
                    MMA_16816(c[ni], a_h, Bh);
                    MMA_16816(c[ni], a_h, Bl);
                    MMA_16816(c[ni], a_l, Bh);
                }
            }
        }

        // ---- scale + bias + gate ----
#pragma unroll
        for (int nf = 0; nf < 8; nf++) {
            int cb = it*64 + nf*8 + (lane & 3)*2;
            float2 b0 = *(const float2*)(bcp + (qrow0 + r0)*SQ + cb);
            float2 b1 = *(const float2*)(bcp + (qrow0 + r1)*SQ + cb);
            c[nf][0] = (c[nf][0]*0.125f + b0.x) * g0;
            c[nf][1] = (c[nf][1]*0.125f + b0.y) * g0;
            c[nf][2] = (c[nf][2]*0.125f + b1.x) * g1;
            c[nf][3] = (c[nf][3]*0.125f + b1.y) * g1;
        }

        // ---- online softmax, fully in registers ----
        float pm0 = -1e30f, pm1 = -1e30f;
#pragma unroll
        for (int nf = 0; nf < 8; nf++) {
            pm0 = fmaxf(pm0, fmaxf(c[nf][0], c[nf][1]));
            pm1 = fmaxf(pm1, fmaxf(c[nf][2], c[nf][3]));
        }
        pm0 = fmaxf(pm0, __shfl_xor_sync(0xffffffffu, pm0, 1));
        pm0 = fmaxf(pm0, __shfl_xor_sync(0xffffffffu, pm0, 2));
        pm1 = fmaxf(pm1, __shfl_xor_sync(0xffffffffu, pm1, 1));
        pm1 = fmaxf(pm1, __shfl_xor_sync(0xffffffffu, pm1, 2));
        float mn0 = fmaxf(m0r, pm0), mn1 = fmaxf(m1r, pm1);
        float al0 = exp_fast(m0r - mn0), al1 = exp_fast(m1r - mn1);
        m0r = mn0; m1r = mn1;
        float s0 = 0.f, s1 = 0.f;
#pragma unroll
        for (int nf = 0; nf < 8; nf++) {
            c[nf][0] = exp_fast(c[nf][0] - mn0); s0 += c[nf][0];
            c[nf][1] = exp_fast(c[nf][1] - mn0); s0 += c[nf][1];
            c[nf][2] = exp_fast(c[nf][2] - mn1); s1 += c[nf][2];
            c[nf][3] = exp_fast(c[nf][3] - mn1); s1 += c[nf][3];
        }
        s0 += __shfl_xor_sync(0xffffffffu, s0, 1);
        s0 += __shfl_xor_sync(0xffffffffu, s0, 2);
        s1 += __shfl_xor_sync(0xffffffffu, s1, 1);
        s1 += __shfl_xor_sync(0xffffffffu, s1, 2);
        l0r = l0r*al0 + s0;
        l1r = l1r*al1 + s1;
#pragma unroll
        for (int d = 0; d < 8; d++) {
            o[d][0] *= al0; o[d][1] *= al0; o[d][2] *= al1; o[d][3] *= al1;
        }

        // ---- O += P V (3-pass split) ----
#pragma unroll
        for (int kc = 0; kc < 4; kc++) {
            uint32_t pa_h[4], pa_l[4];
#pragma unroll
            for (int q2 = 0; q2 < 2; q2++) {
                float* c4 = c[2*kc + q2];
                uint32_t h0 = cvt2_bf16(c4[0], c4[1]);
                uint32_t h1 = cvt2_bf16(c4[2], c4[3]);
                pa_h[q2*2]   = h0;
                pa_h[q2*2+1] = h1;
                pa_l[q2*2]   = cvt2_bf16(c4[0] - lo_bf16f(h0), c4[1] - hi_bf16f(h0));
                pa_l[q2*2+1] = cvt2_bf16(c4[2] - lo_bf16f(h1), c4[3] - hi_bf16f(h1));
            }
#pragma unroll
            for (int db = 0; db < 4; db++) {
                uint32_t vaddr = kvb + 2*AKVARR +
                    (uint32_t)((kc*16 + ((lane >> 3) & 1)*8 + (lane & 7))*APCH + (db*16 + (lane >> 4)*8)*2);
                uint32_t vh4[4], vl4[4];
                LDSM_X4_T(vh4[0], vh4[1], vh4[2], vh4[3], vaddr);
                LDSM_X4_T(vl4[0], vl4[1], vl4[2], vl4[3], vaddr + AKVARR);
#pragma unroll
                for (int s2 = 0; s2 < 2; s2++) {
                    uint32_t Bh[2] = { vh4[s2*2], vh4[s2*2+1] };
                    uint32_t Bl[2] = { vl4[s2*2], vl4[s2*2+1] };
                    MMA_16816(o[db*2+s2], pa_h, Bh);
                    MMA_16816(o[db*2+s2], pa_h, Bl);
                    MMA_16816(o[db*2+s2], pa_l, Bh);
                }
            }
        }
        __syncthreads();
        if (it + 2 < NIT) { pf((it + 2)*64, cur); CP_COMMIT(); }
    }

    // ---- epilogue: warp owns its rows fully; packed bf16x2 stores ----
    float inv0 = 1.f / l0r, inv1 = 1.f / l1r;
#pragma unroll
    for (int nf = 0; nf < 8; nf++) {
        int d = nf*8 + (lane & 3)*2;
        float v00 = o[nf][0]*inv0, v01 = o[nf][1]*inv0;
        float v10 = o[nf][2]*inv1, v11 = o[nf][3]*inv1;
        size_t i0 = (qrow0 + r0)*D_ + hoff + d;
        size_t i1 = (qrow0 + r1)*D_ + hoff + d;
        uint32_t h0 = cvt2_bf16(v00, v01);
        uint32_t h1 = cvt2_bf16(v10, v11);
        *(uint32_t*)(Oh + i0) = h0;
        *(uint32_t*)(Oh + i1) = h1;
        *(uint32_t*)(Ol + i0) = cvt2_bf16(v00 - lo_bf16f(h0), v01 - hi_bf16f(h0));
        *(uint32_t*)(Ol + i1) = cvt2_bf16(v10 - lo_bf16f(h1), v11 - hi_bf16f(h1));
    }
}

// ================= launch =================
extern "C" void kernel_launch(void* const* d_in, const int* in_sizes, int n_in,
                              void* d_out, int out_size) {
    const float* q        = (const float*)d_in[0];
    const float* kv       = (const float*)d_in[1];
    const float* attn_b   = (const float*)d_in[2];
    const float* obs_b    = (const float*)d_in[3];
    const float* density  = (const float*)d_in[4];
    const float* ln_q_w   = (const float*)d_in[5];
    const float* ln_q_b   = (const float*)d_in[6];
    const float* ln_kv_w  = (const float*)d_in[7];
    const float* ln_kv_b  = (const float*)d_in[8];
    const float* wq = (const float*)d_in[9];  const float* bq = (const float*)d_in[10];
    const float* wk = (const float*)d_in[11]; const float* bk = (const float*)d_in[12];
    const float* wv = (const float*)d_in[13]; const float* bv = (const float*)d_in[14];
    const float* wo = (const float*)d_in[15]; const float* bo = (const float*)d_in[16];
    const float* dist_raw = (const float*)d_in[17];
    const float* obs_raw  = (const float*)d_in[18];
    const float* dens_raw = (const float*)d_in[19];
    const float* ln_f_w = (const float*)d_in[20]; const float* ln_f_b = (const float*)d_in[21];
    const float* w1 = (const float*)d_in[22]; const float* b1 = (const float*)d_in[23];
    const float* w2 = (const float*)d_in[24]; const float* b2 = (const float*)d_in[25];
    float* out = (float*)d_out;

    float *x, *biasc;
    cudaGetSymbolAddress((void**)&x,   g_x);
    cudaGetSymbolAddress((void**)&biasc, g_biasc);
    bf16 *lnq_h, *lnq_l, *lnkv_h, *lnkv_l, *att_h, *att_l, *h1_h, *h1_l;
    bf16 *Qh, *Ql, *Kh, *Kl, *Vh, *Vl;
    cudaGetSymbolAddress((void**)&lnq_h, g_lnq_h);   cudaGetSymbolAddress((void**)&lnq_l, g_lnq_l);
    cudaGetSymbolAddress((void**)&lnkv_h, g_lnkv_h); cudaGetSymbolAddress((void**)&lnkv_l, g_lnkv_l);
    cudaGetSymbolAddress((void**)&Qh, g_Qh); cudaGetSymbolAddress((void**)&Ql, g_Ql);
    cudaGetSymbolAddress((void**)&Kh, g_Kh); cudaGetSymbolAddress((void**)&Kl, g_Kl);
    cudaGetSymbolAddress((void**)&Vh, g_Vh); cudaGetSymbolAddress((void**)&Vl, g_Vl);
    cudaGetSymbolAddress((void**)&att_h, g_att_h);   cudaGetSymbolAddress((void**)&att_l, g_att_l);
    cudaGetSymbolAddress((void**)&h1_h, g_h1_h);     cudaGetSymbolAddress((void**)&h1_l, g_h1_l);
    bf16 *wt_h[6], *wt_l[6];
    cudaGetSymbolAddress((void**)&wt_h[0], g_wqt_h); cudaGetSymbolAddress((void**)&wt_l[0], g_wqt_l);
    cudaGetSymbolAddress((void**)&wt_h[1], g_wkt_h); cudaGetSymbolAddress((void**)&wt_l[1], g_wkt_l);
    cudaGetSymbolAddress((void**)&wt_h[2], g_wvt_h); cudaGetSymbolAddress((void**)&wt_l[2], g_wvt_l);
    cudaGetSymbolAddress((void**)&wt_h[3], g_wot_h); cudaGetSymbolAddress((void**)&wt_l[3], g_wot_l);
    cudaGetSymbolAddress((void**)&wt_h[4], g_w1t_h); cudaGetSymbolAddress((void**)&wt_l[4], g_w1t_l);
    cudaGetSymbolAddress((void**)&wt_h[5], g_w2t_h); cudaGetSymbolAddress((void**)&wt_l[5], g_w2t_l);

    cudaFuncSetAttribute(gemm_mma_k<1>, cudaFuncAttributeMaxDynamicSharedMemorySize, GT_SMEM2);
    cudaFuncSetAttribute(gemm_mma_k<2>, cudaFuncAttributeMaxDynamicSharedMemorySize, GT_SMEM2);
    cudaFuncSetAttribute(gemm_mma_k<3>, cudaFuncAttributeMaxDynamicSharedMemorySize, GT_SMEM2);
    cudaFuncSetAttribute(attn_mma_k, cudaFuncAttributeMaxDynamicSharedMemorySize, ATT_SMEM);

    // [0] weight transpose+split
    WArgs wa;
    wa.src[0] = wq; wa.src[1] = wk; wa.src[2] = wv; wa.src[3] = wo; wa.src[4] = w1; wa.src[5] = w2;
    for (int i = 0; i < 6; i++) { wa.dh[i] = wt_h[i]; wa.dl[i] = wt_l[i]; }
    wa.K[0]=1024; wa.K[1]=1024; wa.K[2]=1024; wa.K[3]=1024; wa.K[4]=1024; wa.K[5]=2048;
    wa.N[0]=1024; wa.N[1]=1024; wa.N[2]=1024; wa.N[3]=1024; wa.N[4]=2048; wa.N[5]=1024;
    convw_k<<<dim3(64, 64, 6), dim3(32, 8)>>>(wa);

    // [1][2] LayerNorms -> hi/lo bf16
    ln_k<<<B_*KQ, 256>>>(q,  ln_q_w,  ln_q_b,  lnq_h,  lnq_l);
    ln_k<<<B_*SQ, 256>>>(kv, ln_kv_w, ln_kv_b, lnkv_h, lnkv_l);

    // [3][4][5] Q/K/V projections -> split bf16 (MODE 3)
    gemm_mma_k<3><<<dim3(8, 16), 256, GT_SMEM2>>>(lnq_h,  lnq_l,  wt_h[0], wt_l[0], bq, nullptr,
                                                  nullptr, Qh, Ql, B_*KQ, D_, D_);
    gemm_mma_k<3><<<dim3(8, 64), 256, GT_SMEM2>>>(lnkv_h, lnkv_l, wt_h[1], wt_l[1], bk, nullptr,
                                                  nullptr, Kh, Kl, B_*SQ, D_, D_);
    gemm_mma_k<3><<<dim3(8, 64), 256, GT_SMEM2>>>(lnkv_h, lnkv_l, wt_h[2], wt_l[2], bv, nullptr,
                                                  nullptr, Vh, Vl, B_*SQ, D_, D_);

    // [6] combined bias prepass
    biasprep_k<<<(B_*KQ*SQ)/4/256, 256>>>(attn_b, obs_b, dist_raw, obs_raw, biasc);

    // [7] tensor-core flash attention (128-row q tiles) -> att hi/lo bf16
    attn_mma_k<<<dim3(KQ/128, H_, B_), 256, ATT_SMEM>>>(
        Qh, Ql, Kh, Kl, Vh, Vl, biasc, density, dens_raw, att_h, att_l);

    // [8] O projection + residual: x = q + att @ wo + bo
    gemm_mma_k<2><<<dim3(8, 16), 256, GT_SMEM2>>>(att_h, att_l, wt_h[3], wt_l[3], bo, q,
                                                  x, nullptr, nullptr, B_*KQ, D_, D_);

    // [9] final LN
    ln_k<<<B_*KQ, 256>>>(x, ln_f_w, ln_f_b, lnq_h, lnq_l);

    // [10] MLP1 with GELU -> h1 hi/lo bf16
    gemm_mma_k<1><<<dim3(16, 16), 256, GT_SMEM2>>>(lnq_h, lnq_l, wt_h[4], wt_l[4], b1, nullptr,
                                                   nullptr, h1_h, h1_l, B_*KQ, 2*D_, D_);

    // [11] MLP2 + residual -> out
    gemm_mma_k<2><<<dim3(8, 16), 256, GT_SMEM2>>>(h1_h, h1_l, wt_h[5], wt_l[5], b2, x,
                                                  out, nullptr, nullptr, B_*KQ, D_, 2*D_);
}

// round 7
// speedup vs baseline: 3.0308x; 1.0375x over previous
#include <cuda_runtime.h>
#include <cuda_fp16.h>
#include <math.h>
#include <cstdint>

typedef __half f16;

// Problem constants
#define B_  2
#define KQ  1024
#define SQ  4096
#define D_  1024
#define H_  16
#define HD_ 64
#define EPSV 1e-5f

// ================= scratch (static device globals) =================
__device__ float g_x  [B_*KQ*D_];
__device__ float g_biasc[B_*KQ*SQ];

__device__ f16 g_lnq [B_*KQ*D_];
__device__ f16 g_lnkv[B_*SQ*D_];
__device__ f16 g_Qh[B_*KQ*D_], g_Ql[B_*KQ*D_];
__device__ f16 g_Kh[B_*SQ*D_];
__device__ f16 g_Vh[B_*SQ*D_], g_Vl[B_*SQ*D_];
__device__ f16 g_att[B_*KQ*D_];
__device__ f16 g_h1 [B_*KQ*2*D_];
__device__ f16 g_wqt_h[D_*D_],   g_wqt_l[D_*D_];
__device__ f16 g_wkt_h[D_*D_],   g_wkt_l[D_*D_];
__device__ f16 g_wvt_h[D_*D_],   g_wvt_l[D_*D_];
__device__ f16 g_wot_h[D_*D_],   g_wot_l[D_*D_];
__device__ f16 g_w1t_h[2*D_*D_], g_w1t_l[2*D_*D_];
__device__ f16 g_w2t_h[2*D_*D_], g_w2t_l[2*D_*D_];

__device__ __forceinline__ float softplus_f(float x) {
    return fmaxf(x, 0.f) + log1pf(__expf(-fabsf(x)));
}
__device__ __forceinline__ float gelu_f(float x) {
    return 0.5f * x * (1.f + erff(x * 0.70710678118654752f));
}
__device__ __forceinline__ void split_store_h(f16* hi, f16* lo, size_t idx, float v) {
    f16 h = __float2half_rn(v);
    hi[idx] = h;
    lo[idx] = __float2half_rn(v - __half2float(h));
}
__device__ __forceinline__ uint32_t smem_to_u32(const void* p) {
    uint32_t a;
    asm("{ .reg .u64 t; cvta.to.shared.u64 t, %1; cvt.u32.u64 %0, t; }" : "=r"(a) : "l"(p));
    return a;
}

// FMA-pipe exp (no MUFU): e^x for x <= 0, clamped at -87
__device__ __forceinline__ float exp_fast(float x) {
    float y = fmaxf(x, -87.0f) * 1.44269504f;
    float r = rintf(y);
    float f = y - r;
    float p = 1.3333558146e-3f;
    p = fmaf(p, f, 9.6181291076e-3f);
    p = fmaf(p, f, 5.5504108665e-2f);
    p = fmaf(p, f, 2.4022650696e-1f);
    p = fmaf(p, f, 6.9314718056e-1f);
    p = fmaf(p, f, 1.0f);
    return __int_as_float(((int)r + 127) << 23) * p;
}

// pack two floats into f16x2: first arg -> low half, second -> high half
__device__ __forceinline__ uint32_t cvt2_f16(float lo, float hi) {
    uint32_t r; asm("cvt.rn.f16x2.f32 %0, %1, %2;" : "=r"(r) : "f"(hi), "f"(lo)); return r;
}

// cp.async helpers
#define CP_ASYNC16(dst, src) \
    asm volatile("cp.async.cg.shared.global [%0], [%1], 16;" :: "r"(dst), "l"(src))
#define CP_COMMIT() asm volatile("cp.async.commit_group;" ::: "memory")
#define CP_WAIT2()  asm volatile("cp.async.wait_group 2;" ::: "memory")
#define CP_WAIT1()  asm volatile("cp.async.wait_group 1;" ::: "memory")
#define CP_WAIT0()  asm volatile("cp.async.wait_group 0;" ::: "memory")

#define LDSM_X4(r0, r1, r2, r3, addr) \
    asm volatile("ldmatrix.sync.aligned.m8n8.x4.shared.b16 {%0,%1,%2,%3}, [%4];" \
        : "=r"(r0), "=r"(r1), "=r"(r2), "=r"(r3) : "r"(addr))
#define LDSM_X4_T(r0, r1, r2, r3, addr) \
    asm volatile("ldmatrix.sync.aligned.m8n8.x4.trans.shared.b16 {%0,%1,%2,%3}, [%4];" \
        : "=r"(r0), "=r"(r1), "=r"(r2), "=r"(r3) : "r"(addr))

#define MMA_16816(c, a, b) \
    asm volatile("mma.sync.aligned.m16n8k16.row.col.f32.f16.f16.f32 " \
        "{%0,%1,%2,%3}, {%4,%5,%6,%7}, {%8,%9}, {%0,%1,%2,%3};" \
        : "+f"((c)[0]), "+f"((c)[1]), "+f"((c)[2]), "+f"((c)[3]) \
        : "r"((a)[0]), "r"((a)[1]), "r"((a)[2]), "r"((a)[3]), "r"((b)[0]), "r"((b)[1]))

// ================= LayerNorm -> fp16 (hi only) =================
__global__ void ln_k(const float* __restrict__ x, const float* __restrict__ w,
                     const float* __restrict__ bb, f16* __restrict__ yh) {
    __shared__ float r0[8], r1[8];
    __shared__ float mu_s, rs_s;
    int row = blockIdx.x;
    const float* xr = x + (size_t)row * D_;
    int t = threadIdx.x;
    float v[4]; float s = 0.f, s2 = 0.f;
#pragma unroll
    for (int i = 0; i < 4; i++) { float a = xr[t + i*256]; v[i] = a; s += a; s2 += a*a; }
    int lane = t & 31, wp = t >> 5;
#pragma unroll
    for (int o = 16; o; o >>= 1) {
        s  += __shfl_xor_sync(0xffffffffu, s,  o);
        s2 += __shfl_xor_sync(0xffffffffu, s2, o);
    }
    if (lane == 0) { r0[wp] = s; r1[wp] = s2; }
    __syncthreads();
    if (t == 0) {
        float ts = 0.f, t2 = 0.f;
        for (int i = 0; i < 8; i++) { ts += r0[i]; t2 += r1[i]; }
        float mu = ts * (1.f / D_);
        float var = t2 * (1.f / D_) - mu * mu;
        mu_s = mu; rs_s = rsqrtf(var + EPSV);
    }
    __syncthreads();
    float mu = mu_s, rs = rs_s;
#pragma unroll
    for (int i = 0; i < 4; i++) {
        int c = t + i*256;
        float yv = (v[i] - mu) * rs * w[c] + bb[c];
        yh[(size_t)row * D_ + c] = __float2half_rn(yv);
    }
}

// ================= weight transpose + split (fp16 hi/lo) =================
struct WArgs {
    const float* src[6];
    f16* dh[6]; f16* dl[6];
    int K[6]; int N[6];
};
__global__ void convw_k(WArgs a) {
    int w = blockIdx.z;
    int Kd = a.K[w], Nd = a.N[w];
    int n0 = blockIdx.x * 32, k0 = blockIdx.y * 32;
    if (n0 >= Nd || k0 >= Kd) return;
    __shared__ float t[32][33];
    int tx = threadIdx.x, ty = threadIdx.y;
    const float* s = a.src[w];
#pragma unroll
    for (int i = 0; i < 4; i++)
        t[ty + i*8][tx] = s[(size_t)(k0 + ty + i*8) * Nd + n0 + tx];
    __syncthreads();
#pragma unroll
    for (int i = 0; i < 4; i++) {
        float v = t[tx][ty + i*8];
        split_store_h(a.dh[w], a.dl[w], (size_t)(n0 + ty + i*8) * Kd + k0 + tx, v);
    }
}

// ================= combined bias prepass =================
__global__ void biasprep_k(const float* __restrict__ ab, const float* __restrict__ ob,
                           const float* __restrict__ pd, const float* __restrict__ po,
                           float* __restrict__ out) {
    int i = blockIdx.x * blockDim.x + threadIdx.x;
    float spd = softplus_f(pd[0]);
    float spo = softplus_f(po[0]);
    float4 a = ((const float4*)ab)[i];
    float4 o = ((const float4*)ob)[i];
    float4 r;
    r.x = spd*a.x + spo*o.x; r.y = spd*a.y + spo*o.y;
    r.z = spd*a.z + spo*o.z; r.w = spd*a.w + spo*o.w;
    ((float4*)out)[i] = r;
}

// ================= HMMA fp16 2-term GEMM (single k-sweep) =================
// C = A @ (Wh + Wl) + bias; A fp16 hi-only [M,Kd]; Wt split [N,Kd].
// MODE 0: fp32. 1: gelu -> f16 hi. 2: +R fp32. 3: f16 hi+lo. 4: f16 hi.
#define GPAD 40
#define GSTG 3
#define GABUF (128*GPAD)                   // f16 elems per array
#define GSTRIDE (3*GABUF*2)                // bytes per stage (A,Bh,Bl)
#define GT_SMEM3 (GSTG*GSTRIDE)            // 92160 bytes

template<int MODE>
__global__ void __launch_bounds__(256, 2) gemm_mma_k(
        const f16* __restrict__ Ag,
        const f16* __restrict__ Bhg, const f16* __restrict__ Blg,
        const float* __restrict__ bias, const float* __restrict__ R,
        float* __restrict__ Cf, f16* __restrict__ Chi, f16* __restrict__ Clo,
        int M, int N, int Kd) {
    extern __shared__ char gsm[];
    int tid = threadIdx.x, lane = tid & 31, wid = tid >> 5;
    int wm = wid & 3, wn = wid >> 2;
    int n0 = blockIdx.x * 128, m0 = blockIdx.y * 128;
    uint32_t sbase = smem_to_u32(gsm);

    float c[2][8][4];
#pragma unroll
    for (int i = 0; i < 2; i++)
#pragma unroll
        for (int j = 0; j < 8; j++)
#pragma unroll
            for (int q = 0; q < 4; q++) c[i][j][q] = 0.f;

    int nch = Kd >> 5;
    int lr = tid >> 2;
    int ls = (tid & 3) << 3;

    auto prefetch = [&](int ch, int buf) {
        int kc = ch << 5;
        uint32_t st = sbase + (uint32_t)buf * GSTRIDE;
        uint32_t da  = st;
        uint32_t dbh = st + GABUF*2;
        uint32_t dbl = st + 2*GABUF*2;
        CP_ASYNC16(da  + (lr*GPAD + ls)*2,      Ag  + (size_t)(m0 + lr)      * Kd + kc + ls);
        CP_ASYNC16(da  + ((lr+64)*GPAD + ls)*2, Ag  + (size_t)(m0 + lr + 64) * Kd + kc + ls);
        CP_ASYNC16(dbh + (lr*GPAD + ls)*2,      Bhg + (size_t)(n0 + lr)      * Kd + kc + ls);
        CP_ASYNC16(dbh + ((lr+64)*GPAD + ls)*2, Bhg + (size_t)(n0 + lr + 64) * Kd + kc + ls);
        CP_ASYNC16(dbl + (lr*GPAD + ls)*2,      Blg + (size_t)(n0 + lr)      * Kd + kc + ls);
        CP_ASYNC16(dbl + ((lr+64)*GPAD + ls)*2, Blg + (size_t)(n0 + lr + 64) * Kd + kc + ls);
    };

#pragma unroll
    for (int s = 0; s < GSTG; s++) { prefetch(s, s); CP_COMMIT(); }

    for (int it = 0; it < nch; ++it) {
        int cur = it % GSTG;
        int rem = nch - 1 - it;
        if (rem >= 2) CP_WAIT2();
        else if (rem == 1) CP_WAIT1();
        else CP_WAIT0();
        __syncthreads();

        uint32_t st = sbase + (uint32_t)cur * GSTRIDE;
#pragma unroll
        for (int kk = 0; kk < 32; kk += 16) {
            uint32_t a[2][4];
#pragma unroll
            for (int mi = 0; mi < 2; mi++) {
                int row = wm*32 + mi*16 + ((lane >> 3) & 1)*8 + (lane & 7);
                int col = kk + (lane >> 4)*8;
                LDSM_X4(a[mi][0], a[mi][1], a[mi][2], a[mi][3],
                        st + (uint32_t)(row*GPAD + col)*2);
            }
#pragma unroll
            for (int pass = 0; pass < 2; pass++) {
                uint32_t bb = st + (pass ? 2*GABUF*2 : GABUF*2);
                uint32_t b[8][2];
#pragma unroll
                for (int g = 0; g < 4; g++) {
                    int row = wn*64 + g*16 + (lane >> 4)*8 + (lane & 7);
                    int col = kk + ((lane >> 3) & 1)*8;
                    uint32_t r0, r1, r2, r3;
                    LDSM_X4(r0, r1, r2, r3, bb + (uint32_t)(row*GPAD + col)*2);
                    b[2*g][0] = r0; b[2*g][1] = r1;
                    b[2*g+1][0] = r2; b[2*g+1][1] = r3;
                }
#pragma unroll
                for (int mi = 0; mi < 2; mi++)
#pragma unroll
                    for (int ni = 0; ni < 8; ni++)
                        MMA_16816(c[mi][ni], a[mi], b[ni]);
            }
        }
        __syncthreads();
        if (it + GSTG < nch) { prefetch(it + GSTG, cur); CP_COMMIT(); }
    }

#pragma unroll
    for (int mi = 0; mi < 2; mi++) {
#pragma unroll
        for (int half = 0; half < 2; half++) {
            int row = m0 + wm*32 + mi*16 + half*8 + (lane >> 2);
#pragma unroll
            for (int ni = 0; ni < 8; ni++) {
                int col = n0 + wn*64 + ni*8 + (lane & 3)*2;
                float v0 = c[mi][ni][half*2 + 0] + bias[col];
                float v1 = c[mi][ni][half*2 + 1] + bias[col + 1];
                size_t idx = (size_t)row * N + col;
                if (MODE == 1) {
                    v0 = gelu_f(v0); v1 = gelu_f(v1);
                    *(uint32_t*)(Chi + idx) = cvt2_f16(v0, v1);
                } else if (MODE == 3) {
                    uint32_t h2 = cvt2_f16(v0, v1);
                    *(uint32_t*)(Chi + idx) = h2;
                    float h0 = __half2float(__ushort_as_half((unsigned short)(h2 & 0xFFFF)));
                    float h1 = __half2float(__ushort_as_half((unsigned short)(h2 >> 16)));
                    *(uint32_t*)(Clo + idx) = cvt2_f16(v0 - h0, v1 - h1);
                } else if (MODE == 4) {
                    *(uint32_t*)(Chi + idx) = cvt2_f16(v0, v1);
                } else {
                    if (MODE == 2) {
                        float2 r2 = *(const float2*)(R + idx);
                        v0 += r2.x; v1 += r2.y;
                    }
                    float2 o2; o2.x = v0; o2.y = v1;
                    *(float2*)(Cf + idx) = o2;
                }
            }
        }
    }
}

// ================= Tensor-core flash attention (fp16, 128-row q-tiles) ======
// QK^T = (Qh+Ql) Kh ; PV = Ph (Vh+Vl). Single sweep, 2 MMAs per fragment.
#define NIT   (SQ/64)
#define APCH  144
#define AQ_H  0
#define AQ_L  (128*APCH)          // 18432
#define AKV   (2*128*APCH)        // 36864
#define AKVARR (64*APCH)          // 9216 per array
#define AKVBUF (3*AKVARR)         // 27648 per stage (Kh,Vh,Vl)
#define AGATE (AKV + 2*AKVBUF)    // 92160
#define ATT_SMEM (AGATE + 512)    // 92672

__global__ void __launch_bounds__(256, 2) attn_mma_k(
        const f16* __restrict__ Qhg, const f16* __restrict__ Qlg,
        const f16* __restrict__ Khg,
        const f16* __restrict__ Vhg, const f16* __restrict__ Vlg,
        const float* __restrict__ bcp, const float* __restrict__ dens,
        const float* __restrict__ p_dens,
        f16* __restrict__ Oh) {
    extern __shared__ char smem[];
    uint32_t sb = smem_to_u32(smem);
    int tid = threadIdx.x, lane = tid & 31, w = tid >> 5;
    int qt = blockIdx.x, h = blockIdx.y, b = blockIdx.z;
    int q0 = qt * 128;
    size_t qrow0 = (size_t)(b * KQ + q0);
    size_t srow0 = (size_t)(b * SQ);
    int hoff = h * 64;

    // load Q tile 128x64 (hi/lo)
#pragma unroll
    for (int i = 0; i < 4; i++) {
        int idx = tid + i*256;
        int r = idx >> 3, cc = idx & 7;
        *(uint4*)(smem + AQ_H + r*APCH + cc*16) = *(const uint4*)(Qhg + (qrow0 + r)*D_ + hoff + cc*8);
        *(uint4*)(smem + AQ_L + r*APCH + cc*16) = *(const uint4*)(Qlg + (qrow0 + r)*D_ + hoff + cc*8);
    }
    if (tid < 128) {
        float* gp = (float*)(smem + AGATE);
        gp[tid] = 1.f + tanhf(p_dens[0]) * dens[b*KQ + q0 + tid];
    }

    auto pf = [&](int s0, int buf) {
        uint32_t base = sb + AKV + buf*AKVBUF;
#pragma unroll
        for (int j = 0; j < 2; j++) {
            int rem = tid + j*256;
            int row = rem >> 3, cc = rem & 7;
            size_t goff = (srow0 + s0 + row)*D_ + hoff + cc*8;
            uint32_t soff = (uint32_t)(row*APCH + cc*16);
            CP_ASYNC16(base + 0*AKVARR + soff, Khg + goff);
            CP_ASYNC16(base + 1*AKVARR + soff, Vhg + goff);
            CP_ASYNC16(base + 2*AKVARR + soff, Vlg + goff);
        }
    };
    pf(0, 0);  CP_COMMIT();
    pf(64, 1); CP_COMMIT();

    float m0r = -1e30f, m1r = -1e30f, l0r = 0.f, l1r = 0.f;
    float o[8][4];
#pragma unroll
    for (int i = 0; i < 8; i++)
#pragma unroll
        for (int j = 0; j < 4; j++) o[i][j] = 0.f;
    float g0 = 0.f, g1 = 0.f;
    int r0 = w*16 + (lane >> 2), r1 = r0 + 8;

    for (int it = 0; it < NIT; it++) {
        int cur = it & 1;
        if (it + 1 < NIT) CP_WAIT1(); else CP_WAIT0();
        __syncthreads();
        if (it == 0) {
            float* gp = (float*)(smem + AGATE);
            g0 = gp[r0]; g1 = gp[r1];
        }
        uint32_t kvb = sb + AKV + cur*AKVBUF;

        // ---- S = (Qh+Ql) Kh ----
        float c[8][4];
#pragma unroll
        for (int i = 0; i < 8; i++)
#pragma unroll
            for (int j = 0; j < 4; j++) c[i][j] = 0.f;
#pragma unroll
        for (int ki = 0; ki < 4; ki++) {
            uint32_t a_h[4], a_l[4];
            uint32_t qaddr = sb + AQ_H + (uint32_t)((w*16 + (lane & 15))*APCH + (ki*16 + (lane >> 4)*8)*2);
            LDSM_X4(a_h[0], a_h[1], a_h[2], a_h[3], qaddr);
            LDSM_X4(a_l[0], a_l[1], a_l[2], a_l[3], qaddr + (AQ_L - AQ_H));
#pragma unroll
            for (int nf = 0; nf < 4; nf++) {
                uint32_t kaddr = kvb + (uint32_t)((nf*16 + (lane & 15))*APCH + (ki*16 + (lane >> 4)*8)*2);
                uint32_t bh4[4];
                LDSM_X4(bh4[0], bh4[1], bh4[2], bh4[3], kaddr);
#pragma unroll
                for (int half = 0; half < 2; half++) {
                    uint32_t Bh[2] = { bh4[half], bh4[half+2] };
                    int ni = nf*2 + half;
                    MMA_16816(c[ni], a_h, Bh);
                    MMA_16816(c[ni], a_l, Bh);
                }
            }
        }

        // ---- scale + bias + gate ----
#pragma unroll
        for (int nf = 0; nf < 8; nf++) {
            int cb = it*64 + nf*8 + (lane & 3)*2;
            float2 b0 = *(const float2*)(bcp + (qrow0 + r0)*SQ + cb);
            float2 b1 = *(const float2*)(bcp + (qrow0 + r1)*SQ + cb);
            c[nf][0] = (c[nf][0]*0.125f + b0.x) * g0;
            c[nf][1] = (c[nf][1]*0.125f + b0.y) * g0;
            c[nf][2] = (c[nf][2]*0.125f + b1.x) * g1;
            c[nf][3] = (c[nf][3]*0.125f + b1.y) * g1;
        }

        // ---- online softmax in registers ----
        float pm0 = -1e30f, pm1 = -1e30f;
#pragma unroll
        for (int nf = 0; nf < 8; nf++) {
            pm0 = fmaxf(pm0, fmaxf(c[nf][0], c[nf][1]));
            pm1 = fmaxf(pm1, fmaxf(c[nf][2], c[nf][3]));
        }
        pm0 = fmaxf(pm0, __shfl_xor_sync(0xffffffffu, pm0, 1));
        pm0 = fmaxf(pm0, __shfl_xor_sync(0xffffffffu, pm0, 2));
        pm1 = fmaxf(pm1, __shfl_xor_sync(0xffffffffu, pm1, 1));
        pm1 = fmaxf(pm1, __shfl_xor_sync(0xffffffffu, pm1, 2));
        float mn0 = fmaxf(m0r, pm0), mn1 = fmaxf(m1r, pm1);
        float al0 = exp_fast(m0r - mn0), al1 = exp_fast(m1r - mn1);
        m0r = mn0; m1r = mn1;
        float s0 = 0.f, s1 = 0.f;
#pragma unroll
        for (int nf = 0; nf < 8; nf++) {
            c[nf][0] = exp_fast(c[nf][0] - mn0); s0 += c[nf][0];
            c[nf][1] = exp_fast(c[nf][1] - mn0); s0 += c[nf][1];
            c[nf][2] = exp_fast(c[nf][2] - mn1); s1 += c[nf][2];
            c[nf][3] = exp_fast(c[nf][3] - mn1); s1 += c[nf][3];
        }
        s0 += __shfl_xor_sync(0xffffffffu, s0, 1);
        s0 += __shfl_xor_sync(0xffffffffu, s0, 2);
        s1 += __shfl_xor_sync(0xffffffffu, s1, 1);
        s1 += __shfl_xor_sync(0xffffffffu, s1, 2);
        l0r = l0r*al0 + s0;
        l1r = l1r*al1 + s1;
#pragma unroll
        for (int d = 0; d < 8; d++) {
            o[d][0] *= al0; o[d][1] *= al0; o[d][2] *= al1; o[d][3] *= al1;
        }

        // ---- O += Ph (Vh+Vl) ----
#pragma unroll
        for (int kc = 0; kc < 4; kc++) {
            uint32_t pa_h[4];
#pragma unroll
            for (int q2 = 0; q2 < 2; q2++) {
                float* c4 = c[2*kc + q2];
                pa_h[q2*2]   = cvt2_f16(c4[0], c4[1]);
                pa_h[q2*2+1] = cvt2_f16(c4[2], c4[3]);
            }
#pragma unroll
            for (int db = 0; db < 4; db++) {
                uint32_t vaddr = kvb + 1*AKVARR +
                    (uint32_t)((kc*16 + ((lane >> 3) & 1)*8 + (lane & 7))*APCH + (db*16 + (lane >> 4)*8)*2);
                uint32_t vh4[4], vl4[4];
                LDSM_X4_T(vh4[0], vh4[1], vh4[2], vh4[3], vaddr);
                LDSM_X4_T(vl4[0], vl4[1], vl4[2], vl4[3], vaddr + AKVARR);
#pragma unroll
                for (int s2 = 0; s2 < 2; s2++) {
                    uint32_t Bh[2] = { vh4[s2*2], vh4[s2*2+1] };
                    uint32_t Bl[2] = { vl4[s2*2], vl4[s2*2+1] };
                    MMA_16816(o[db*2+s2], pa_h, Bh);
                    MMA_16816(o[db*2+s2], pa_h, Bl);
                }
            }
        }
        __syncthreads();
        if (it + 2 < NIT) { pf((it + 2)*64, cur); CP_COMMIT(); }
    }

    // ---- epilogue ----
    float inv0 = 1.f / l0r, inv1 = 1.f / l1r;
#pragma unroll
    for (int nf = 0; nf < 8; nf++) {
        int d = nf*8 + (lane & 3)*2;
        size_t i0 = (qrow0 + r0)*D_ + hoff + d;
        size_t i1 = (qrow0 + r1)*D_ + hoff + d;
        *(uint32_t*)(Oh + i0) = cvt2_f16(o[nf][0]*inv0, o[nf][1]*inv0);
        *(uint32_t*)(Oh + i1) = cvt2_f16(o[nf][2]*inv1, o[nf][3]*inv1);
    }
}

// ================= launch =================
extern "C" void kernel_launch(void* const* d_in, const int* in_sizes, int n_in,
                              void* d_out, int out_size) {
    const float* q        = (const float*)d_in[0];
    const float* kv       = (const float*)d_in[1];
    const float* attn_b   = (const float*)d_in[2];
    const float* obs_b    = (const float*)d_in[3];
    const float* density  = (const float*)d_in[4];
    const float* ln_q_w   = (const float*)d_in[5];
    const float* ln_q_b   = (const float*)d_in[6];
    const float* ln_kv_w  = (const float*)d_in[7];
    const float* ln_kv_b  = (const float*)d_in[8];
    const float* wq = (const float*)d_in[9];  const float* bq = (const float*)d_in[10];
    const float* wk = (const float*)d_in[11]; const float* bk = (const float*)d_in[12];
    const float* wv = (const float*)d_in[13]; const float* bv = (const float*)d_in[14];
    const float* wo = (const float*)d_in[15]; const float* bo = (const float*)d_in[16];
    const float* dist_raw = (const float*)d_in[17];
    const float* obs_raw  = (const float*)d_in[18];
    const float* dens_raw = (const float*)d_in[19];
    const float* ln_f_w = (const float*)d_in[20]; const float* ln_f_b = (const float*)d_in[21];
    const float* w1 = (const float*)d_in[22]; const float* b1 = (const float*)d_in[23];
    const float* w2 = (const float*)d_in[24]; const float* b2 = (const float*)d_in[25];
    float* out = (float*)d_out;

    float *x, *biasc;
    cudaGetSymbolAddress((void**)&x,   g_x);
    cudaGetSymbolAddress((void**)&biasc, g_biasc);
    f16 *lnq, *lnkv, *att, *h1, *Qh, *Ql, *Kh, *Vh, *Vl;
    cudaGetSymbolAddress((void**)&lnq,  g_lnq);
    cudaGetSymbolAddress((void**)&lnkv, g_lnkv);
    cudaGetSymbolAddress((void**)&att,  g_att);
    cudaGetSymbolAddress((void**)&h1,   g_h1);
    cudaGetSymbolAddress((void**)&Qh, g_Qh); cudaGetSymbolAddress((void**)&Ql, g_Ql);
    cudaGetSymbolAddress((void**)&Kh, g_Kh);
    cudaGetSymbolAddress((void**)&Vh, g_Vh); cudaGetSymbolAddress((void**)&Vl, g_Vl);
    f16 *wt_h[6], *wt_l[6];
    cudaGetSymbolAddress((void**)&wt_h[0], g_wqt_h); cudaGetSymbolAddress((void**)&wt_l[0], g_wqt_l);
    cudaGetSymbolAddress((void**)&wt_h[1], g_wkt_h); cudaGetSymbolAddress((void**)&wt_l[1], g_wkt_l);
    cudaGetSymbolAddress((void**)&wt_h[2], g_wvt_h); cudaGetSymbolAddress((void**)&wt_l[2], g_wvt_l);
    cudaGetSymbolAddress((void**)&wt_h[3], g_wot_h); cudaGetSymbolAddress((void**)&wt_l[3], g_wot_l);
    cudaGetSymbolAddress((void**)&wt_h[4], g_w1t_h); cudaGetSymbolAddress((void**)&wt_l[4], g_w1t_l);
    cudaGetSymbolAddress((void**)&wt_h[5], g_w2t_h); cudaGetSymbolAddress((void**)&wt_l[5], g_w2t_l);

    cudaFuncSetAttribute(gemm_mma_k<1>, cudaFuncAttributeMaxDynamicSharedMemorySize, GT_SMEM3);
    cudaFuncSetAttribute(gemm_mma_k<2>, cudaFuncAttributeMaxDynamicSharedMemorySize, GT_SMEM3);
    cudaFuncSetAttribute(gemm_mma_k<3>, cudaFuncAttributeMaxDynamicSharedMemorySize, GT_SMEM3);
    cudaFuncSetAttribute(gemm_mma_k<4>, cudaFuncAttributeMaxDynamicSharedMemorySize, GT_SMEM3);
    cudaFuncSetAttribute(attn_mma_k, cudaFuncAttributeMaxDynamicSharedMemorySize, ATT_SMEM);

    // [0] weight transpose+split
    WArgs wa;
    wa.src[0] = wq; wa.src[1] = wk; wa.src[2] = wv; wa.src[3] = wo; wa.src[4] = w1; wa.src[5] = w2;
    for (int i = 0; i < 6; i++) { wa.dh[i] = wt_h[i]; wa.dl[i] = wt_l[i]; }
    wa.K[0]=1024; wa.K[1]=1024; wa.K[2]=1024; wa.K[3]=1024; wa.K[4]=1024; wa.K[5]=2048;
    wa.N[0]=1024; wa.N[1]=1024; wa.N[2]=1024; wa.N[3]=1024; wa.N[4]=2048; wa.N[5]=1024;
    convw_k<<<dim3(64, 64, 6), dim3(32, 8)>>>(wa);

    // [1][2] LayerNorms -> fp16
    ln_k<<<B_*KQ, 256>>>(q,  ln_q_w,  ln_q_b,  lnq);
    ln_k<<<B_*SQ, 256>>>(kv, ln_kv_w, ln_kv_b, lnkv);

    // [3][4][5] projections: Q -> hi+lo (MODE 3), K -> hi (MODE 4), V -> hi+lo
    gemm_mma_k<3><<<dim3(8, 16), 256, GT_SMEM3>>>(lnq,  wt_h[0], wt_l[0], bq, nullptr,
                                                  nullptr, Qh, Ql, B_*KQ, D_, D_);
    gemm_mma_k<4><<<dim3(8, 64), 256, GT_SMEM3>>>(lnkv, wt_h[1], wt_l[1], bk, nullptr,
                                                  nullptr, Kh, nullptr, B_*SQ, D_, D_);
    gemm_mma_k<3><<<dim3(8, 64), 256, GT_SMEM3>>>(lnkv, wt_h[2], wt_l[2], bv, nullptr,
                                                  nullptr, Vh, Vl, B_*SQ, D_, D_);

    // [6] combined bias prepass
    biasprep_k<<<(B_*KQ*SQ)/4/256, 256>>>(attn_b, obs_b, dist_raw, obs_raw, biasc);

    // [7] flash attention -> att fp16
    attn_mma_k<<<dim3(KQ/128, H_, B_), 256, ATT_SMEM>>>(
        Qh, Ql, Kh, Vh, Vl, biasc, density, dens_raw, att);

    // [8] O projection + residual: x = q + att @ wo + bo
    gemm_mma_k<2><<<dim3(8, 16), 256, GT_SMEM3>>>(att, wt_h[3], wt_l[3], bo, q,
                                                  x, nullptr, nullptr, B_*KQ, D_, D_);

    // [9] final LN
    ln_k<<<B_*KQ, 256>>>(x, ln_f_w, ln_f_b, lnq);

    // [10] MLP1 with GELU -> h1 fp16
    gemm_mma_k<1><<<dim3(16, 16), 256, GT_SMEM3>>>(lnq, wt_h[4], wt_l[4], b1, nullptr,
                                                   nullptr, h1, nullptr, B_*KQ, 2*D_, D_);

    // [11] MLP2 + residual -> out
    gemm_mma_k<2><<<dim3(8, 16), 256, GT_SMEM3>>>(h1, wt_h[5], wt_l[5], b2, x,
                                                  out, nullptr, nullptr, B_*KQ, D_, 2*D_);
}

// round 8
// speedup vs baseline: 6.4616x; 2.1319x over previous
#include <cuda_runtime.h>
#include <cuda_fp16.h>
#include <math.h>
#include <cstdint>

typedef __half f16;

// Problem constants
#define B_  2
#define KQ  1024
#define SQ  4096
#define D_  1024
#define H_  16
#define HD_ 64
#define EPSV 1e-5f

// ================= scratch (static device globals) =================
__device__ float g_x  [B_*KQ*D_];
__device__ float g_biasc[B_*KQ*SQ];

__device__ f16 g_lnq [B_*KQ*D_];
__device__ f16 g_lnkv[B_*SQ*D_];
__device__ f16 g_Qh[B_*KQ*D_];
__device__ f16 g_Kh[B_*SQ*D_];
__device__ f16 g_Vh[B_*SQ*D_], g_Vl[B_*SQ*D_];
__device__ f16 g_att[B_*KQ*D_];
__device__ f16 g_h1 [B_*KQ*2*D_];
__device__ f16 g_wqt[D_*D_];
__device__ f16 g_wkt[D_*D_];
__device__ f16 g_wvt[D_*D_];
__device__ f16 g_wot[D_*D_];
__device__ f16 g_w1t[2*D_*D_];
__device__ f16 g_w2t[2*D_*D_];

__device__ __forceinline__ float softplus_f(float x) {
    return fmaxf(x, 0.f) + log1pf(__expf(-fabsf(x)));
}
__device__ __forceinline__ float gelu_f(float x) {
    return 0.5f * x * (1.f + erff(x * 0.70710678118654752f));
}
__device__ __forceinline__ uint32_t smem_to_u32(const void* p) {
    uint32_t a;
    asm("{ .reg .u64 t; cvta.to.shared.u64 t, %1; cvt.u32.u64 %0, t; }" : "=r"(a) : "l"(p));
    return a;
}

// FMA-pipe exp (no MUFU): e^x for x <= 0, clamped
__device__ __forceinline__ float exp_fast(float x) {
    float y = fmaxf(x, -87.0f) * 1.44269504f;
    float r = rintf(y);
    float f = y - r;
    float p = 1.3333558146e-3f;
    p = fmaf(p, f, 9.6181291076e-3f);
    p = fmaf(p, f, 5.5504108665e-2f);
    p = fmaf(p, f, 2.4022650696e-1f);
    p = fmaf(p, f, 6.9314718056e-1f);
    p = fmaf(p, f, 1.0f);
    return __int_as_float(((int)r + 127) << 23) * p;
}

// pack two floats into f16x2: first arg -> low half, second -> high half
__device__ __forceinline__ uint32_t cvt2_f16(float lo, float hi) {
    uint32_t r; asm("cvt.rn.f16x2.f32 %0, %1, %2;" : "=r"(r) : "f"(hi), "f"(lo)); return r;
}

// cp.async helpers
#define CP_ASYNC16(dst, src) \
    asm volatile("cp.async.cg.shared.global [%0], [%1], 16;" :: "r"(dst), "l"(src))
#define CP_COMMIT() asm volatile("cp.async.commit_group;" ::: "memory")
#define CP_WAIT3()  asm volatile("cp.async.wait_group 3;" ::: "memory")
#define CP_WAIT2()  asm volatile("cp.async.wait_group 2;" ::: "memory")
#define CP_WAIT1()  asm volatile("cp.async.wait_group 1;" ::: "memory")
#define CP_WAIT0()  asm volatile("cp.async.wait_group 0;" ::: "memory")

#define LDSM_X4(r0, r1, r2, r3, addr) \
    asm volatile("ldmatrix.sync.aligned.m8n8.x4.shared.b16 {%0,%1,%2,%3}, [%4];" \
        : "=r"(r0), "=r"(r1), "=r"(r2), "=r"(r3) : "r"(addr))
#define LDSM_X4_T(r0, r1, r2, r3, addr) \
    asm volatile("ldmatrix.sync.aligned.m8n8.x4.trans.shared.b16 {%0,%1,%2,%3}, [%4];" \
        : "=r"(r0), "=r"(r1), "=r"(r2), "=r"(r3) : "r"(addr))

#define MMA_16816(c, a, b) \
    asm volatile("mma.sync.aligned.m16n8k16.row.col.f32.f16.f16.f32 " \
        "{%0,%1,%2,%3}, {%4,%5,%6,%7}, {%8,%9}, {%0,%1,%2,%3};" \
        : "+f"((c)[0]), "+f"((c)[1]), "+f"((c)[2]), "+f"((c)[3]) \
        : "r"((a)[0]), "r"((a)[1]), "r"((a)[2]), "r"((a)[3]), "r"((b)[0]), "r"((b)[1]))

// ================= prep: weight transpose->fp16 + combined bias =================
struct PrepArgs {
    const float* wsrc[6];
    f16* wdst[6];
    int K[6]; int N[6];
    const float* ab; const float* ob; const float* pd; const float* po;
    float* biasc;
};
__global__ void prep_k(PrepArgs a) {
    int z = blockIdx.z;
    int tx = threadIdx.x, ty = threadIdx.y;
    if (z < 6) {
        int Kd = a.K[z], Nd = a.N[z];
        int n0 = blockIdx.x * 32, k0 = blockIdx.y * 32;
        if (n0 >= Nd || k0 >= Kd) return;
        __shared__ float t[32][33];
        const float* s = a.wsrc[z];
#pragma unroll
        for (int i = 0; i < 4; i++)
            t[ty + i*8][tx] = s[(size_t)(k0 + ty + i*8) * Nd + n0 + tx];
        __syncthreads();
#pragma unroll
        for (int i = 0; i < 4; i++) {
            float v = t[tx][ty + i*8];
            a.wdst[z][(size_t)(n0 + ty + i*8) * Kd + k0 + tx] = __float2half_rn(v);
        }
    } else {
        // combined bias: biasc = softplus(pd)*ab + softplus(po)*ob
        int cta = blockIdx.y * 64 + blockIdx.x;          // 0..4095
        int tid = ty * 32 + tx;                          // 0..255
        float spd = softplus_f(a.pd[0]);
        float spo = softplus_f(a.po[0]);
        size_t base = (size_t)cta * 512 + tid * 2;       // float4 units
#pragma unroll
        for (int j = 0; j < 2; j++) {
            float4 av = ((const float4*)a.ab)[base + j];
            float4 ov = ((const float4*)a.ob)[base + j];
            float4 r;
            r.x = spd*av.x + spo*ov.x; r.y = spd*av.y + spo*ov.y;
            r.z = spd*av.z + spo*ov.z; r.w = spd*av.w + spo*ov.w;
            ((float4*)a.biasc)[base + j] = r;
        }
    }
}

// ================= LayerNorm -> fp16 =================
__device__ __forceinline__ void ln_body(const float* xr, const float* w, const float* bb,
                                        f16* yr) {
    __shared__ float r0[8], r1[8];
    __shared__ float mu_s, rs_s;
    int t = threadIdx.x;
    float v[4]; float s = 0.f, s2 = 0.f;
#pragma unroll
    for (int i = 0; i < 4; i++) { float a = xr[t + i*256]; v[i] = a; s += a; s2 += a*a; }
    int lane = t & 31, wp = t >> 5;
#pragma unroll
    for (int o = 16; o; o >>= 1) {
        s  += __shfl_xor_sync(0xffffffffu, s,  o);
        s2 += __shfl_xor_sync(0xffffffffu, s2, o);
    }
    if (lane == 0) { r0[wp] = s; r1[wp] = s2; }
    __syncthreads();
    if (t == 0) {
        float ts = 0.f, t2 = 0.f;
        for (int i = 0; i < 8; i++) { ts += r0[i]; t2 += r1[i]; }
        float mu = ts * (1.f / D_);
        float var = t2 * (1.f / D_) - mu * mu;
        mu_s = mu; rs_s = rsqrtf(var + EPSV);
    }
    __syncthreads();
    float mu = mu_s, rs = rs_s;
#pragma unroll
    for (int i = 0; i < 4; i++) {
        int c = t + i*256;
        yr[c] = __float2half_rn((v[i] - mu) * rs * w[c] + bb[c]);
    }
}

// both input LNs in one launch: rows [0,2048) = q, rest = kv
__global__ void ln_all_k(const float* __restrict__ q, const float* __restrict__ kv,
                         const float* __restrict__ wq, const float* __restrict__ bq,
                         const float* __restrict__ wkv, const float* __restrict__ bkv,
                         f16* __restrict__ oq, f16* __restrict__ okv) {
    int row = blockIdx.x;
    if (row < B_*KQ) ln_body(q + (size_t)row * D_, wq, bq, oq + (size_t)row * D_);
    else {
        row -= B_*KQ;
        ln_body(kv + (size_t)row * D_, wkv, bkv, okv + (size_t)row * D_);
    }
}

__global__ void ln_one_k(const float* __restrict__ x, const float* __restrict__ w,
                         const float* __restrict__ bb, f16* __restrict__ y) {
    int row = blockIdx.x;
    ln_body(x + (size_t)row * D_, w, bb, y + (size_t)row * D_);
}

// ================= HMMA fp16 GEMM core (single-pass, runtime mode) ==========
// mode 1: gelu -> Chi.  mode 2: +R -> Cf fp32.  mode 5: Chi (+Clo if non-null).
#define GPAD 40
#define GSTG 4
#define GABUF (128*GPAD)                   // f16 elems per array
#define GSTRIDE (2*GABUF*2)                // bytes per stage (A,B) = 20480
#define GT_SMEM4 (GSTG*GSTRIDE)            // 81920 bytes

__device__ __forceinline__ void gemm_core(
        int mode, char* gsm,
        const f16* __restrict__ Ag, const f16* __restrict__ Bg,
        const float* __restrict__ bias, const float* __restrict__ R,
        float* __restrict__ Cf, f16* __restrict__ Chi, f16* __restrict__ Clo,
        int m0, int n0, int N, int Kd) {
    int tid = threadIdx.x, lane = tid & 31, wid = tid >> 5;
    int wm = wid & 3, wn = wid >> 2;
    uint32_t sbase = smem_to_u32(gsm);

    float c[2][8][4];
#pragma unroll
    for (int i = 0; i < 2; i++)
#pragma unroll
        for (int j = 0; j < 8; j++)
#pragma unroll
            for (int q = 0; q < 4; q++) c[i][j][q] = 0.f;

    int nch = Kd >> 5;
    int lr = tid >> 2;
    int ls = (tid & 3) << 3;

    auto prefetch = [&](int ch, int buf) {
        int kc = ch << 5;
        uint32_t st = sbase + (uint32_t)buf * GSTRIDE;
        uint32_t db = st + GABUF*2;
        CP_ASYNC16(st + (lr*GPAD + ls)*2,      Ag + (size_t)(m0 + lr)      * Kd + kc + ls);
        CP_ASYNC16(st + ((lr+64)*GPAD + ls)*2, Ag + (size_t)(m0 + lr + 64) * Kd + kc + ls);
        CP_ASYNC16(db + (lr*GPAD + ls)*2,      Bg + (size_t)(n0 + lr)      * Kd + kc + ls);
        CP_ASYNC16(db + ((lr+64)*GPAD + ls)*2, Bg + (size_t)(n0 + lr + 64) * Kd + kc + ls);
    };

#pragma unroll
    for (int s = 0; s < GSTG; s++) { prefetch(s, s); CP_COMMIT(); }

    for (int it = 0; it < nch; ++it) {
        int cur = it & (GSTG - 1);
        int rem = nch - 1 - it;
        if (rem >= 3) CP_WAIT3();
        else if (rem == 2) CP_WAIT2();
        else if (rem == 1) CP_WAIT1();
        else CP_WAIT0();
        __syncthreads();

        uint32_t st = sbase + (uint32_t)cur * GSTRIDE;
        uint32_t bb = st + GABUF*2;
#pragma unroll
        for (int kk = 0; kk < 32; kk += 16) {
            uint32_t a[2][4];
#pragma unroll
            for (int mi = 0; mi < 2; mi++) {
                int row = wm*32 + mi*16 + ((lane >> 3) & 1)*8 + (lane & 7);
                int col = kk + (lane >> 4)*8;
                LDSM_X4(a[mi][0], a[mi][1], a[mi][2], a[mi][3],
                        st + (uint32_t)(row*GPAD + col)*2);
            }
            uint32_t b[8][2];
#pragma unroll
            for (int g = 0; g < 4; g++) {
                int row = wn*64 + g*16 + (lane >> 4)*8 + (lane & 7);
                int col = kk + ((lane >> 3) & 1)*8;
                uint32_t r0, r1, r2, r3;
                LDSM_X4(r0, r1, r2, r3, bb + (uint32_t)(row*GPAD + col)*2);
                b[2*g][0] = r0; b[2*g][1] = r1;
                b[2*g+1][0] = r2; b[2*g+1][1] = r3;
            }
#pragma unroll
            for (int mi = 0; mi < 2; mi++)
#pragma unroll
                for (int ni = 0; ni < 8; ni++)
                    MMA_16816(c[mi][ni], a[mi], b[ni]);
        }
        __syncthreads();
        if (it + GSTG < nch) { prefetch(it + GSTG, cur); CP_COMMIT(); }
    }

#pragma unroll
    for (int mi = 0; mi < 2; mi++) {
#pragma unroll
        for (int half = 0; half < 2; half++) {
            int row = m0 + wm*32 + mi*16 + half*8 + (lane >> 2);
#pragma unroll
            for (int ni = 0; ni < 8; ni++) {
                int col = n0 + wn*64 + ni*8 + (lane & 3)*2;
                float v0 = c[mi][ni][half*2 + 0] + bias[col];
                float v1 = c[mi][ni][half*2 + 1] + bias[col + 1];
                size_t idx = (size_t)row * N + col;
                if (mode == 1) {
                    v0 = gelu_f(v0); v1 = gelu_f(v1);
                    *(uint32_t*)(Chi + idx) = cvt2_f16(v0, v1);
                } else if (mode == 5) {
                    uint32_t h2 = cvt2_f16(v0, v1);
                    *(uint32_t*)(Chi + idx) = h2;
                    if (Clo) {
                        float h0 = __half2float(__ushort_as_half((unsigned short)(h2 & 0xFFFF)));
                        float h1 = __half2float(__ushort_as_half((unsigned short)(h2 >> 16)));
                        *(uint32_t*)(Clo + idx) = cvt2_f16(v0 - h0, v1 - h1);
                    }
                } else {  // mode 2
                    float2 r2 = *(const float2*)(R + idx);
                    float2 o2; o2.x = v0 + r2.x; o2.y = v1 + r2.y;
                    *(float2*)(Cf + idx) = o2;
                }
            }
        }
    }
}

__global__ void __launch_bounds__(256, 2) gemm_g(
        int mode, const f16* Ag, const f16* Bg,
        const float* bias, const float* R,
        float* Cf, f16* Chi, f16* Clo, int N, int Kd) {
    extern __shared__ char gsm[];
    gemm_core(mode, gsm, Ag, Bg, bias, R, Cf, Chi, Clo,
              blockIdx.y * 128, blockIdx.x * 128, N, Kd);
}

// fused QKV projections: grid (8, 144); y<16 -> Q, y<80 -> K, else V
__global__ void __launch_bounds__(256, 2) qkv_k(
        const f16* lnq, const f16* lnkv,
        const f16* wq, const f16* wk, const f16* wv,
        const float* bq, const float* bk, const float* bv,
        f16* Qh, f16* Kh, f16* Vh, f16* Vl) {
    extern __shared__ char gsm[];
    int y = blockIdx.y;
    const f16 *A, *Bw; const float* bias; f16 *Ch; f16 *Cl = nullptr; int m0;
    if (y < 16)      { A = lnq;  Bw = wq; bias = bq; Ch = Qh; m0 = y * 128; }
    else if (y < 80) { A = lnkv; Bw = wk; bias = bk; Ch = Kh; m0 = (y - 16) * 128; }
    else             { A = lnkv; Bw = wv; bias = bv; Ch = Vh; Cl = Vl; m0 = (y - 80) * 128; }
    gemm_core(5, gsm, A, Bw, bias, nullptr, nullptr, Ch, Cl,
              m0, blockIdx.x * 128, D_, D_);
}

// ================= Tensor-core flash attention (fp16, 128-row q-tiles) ======
// QK^T = Qh Kh (1 MMA/frag); PV = Ph (Vh+Vl). 3-stage KV pipeline.
#define NIT   (SQ/64)
#define APCH  144
#define AQ_H  0
#define AKV   (128*APCH)          // 18432
#define AKVARR (64*APCH)          // 9216 per array
#define AKVBUF (3*AKVARR)         // 27648 per stage (Kh,Vh,Vl)
#define ASTG  3
#define AGATE (AKV + ASTG*AKVBUF) // 101376
#define ATT_SMEM (AGATE + 512)    // 101888

__global__ void __launch_bounds__(256, 2) attn_mma_k(
        const f16* __restrict__ Qhg,
        const f16* __restrict__ Khg,
        const f16* __restrict__ Vhg, const f16* __restrict__ Vlg,
        const float* __restrict__ bcp, const float* __restrict__ dens,
        const float* __restrict__ p_dens,
        f16* __restrict__ Oh) {
    extern __shared__ char smem[];
    uint32_t sb = smem_to_u32(smem);
    int tid = threadIdx.x, lane = tid & 31, w = tid >> 5;
    int qt = blockIdx.x, h = blockIdx.y, b = blockIdx.z;
    int q0 = qt * 128;
    size_t qrow0 = (size_t)(b * KQ + q0);
    size_t srow0 = (size_t)(b * SQ);
    int hoff = h * 64;

    // load Q tile 128x64 (hi only)
#pragma unroll
    for (int i = 0; i < 4; i++) {
        int idx = tid + i*256;
        int r = idx >> 3, cc = idx & 7;
        *(uint4*)(smem + AQ_H + r*APCH + cc*16) = *(const uint4*)(Qhg + (qrow0 + r)*D_ + hoff + cc*8);
    }
    if (tid < 128) {
        float* gp = (float*)(smem + AGATE);
        gp[tid] = 1.f + tanhf(p_dens[0]) * dens[b*KQ + q0 + tid];
    }

    auto pf = [&](int s0, int buf) {
        uint32_t base = sb + AKV + buf*AKVBUF;
#pragma unroll
        for (int j = 0; j < 2; j++) {
            int rem = tid + j*256;
            int row = rem >> 3, cc = rem & 7;
            size_t goff = (srow0 + s0 + row)*D_ + hoff + cc*8;
            uint32_t soff = (uint32_t)(row*APCH + cc*16);
            CP_ASYNC16(base + 0*AKVARR + soff, Khg + goff);
            CP_ASYNC16(base + 1*AKVARR + soff, Vhg + goff);
            CP_ASYNC16(base + 2*AKVARR + soff, Vlg + goff);
        }
    };
    pf(0, 0);   CP_COMMIT();
    pf(64, 1);  CP_COMMIT();
    pf(128, 2); CP_COMMIT();

    float m0r = -1e30f, m1r = -1e30f, l0r = 0.f, l1r = 0.f;
    float o[8][4];
#pragma unroll
    for (int i = 0; i < 8; i++)
#pragma unroll
        for (int j = 0; j < 4; j++) o[i][j] = 0.f;
    float g0 = 0.f, g1 = 0.f;
    int r0 = w*16 + (lane >> 2), r1 = r0 + 8;
    int cur = 0;

    for (int it = 0; it < NIT; it++) {
        int rem = NIT - 1 - it;
        if (rem >= 2) CP_WAIT2();
        else if (rem == 1) CP_WAIT1();
        else CP_WAIT0();
        __syncthreads();
        if (it == 0) {
            float* gp = (float*)(smem + AGATE);
            g0 = gp[r0]; g1 = gp[r1];
        }
        uint32_t kvb = sb + AKV + cur*AKVBUF;

        // ---- S = Qh Kh ----
        float c[8][4];
#pragma unroll
        for (int i = 0; i < 8; i++)
#pragma unroll
            for (int j = 0; j < 4; j++) c[i][j] = 0.f;
#pragma unroll
        for (int ki = 0; ki < 4; ki++) {
            uint32_t a_h[4];
            uint32_t qaddr = sb + AQ_H + (uint32_t)((w*16 + (lane & 15))*APCH + (ki*16 + (lane >> 4)*8)*2);
            LDSM_X4(a_h[0], a_h[1], a_h[2], a_h[3], qaddr);
#pragma unroll
            for (int nf = 0; nf < 4; nf++) {
                uint32_t kaddr = kvb + (uint32_t)((nf*16 + (lane & 15))*APCH + (ki*16 + (lane >> 4)*8)*2);
                uint32_t bh4[4];
                LDSM_X4(bh4[0], bh4[1], bh4[2], bh4[3], kaddr);
#pragma unroll
                for (int half = 0; half < 2; half++) {
                    uint32_t Bh[2] = { bh4[half], bh4[half+2] };
                    MMA_16816(c[nf*2 + half], a_h, Bh);
                }
            }
        }

        // ---- scale + bias + gate ----
#pragma unroll
        for (int nf = 0; nf < 8; nf++) {
            int cb = it*64 + nf*8 + (lane & 3)*2;
            float2 b0 = *(const float2*)(bcp + (qrow0 + r0)*SQ + cb);
            float2 b1 = *(const float2*)(bcp + (qrow0 + r1)*SQ + cb);
            c[nf][0] = (c[nf][0]*0.125f + b0.x) * g0;
            c[nf][1] = (c[nf][1]*0.125f + b0.y) * g0;
            c[nf][2] = (c[nf][2]*0.125f + b1.x) * g1;
            c[nf][3] = (c[nf][3]*0.125f + b1.y) * g1;
        }

        // ---- online softmax in registers (hybrid MUFU/FMA exp) ----
        float pm0 = -1e30f, pm1 = -1e30f;
#pragma unroll
        for (int nf = 0; nf < 8; nf++) {
            pm0 = fmaxf(pm0, fmaxf(c[nf][0], c[nf][1]));
            pm1 = fmaxf(pm1, fmaxf(c[nf][2], c[nf][3]));
        }
        pm0 = fmaxf(pm0, __shfl_xor_sync(0xffffffffu, pm0, 1));
        pm0 = fmaxf(pm0, __shfl_xor_sync(0xffffffffu, pm0, 2));
        pm1 = fmaxf(pm1, __shfl_xor_sync(0xffffffffu, pm1, 1));
        pm1 = fmaxf(pm1, __shfl_xor_sync(0xffffffffu, pm1, 2));
        float mn0 = fmaxf(m0r, pm0), mn1 = fmaxf(m1r, pm1);
        float al0 = __expf(m0r - mn0), al1 = __expf(m1r - mn1);
        m0r = mn0; m1r = mn1;
        float s0 = 0.f, s1 = 0.f;
#pragma unroll
        for (int nf = 0; nf < 8; nf++) {
            if (nf & 1) {
                c[nf][0] = exp_fast(c[nf][0] - mn0); s0 += c[nf][0];
                c[nf][1] = exp_fast(c[nf][1] - mn0); s0 += c[nf][1];
                c[nf][2] = exp_fast(c[nf][2] - mn1); s1 += c[nf][2];
                c[nf][3] = exp_fast(c[nf][3] - mn1); s1 += c[nf][3];
            } else {
                c[nf][0] = __expf(c[nf][0] - mn0); s0 += c[nf][0];
                c[nf][1] = __expf(c[nf][1] - mn0); s0 += c[nf][1];
                c[nf][2] = __expf(c[nf][2] - mn1); s1 += c[nf][2];
                c[nf][3] = __expf(c[nf][3] - mn1); s1 += c[nf][3];
            }
        }
        s0 += __shfl_xor_sync(0xffffffffu, s0, 1);
        s0 += __shfl_xor_sync(0xffffffffu, s0, 2);
        s1 += __shfl_xor_sync(0xffffffffu, s1, 1);
        s1 += __shfl_xor_sync(0xffffffffu, s1, 2);
        l0r = l0r*al0 + s0;
        l1r = l1r*al1 + s1;
#pragma unroll
        for (int d = 0; d < 8; d++) {
            o[d][0] *= al0; o[d][1] *= al0; o[d][2] *= al1; o[d][3] *= al1;
        }

        // ---- O += Ph (Vh+Vl) ----
#pragma unroll
        for (int kc = 0; kc < 4; kc++) {
            uint32_t pa_h[4];
#pragma unroll
            for (int q2 = 0; q2 < 2; q2++) {
                float* c4 = c[2*kc + q2];
                pa_h[q2*2]   = cvt2_f16(c4[0], c4[1]);
                pa_h[q2*2+1] = cvt2_f16(c4[2], c4[3]);
            }
#pragma unroll
            for (int db = 0; db < 4; db++) {
                uint32_t vaddr = kvb + 1*AKVARR +
                    (uint32_t)((kc*16 + ((lane >> 3) & 1)*8 + (lane & 7))*APCH + (db*16 + (lane >> 4)*8)*2);
                uint32_t vh4[4], vl4[4];
                LDSM_X4_T(vh4[0], vh4[1], vh4[2], vh4[3], vaddr);
                LDSM_X4_T(vl4[0], vl4[1], vl4[2], vl4[3], vaddr + AKVARR);
#pragma unroll
                for (int s2 = 0; s2 < 2; s2++) {
                    uint32_t Bh[2] = { vh4[s2*2], vh4[s2*2+1] };
                    uint32_t Bl[2] = { vl4[s2*2], vl4[s2*2+1] };
                    MMA_16816(o[db*2+s2], pa_h, Bh);
                    MMA_16816(o[db*2+s2], pa_h, Bl);
                }
            }
        }
        __syncthreads();
        if (it + ASTG < NIT) { pf((it + ASTG)*64, cur); CP_COMMIT(); }
        cur = (cur + 1 == ASTG) ? 0 : cur + 1;
    }

    // ---- epilogue ----
    float inv0 = 1.f / l0r, inv1 = 1.f / l1r;
#pragma unroll
    for (int nf = 0; nf < 8; nf++) {
        int d = nf*8 + (lane & 3)*2;
        size_t i0 = (qrow0 + r0)*D_ + hoff + d;
        size_t i1 = (qrow0 + r1)*D_ + hoff + d;
        *(uint32_t*)(Oh + i0) = cvt2_f16(o[nf][0]*inv0, o[nf][1]*inv0);
        *(uint32_t*)(Oh + i1) = cvt2_f16(o[nf][2]*inv1, o[nf][3]*inv1);
    }
}

// ================= launch =================
extern "C" void kernel_launch(void* const* d_in, const int* in_sizes, int n_in,
                              void* d_out, int out_size) {
    const float* q        = (const float*)d_in[0];
    const float* kv       = (const float*)d_in[1];
    const float* attn_b   = (const float*)d_in[2];
    const float* obs_b    = (const float*)d_in[3];
    const float* density  = (const float*)d_in[4];
    const float* ln_q_w   = (const float*)d_in[5];
    const float* ln_q_b   = (const float*)d_in[6];
    const float* ln_kv_w  = (const float*)d_in[7];
    const float* ln_kv_b  = (const float*)d_in[8];
    const float* wq = (const float*)d_in[9];  const float* bq = (const float*)d_in[10];
    const float* wk = (const float*)d_in[11]; const float* bk = (const float*)d_in[12];
    const float* wv = (const float*)d_in[13]; const float* bv = (const float*)d_in[14];
    const float* wo = (const float*)d_in[15]; const float* bo = (const float*)d_in[16];
    const float* dist_raw = (const float*)d_in[17];
    const float* obs_raw  = (const float*)d_in[18];
    const float* dens_raw = (const float*)d_in[19];
    const float* ln_f_w = (const float*)d_in[20]; const float* ln_f_b = (const float*)d_in[21];
    const float* w1 = (const float*)d_in[22]; const float* b1 = (const float*)d_in[23];
    const float* w2 = (const float*)d_in[24]; const float* b2 = (const float*)d_in[25];
    float* out = (float*)d_out;

    float *x, *biasc;
    cudaGetSymbolAddress((void**)&x,   g_x);
    cudaGetSymbolAddress((void**)&biasc, g_biasc);
    f16 *lnq, *lnkv, *att, *h1, *Qh, *Kh, *Vh, *Vl;
    cudaGetSymbolAddress((void**)&lnq,  g_lnq);
    cudaGetSymbolAddress((void**)&lnkv, g_lnkv);
    cudaGetSymbolAddress((void**)&att,  g_att);
    cudaGetSymbolAddress((void**)&h1,   g_h1);
    cudaGetSymbolAddress((void**)&Qh, g_Qh);
    cudaGetSymbolAddress((void**)&Kh, g_Kh);
    cudaGetSymbolAddress((void**)&Vh, g_Vh); cudaGetSymbolAddress((void**)&Vl, g_Vl);
    f16 *wt[6];
    cudaGetSymbolAddress((void**)&wt[0], g_wqt);
    cudaGetSymbolAddress((void**)&wt[1], g_wkt);
    cudaGetSymbolAddress((void**)&wt[2], g_wvt);
    cudaGetSymbolAddress((void**)&wt[3], g_wot);
    cudaGetSymbolAddress((void**)&wt[4], g_w1t);
    cudaGetSymbolAddress((void**)&wt[5], g_w2t);

    cudaFuncSetAttribute(gemm_g,     cudaFuncAttributeMaxDynamicSharedMemorySize, GT_SMEM4);
    cudaFuncSetAttribute(qkv_k,      cudaFuncAttributeMaxDynamicSharedMemorySize, GT_SMEM4);
    cudaFuncSetAttribute(attn_mma_k, cudaFuncAttributeMaxDynamicSharedMemorySize, ATT_SMEM);

    // [0] prep: weight transpose -> fp16 + combined bias
    PrepArgs pa;
    pa.wsrc[0] = wq; pa.wsrc[1] = wk; pa.wsrc[2] = wv; pa.wsrc[3] = wo; pa.wsrc[4] = w1; pa.wsrc[5] = w2;
    for (int i = 0; i < 6; i++) pa.wdst[i] = wt[i];
    pa.K[0]=1024; pa.K[1]=1024; pa.K[2]=1024; pa.K[3]=1024; pa.K[4]=1024; pa.K[5]=2048;
    pa.N[0]=1024; pa.N[1]=1024; pa.N[2]=1024; pa.N[3]=1024; pa.N[4]=2048; pa.N[5]=1024;
    pa.ab = attn_b; pa.ob = obs_b; pa.pd = dist_raw; pa.po = obs_raw; pa.biasc = biasc;
    prep_k<<<dim3(64, 64, 7), dim3(32, 8)>>>(pa);

    // [1] both input LayerNorms -> fp16
    ln_all_k<<<B_*(KQ + SQ), 256>>>(q, kv, ln_q_w, ln_q_b, ln_kv_w, ln_kv_b, lnq, lnkv);

    // [2] fused Q/K/V projections (Q,K -> hi; V -> hi+lo)
    qkv_k<<<dim3(8, 144), 256, GT_SMEM4>>>(lnq, lnkv, wt[0], wt[1], wt[2],
                                           bq, bk, bv, Qh, Kh, Vh, Vl);

    // [3] flash attention -> att fp16   (captured by ncu)
    attn_mma_k<<<dim3(KQ/128, H_, B_), 256, ATT_SMEM>>>(
        Qh, Kh, Vh, Vl, biasc, density, dens_raw, att);

    // [4] O projection + residual: x = q + att @ wo + bo
    gemm_g<<<dim3(8, 16), 256, GT_SMEM4>>>(2, att, wt[3], bo, q, x, nullptr, nullptr, D_, D_);

    // [5] final LN
    ln_one_k<<<B_*KQ, 256>>>(x, ln_f_w, ln_f_b, lnq);

    // [6] MLP1 with GELU -> h1 fp16
    gemm_g<<<dim3(16, 16), 256, GT_SMEM4>>>(1, lnq, wt[4], b1, nullptr, nullptr, h1, nullptr, 2*D_, D_);

    // [7] MLP2 + residual -> out
    gemm_g<<<dim3(8, 16), 256, GT_SMEM4>>>(2, h1, wt[5], b2, x, out, nullptr, nullptr, D_, 2*D_);
}

// round 9
// speedup vs baseline: 7.1922x; 1.1131x over previous
#include <cuda_runtime.h>
#include <cuda_fp16.h>
#include <math.h>
#include <cstdint>

typedef __half f16;

// Problem constants
#define B_  2
#define KQ  1024
#define SQ  4096
#define D_  1024
#define H_  16
#define HD_ 64
#define EPSV 1e-5f

// ================= scratch (static device globals) =================
__device__ float g_x  [B_*KQ*D_];
__device__ f16   g_biasc[B_*KQ*SQ];

__device__ f16 g_lnq [B_*KQ*D_];
__device__ f16 g_lnkv[B_*SQ*D_];
__device__ f16 g_Qh[B_*KQ*D_];
__device__ f16 g_Kh[B_*SQ*D_];
__device__ f16 g_Vh[B_*SQ*D_];
__device__ f16 g_att[B_*KQ*D_];
__device__ f16 g_h1 [B_*KQ*2*D_];
__device__ f16 g_wqt[D_*D_];
__device__ f16 g_wkt[D_*D_];
__device__ f16 g_wvt[D_*D_];
__device__ f16 g_wot[D_*D_];
__device__ f16 g_w1t[2*D_*D_];
__device__ f16 g_w2t[2*D_*D_];

__device__ __forceinline__ float softplus_f(float x) {
    return fmaxf(x, 0.f) + log1pf(__expf(-fabsf(x)));
}
__device__ __forceinline__ float gelu_f(float x) {
    return 0.5f * x * (1.f + erff(x * 0.70710678118654752f));
}
__device__ __forceinline__ uint32_t smem_to_u32(const void* p) {
    uint32_t a;
    asm("{ .reg .u64 t; cvta.to.shared.u64 t, %1; cvt.u32.u64 %0, t; }" : "=r"(a) : "l"(p));
    return a;
}

// FMA-pipe exp: e^x for x <= 0, clamped
__device__ __forceinline__ float exp_fast(float x) {
    float y = fmaxf(x, -87.0f) * 1.44269504f;
    float r = rintf(y);
    float f = y - r;
    float p = 1.3333558146e-3f;
    p = fmaf(p, f, 9.6181291076e-3f);
    p = fmaf(p, f, 5.5504108665e-2f);
    p = fmaf(p, f, 2.4022650696e-1f);
    p = fmaf(p, f, 6.9314718056e-1f);
    p = fmaf(p, f, 1.0f);
    return __int_as_float(((int)r + 127) << 23) * p;
}

__device__ __forceinline__ uint32_t cvt2_f16(float lo, float hi) {
    uint32_t r; asm("cvt.rn.f16x2.f32 %0, %1, %2;" : "=r"(r) : "f"(hi), "f"(lo)); return r;
}

// cp.async helpers
#define CP_ASYNC16(dst, src) \
    asm volatile("cp.async.cg.shared.global [%0], [%1], 16;" :: "r"(dst), "l"(src))
#define CP_COMMIT() asm volatile("cp.async.commit_group;" ::: "memory")
#define CP_WAIT3()  asm volatile("cp.async.wait_group 3;" ::: "memory")
#define CP_WAIT2()  asm volatile("cp.async.wait_group 2;" ::: "memory")
#define CP_WAIT1()  asm volatile("cp.async.wait_group 1;" ::: "memory")
#define CP_WAIT0()  asm volatile("cp.async.wait_group 0;" ::: "memory")

#define LDSM_X4(r0, r1, r2, r3, addr) \
    asm volatile("ldmatrix.sync.aligned.m8n8.x4.shared.b16 {%0,%1,%2,%3}, [%4];" \
        : "=r"(r0), "=r"(r1), "=r"(r2), "=r"(r3) : "r"(addr))
#define LDSM_X4_T(r0, r1, r2, r3, addr) \
    asm volatile("ldmatrix.sync.aligned.m8n8.x4.trans.shared.b16 {%0,%1,%2,%3}, [%4];" \
        : "=r"(r0), "=r"(r1), "=r"(r2), "=r"(r3) : "r"(addr))

#define MMA_16816(c, a, b) \
    asm volatile("mma.sync.aligned.m16n8k16.row.col.f32.f16.f16.f32 " \
        "{%0,%1,%2,%3}, {%4,%5,%6,%7}, {%8,%9}, {%0,%1,%2,%3};" \
        : "+f"((c)[0]), "+f"((c)[1]), "+f"((c)[2]), "+f"((c)[3]) \
        : "r"((a)[0]), "r"((a)[1]), "r"((a)[2]), "r"((a)[3]), "r"((b)[0]), "r"((b)[1]))

// ================= prep: weight transpose->fp16 + combined bias (f16) =========
struct PrepArgs {
    const float* wsrc[6];
    f16* wdst[6];
    int K[6]; int N[6];
    const float* ab; const float* ob; const float* pd; const float* po;
    f16* biasc;
};
__global__ void prep_k(PrepArgs a) {
    int z = blockIdx.z;
    int tx = threadIdx.x, ty = threadIdx.y;
    if (z < 6) {
        int Kd = a.K[z], Nd = a.N[z];
        int n0 = blockIdx.x * 32, k0 = blockIdx.y * 32;
        if (n0 >= Nd || k0 >= Kd) return;
        __shared__ float t[32][33];
        const float* s = a.wsrc[z];
#pragma unroll
        for (int i = 0; i < 4; i++)
            t[ty + i*8][tx] = s[(size_t)(k0 + ty + i*8) * Nd + n0 + tx];
        __syncthreads();
#pragma unroll
        for (int i = 0; i < 4; i++) {
            float v = t[tx][ty + i*8];
            a.wdst[z][(size_t)(n0 + ty + i*8) * Kd + k0 + tx] = __float2half_rn(v);
        }
    } else {
        int cta = blockIdx.y * 64 + blockIdx.x;          // 0..4095
        int tid = ty * 32 + tx;                          // 0..255
        float spd = softplus_f(a.pd[0]);
        float spo = softplus_f(a.po[0]);
        size_t base = (size_t)cta * 512 + tid * 2;       // float4 units
#pragma unroll
        for (int j = 0; j < 2; j++) {
            float4 av = ((const float4*)a.ab)[base + j];
            float4 ov = ((const float4*)a.ob)[base + j];
            __half2 h0 = __floats2half2_rn(spd*av.x + spo*ov.x, spd*av.y + spo*ov.y);
            __half2 h1 = __floats2half2_rn(spd*av.z + spo*ov.z, spd*av.w + spo*ov.w);
            ((__half2*)a.biasc)[(base + j)*2 + 0] = h0;
            ((__half2*)a.biasc)[(base + j)*2 + 1] = h1;
        }
    }
}

// ================= LayerNorm -> fp16 =================
__device__ __forceinline__ void ln_body(const float* xr, const float* w, const float* bb,
                                        f16* yr) {
    __shared__ float r0[8], r1[8];
    __shared__ float mu_s, rs_s;
    int t = threadIdx.x;
    float v[4]; float s = 0.f, s2 = 0.f;
#pragma unroll
    for (int i = 0; i < 4; i++) { float a = xr[t + i*256]; v[i] = a; s += a; s2 += a*a; }
    int lane = t & 31, wp = t >> 5;
#pragma unroll
    for (int o = 16; o; o >>= 1) {
        s  += __shfl_xor_sync(0xffffffffu, s,  o);
        s2 += __shfl_xor_sync(0xffffffffu, s2, o);
    }
    if (lane == 0) { r0[wp] = s; r1[wp] = s2; }
    __syncthreads();
    if (t == 0) {
        float ts = 0.f, t2 = 0.f;
        for (int i = 0; i < 8; i++) { ts += r0[i]; t2 += r1[i]; }
        float mu = ts * (1.f / D_);
        float var = t2 * (1.f / D_) - mu * mu;
        mu_s = mu; rs_s = rsqrtf(var + EPSV);
    }
    __syncthreads();
    float mu = mu_s, rs = rs_s;
#pragma unroll
    for (int i = 0; i < 4; i++) {
        int c = t + i*256;
        yr[c] = __float2half_rn((v[i] - mu) * rs * w[c] + bb[c]);
    }
}

__global__ void ln_all_k(const float* __restrict__ q, const float* __restrict__ kv,
                         const float* __restrict__ wq, const float* __restrict__ bq,
                         const float* __restrict__ wkv, const float* __restrict__ bkv,
                         f16* __restrict__ oq, f16* __restrict__ okv) {
    int row = blockIdx.x;
    if (row < B_*KQ) ln_body(q + (size_t)row * D_, wq, bq, oq + (size_t)row * D_);
    else {
        row -= B_*KQ;
        ln_body(kv + (size_t)row * D_, wkv, bkv, okv + (size_t)row * D_);
    }
}

__global__ void ln_one_k(const float* __restrict__ x, const float* __restrict__ w,
                         const float* __restrict__ bb, f16* __restrict__ y) {
    int row = blockIdx.x;
    ln_body(x + (size_t)row * D_, w, bb, y + (size_t)row * D_);
}

// ================= HMMA fp16 GEMM core (single-pass) ==========
// mode 1: gelu -> Chi.  mode 2: +R -> Cf fp32.  mode 4: Chi.
#define GPAD 40
#define GSTG 4
#define GABUF (128*GPAD)
#define GSTRIDE (2*GABUF*2)                // 20480 B per stage (A,B)
#define GT_SMEM4 (GSTG*GSTRIDE)            // 81920

__device__ __forceinline__ void gemm_core(
        int mode, char* gsm,
        const f16* __restrict__ Ag, const f16* __restrict__ Bg,
        const float* __restrict__ bias, const float* __restrict__ R,
        float* __restrict__ Cf, f16* __restrict__ Chi,
        int m0, int n0, int N, int Kd) {
    int tid = threadIdx.x, lane = tid & 31, wid = tid >> 5;
    int wm = wid & 3, wn = wid >> 2;
    uint32_t sbase = smem_to_u32(gsm);

    float c[2][8][4];
#pragma unroll
    for (int i = 0; i < 2; i++)
#pragma unroll
        for (int j = 0; j < 8; j++)
#pragma unroll
            for (int q = 0; q < 4; q++) c[i][j][q] = 0.f;

    int nch = Kd >> 5;
    int lr = tid >> 2;
    int ls = (tid & 3) << 3;

    auto prefetch = [&](int ch, int buf) {
        int kc = ch << 5;
        uint32_t st = sbase + (uint32_t)buf * GSTRIDE;
        uint32_t db = st + GABUF*2;
        CP_ASYNC16(st + (lr*GPAD + ls)*2,      Ag + (size_t)(m0 + lr)      * Kd + kc + ls);
        CP_ASYNC16(st + ((lr+64)*GPAD + ls)*2, Ag + (size_t)(m0 + lr + 64) * Kd + kc + ls);
        CP_ASYNC16(db + (lr*GPAD + ls)*2,      Bg + (size_t)(n0 + lr)      * Kd + kc + ls);
        CP_ASYNC16(db + ((lr+64)*GPAD + ls)*2, Bg + (size_t)(n0 + lr + 64) * Kd + kc + ls);
    };

#pragma unroll
    for (int s = 0; s < GSTG; s++) { prefetch(s, s); CP_COMMIT(); }

    for (int it = 0; it < nch; ++it) {
        int cur = it & (GSTG - 1);
        int rem = nch - 1 - it;
        if (rem >= 3) CP_WAIT3();
        else if (rem == 2) CP_WAIT2();
        else if (rem == 1) CP_WAIT1();
        else CP_WAIT0();
        __syncthreads();

        uint32_t st = sbase + (uint32_t)cur * GSTRIDE;
        uint32_t bb = st + GABUF*2;
#pragma unroll
        for (int kk = 0; kk < 32; kk += 16) {
            uint32_t a[2][4];
#pragma unroll
            for (int mi = 0; mi < 2; mi++) {
                int row = wm*32 + mi*16 + ((lane >> 3) & 1)*8 + (lane & 7);
                int col = kk + (lane >> 4)*8;
                LDSM_X4(a[mi][0], a[mi][1], a[mi][2], a[mi][3],
                        st + (uint32_t)(row*GPAD + col)*2);
            }
            uint32_t b[8][2];
#pragma unroll
            for (int g = 0; g < 4; g++) {
                int row = wn*64 + g*16 + (lane >> 4)*8 + (lane & 7);
                int col = kk + ((lane >> 3) & 1)*8;
                uint32_t r0, r1, r2, r3;
                LDSM_X4(r0, r1, r2, r3, bb + (uint32_t)(row*GPAD + col)*2);
                b[2*g][0] = r0; b[2*g][1] = r1;
                b[2*g+1][0] = r2; b[2*g+1][1] = r3;
            }
#pragma unroll
            for (int mi = 0; mi < 2; mi++)
#pragma unroll
                for (int ni = 0; ni < 8; ni++)
                    MMA_16816(c[mi][ni], a[mi], b[ni]);
        }
        __syncthreads();
        if (it + GSTG < nch) { prefetch(it + GSTG, cur); CP_COMMIT(); }
    }

#pragma unroll
    for (int mi = 0; mi < 2; mi++) {
#pragma unroll
        for (int half = 0; half < 2; half++) {
            int row = m0 + wm*32 + mi*16 + half*8 + (lane >> 2);
#pragma unroll
            for (int ni = 0; ni < 8; ni++) {
                int col = n0 + wn*64 + ni*8 + (lane & 3)*2;
                float v0 = c[mi][ni][half*2 + 0] + bias[col];
                float v1 = c[mi][ni][half*2 + 1] + bias[col + 1];
                size_t idx = (size_t)row * N + col;
                if (mode == 1) {
                    v0 = gelu_f(v0); v1 = gelu_f(v1);
                    *(uint32_t*)(Chi + idx) = cvt2_f16(v0, v1);
                } else if (mode == 4) {
                    *(uint32_t*)(Chi + idx) = cvt2_f16(v0, v1);
                } else {  // mode 2
                    float2 r2 = *(const float2*)(R + idx);
                    float2 o2; o2.x = v0 + r2.x; o2.y = v1 + r2.y;
                    *(float2*)(Cf + idx) = o2;
                }
            }
        }
    }
}

__global__ void __launch_bounds__(256, 2) gemm_g(
        int mode, const f16* Ag, const f16* Bg,
        const float* bias, const float* R,
        float* Cf, f16* Chi, int N, int Kd) {
    extern __shared__ char gsm[];
    gemm_core(mode, gsm, Ag, Bg, bias, R, Cf, Chi,
              blockIdx.y * 128, blockIdx.x * 128, N, Kd);
}

// fused QKV projections: grid (8, 144); y<16 -> Q, y<80 -> K, else V
__global__ void __launch_bounds__(256, 2) qkv_k(
        const f16* lnq, const f16* lnkv,
        const f16* wq, const f16* wk, const f16* wv,
        const float* bq, const float* bk, const float* bv,
        f16* Qh, f16* Kh, f16* Vh) {
    extern __shared__ char gsm[];
    int y = blockIdx.y;
    const f16 *A, *Bw; const float* bias; f16 *Ch; int m0;
    if (y < 16)      { A = lnq;  Bw = wq; bias = bq; Ch = Qh; m0 = y * 128; }
    else if (y < 80) { A = lnkv; Bw = wk; bias = bk; Ch = Kh; m0 = (y - 16) * 128; }
    else             { A = lnkv; Bw = wv; bias = bv; Ch = Vh; m0 = (y - 80) * 128; }
    gemm_core(4, gsm, A, Bw, bias, nullptr, nullptr, Ch,
              m0, blockIdx.x * 128, D_, D_);
}

// ================= Tensor-core flash attention (fp16 all-hi) ================
// QK^T = Qh Kh ; PV = Ph Vh. 4-stage KV pipeline, f16 combined bias.
#define NIT   (SQ/64)
#define APCH  144
#define AQ_H  0
#define AKV   (128*APCH)          // 18432
#define AKVARR (64*APCH)          // 9216 per array
#define AKVBUF (2*AKVARR)         // 18432 per stage (Kh,Vh)
#define ASTG  4
#define AGATE (AKV + ASTG*AKVBUF) // 92160
#define ATT_SMEM (AGATE + 512)    // 92672

__global__ void __launch_bounds__(256, 2) attn_mma_k(
        const f16* __restrict__ Qhg,
        const f16* __restrict__ Khg,
        const f16* __restrict__ Vhg,
        const f16* __restrict__ bcp, const float* __restrict__ dens,
        const float* __restrict__ p_dens,
        f16* __restrict__ Oh) {
    extern __shared__ char smem[];
    uint32_t sb = smem_to_u32(smem);
    int tid = threadIdx.x, lane = tid & 31, w = tid >> 5;
    int qt = blockIdx.x, h = blockIdx.y, b = blockIdx.z;
    int q0 = qt * 128;
    size_t qrow0 = (size_t)(b * KQ + q0);
    size_t srow0 = (size_t)(b * SQ);
    int hoff = h * 64;

    // load Q tile 128x64
#pragma unroll
    for (int i = 0; i < 4; i++) {
        int idx = tid + i*256;
        int r = idx >> 3, cc = idx & 7;
        *(uint4*)(smem + AQ_H + r*APCH + cc*16) = *(const uint4*)(Qhg + (qrow0 + r)*D_ + hoff + cc*8);
    }
    if (tid < 128) {
        float* gp = (float*)(smem + AGATE);
        gp[tid] = 1.f + tanhf(p_dens[0]) * dens[b*KQ + q0 + tid];
    }

    auto pf = [&](int s0, int buf) {
        uint32_t base = sb + AKV + buf*AKVBUF;
#pragma unroll
        for (int j = 0; j < 2; j++) {
            int rem = tid + j*256;
            int row = rem >> 3, cc = rem & 7;
            size_t goff = (srow0 + s0 + row)*D_ + hoff + cc*8;
            uint32_t soff = (uint32_t)(row*APCH + cc*16);
            CP_ASYNC16(base + 0*AKVARR + soff, Khg + goff);
            CP_ASYNC16(base + 1*AKVARR + soff, Vhg + goff);
        }
    };
    pf(0, 0);   CP_COMMIT();
    pf(64, 1);  CP_COMMIT();
    pf(128, 2); CP_COMMIT();
    pf(192, 3); CP_COMMIT();

    float m0r = -1e30f, m1r = -1e30f, l0r = 0.f, l1r = 0.f;
    float o[8][4];
#pragma unroll
    for (int i = 0; i < 8; i++)
#pragma unroll
        for (int j = 0; j < 4; j++) o[i][j] = 0.f;
    float g0 = 0.f, g1 = 0.f;
    int r0 = w*16 + (lane >> 2), r1 = r0 + 8;
    const f16* bp0 = bcp + (qrow0 + r0)*SQ + (lane & 3)*2;
    const f16* bp1 = bcp + (qrow0 + r1)*SQ + (lane & 3)*2;
    int cur = 0;

    for (int it = 0; it < NIT; it++) {
        int rem = NIT - 1 - it;
        if (rem >= 3) CP_WAIT3();
        else if (rem == 2) CP_WAIT2();
        else if (rem == 1) CP_WAIT1();
        else CP_WAIT0();
        __syncthreads();
        if (it == 0) {
            float* gp = (float*)(smem + AGATE);
            g0 = gp[r0]; g1 = gp[r1];
        }
        uint32_t kvb = sb + AKV + cur*AKVBUF;

        // ---- S = Qh Kh ----
        float c[8][4];
#pragma unroll
        for (int i = 0; i < 8; i++)
#pragma unroll
            for (int j = 0; j < 4; j++) c[i][j] = 0.f;
#pragma unroll
        for (int ki = 0; ki < 4; ki++) {
            uint32_t a_h[4];
            uint32_t qaddr = sb + AQ_H + (uint32_t)((w*16 + (lane & 15))*APCH + (ki*16 + (lane >> 4)*8)*2);
            LDSM_X4(a_h[0], a_h[1], a_h[2], a_h[3], qaddr);
#pragma unroll
            for (int nf = 0; nf < 4; nf++) {
                uint32_t kaddr = kvb + (uint32_t)((nf*16 + (lane & 15))*APCH + (ki*16 + (lane >> 4)*8)*2);
                uint32_t bh4[4];
                LDSM_X4(bh4[0], bh4[1], bh4[2], bh4[3], kaddr);
#pragma unroll
                for (int half = 0; half < 2; half++) {
                    uint32_t Bh[2] = { bh4[half], bh4[half+2] };
                    MMA_16816(c[nf*2 + half], a_h, Bh);
                }
            }
        }

        // ---- scale + bias(f16) + gate ----
#pragma unroll
        for (int nf = 0; nf < 8; nf++) {
            int cb = it*64 + nf*8;
            uint32_t u0 = *(const uint32_t*)(bp0 + cb);
            uint32_t u1 = *(const uint32_t*)(bp1 + cb);
            float2 b0 = __half22float2(*(const __half2*)&u0);
            float2 b1 = __half22float2(*(const __half2*)&u1);
            c[nf][0] = (c[nf][0]*0.125f + b0.x) * g0;
            c[nf][1] = (c[nf][1]*0.125f + b0.y) * g0;
            c[nf][2] = (c[nf][2]*0.125f + b1.x) * g1;
            c[nf][3] = (c[nf][3]*0.125f + b1.y) * g1;
        }

        // ---- online softmax in registers (hybrid MUFU/FMA exp) ----
        float pm0 = -1e30f, pm1 = -1e30f;
#pragma unroll
        for (int nf = 0; nf < 8; nf++) {
            pm0 = fmaxf(pm0, fmaxf(c[nf][0], c[nf][1]));
            pm1 = fmaxf(pm1, fmaxf(c[nf][2], c[nf][3]));
        }
        pm0 = fmaxf(pm0, __shfl_xor_sync(0xffffffffu, pm0, 1));
        pm0 = fmaxf(pm0, __shfl_xor_sync(0xffffffffu, pm0, 2));
        pm1 = fmaxf(pm1, __shfl_xor_sync(0xffffffffu, pm1, 1));
        pm1 = fmaxf(pm1, __shfl_xor_sync(0xffffffffu, pm1, 2));
        float mn0 = fmaxf(m0r, pm0), mn1 = fmaxf(m1r, pm1);
        float al0 = __expf(m0r - mn0), al1 = __expf(m1r - mn1);
        m0r = mn0; m1r = mn1;
        float s0 = 0.f, s1 = 0.f;
#pragma unroll
        for (int nf = 0; nf < 8; nf++) {
            if (nf & 1) {
                c[nf][0] = exp_fast(c[nf][0] - mn0); s0 += c[nf][0];
                c[nf][1] = exp_fast(c[nf][1] - mn0); s0 += c[nf][1];
                c[nf][2] = exp_fast(c[nf][2] - mn1); s1 += c[nf][2];
                c[nf][3] = exp_fast(c[nf][3] - mn1); s1 += c[nf][3];
            } else {
                c[nf][0] = __expf(c[nf][0] - mn0); s0 += c[nf][0];
                c[nf][1] = __expf(c[nf][1] - mn0); s0 += c[nf][1];
                c[nf][2] = __expf(c[nf][2] - mn1); s1 += c[nf][2];
                c[nf][3] = __expf(c[nf][3] - mn1); s1 += c[nf][3];
            }
        }
        s0 += __shfl_xor_sync(0xffffffffu, s0, 1);
        s0 += __shfl_xor_sync(0xffffffffu, s0, 2);
        s1 += __shfl_xor_sync(0xffffffffu, s1, 1);
        s1 += __shfl_xor_sync(0xffffffffu, s1, 2);
        l0r = l0r*al0 + s0;
        l1r = l1r*al1 + s1;
#pragma unroll
        for (int d = 0; d < 8; d++) {
            o[d][0] *= al0; o[d][1] *= al0; o[d][2] *= al1; o[d][3] *= al1;
        }

        // ---- O += Ph Vh ----
#pragma unroll
        for (int kc = 0; kc < 4; kc++) {
            uint32_t pa_h[4];
#pragma unroll
            for (int q2 = 0; q2 < 2; q2++) {
                float* c4 = c[2*kc + q2];
                pa_h[q2*2]   = cvt2_f16(c4[0], c4[1]);
                pa_h[q2*2+1] = cvt2_f16(c4[2], c4[3]);
            }
#pragma unroll
            for (int db = 0; db < 4; db++) {
                uint32_t vaddr = kvb + 1*AKVARR +
                    (uint32_t)((kc*16 + ((lane >> 3) & 1)*8 + (lane & 7))*APCH + (db*16 + (lane >> 4)*8)*2);
                uint32_t vh4[4];
                LDSM_X4_T(vh4[0], vh4[1], vh4[2], vh4[3], vaddr);
#pragma unroll
                for (int s2 = 0; s2 < 2; s2++) {
                    uint32_t Bh[2] = { vh4[s2*2], vh4[s2*2+1] };
                    MMA_16816(o[db*2+s2], pa_h, Bh);
                }
            }
        }
        __syncthreads();
        if (it + ASTG < NIT) { pf((it + ASTG)*64, cur); CP_COMMIT(); }
        cur = (cur + 1) & (ASTG - 1);
    }

    // ---- epilogue ----
    float inv0 = 1.f / l0r, inv1 = 1.f / l1r;
#pragma unroll
    for (int nf = 0; nf < 8; nf++) {
        int d = nf*8 + (lane & 3)*2;
        size_t i0 = (qrow0 + r0)*D_ + hoff + d;
        size_t i1 = (qrow0 + r1)*D_ + hoff + d;
        *(uint32_t*)(Oh + i0) = cvt2_f16(o[nf][0]*inv0, o[nf][1]*inv0);
        *(uint32_t*)(Oh + i1) = cvt2_f16(o[nf][2]*inv1, o[nf][3]*inv1);
    }
}

// ================= launch =================
extern "C" void kernel_launch(void* const* d_in, const int* in_sizes, int n_in,
                              void* d_out, int out_size) {
    const float* q        = (const float*)d_in[0];
    const float* kv       = (const float*)d_in[1];
    const float* attn_b   = (const float*)d_in[2];
    const float* obs_b    = (const float*)d_in[3];
    const float* density  = (const float*)d_in[4];
    const float* ln_q_w   = (const float*)d_in[5];
    const float* ln_q_b   = (const float*)d_in[6];
    const float* ln_kv_w  = (const float*)d_in[7];
    const float* ln_kv_b  = (const float*)d_in[8];
    const float* wq = (const float*)d_in[9];  const float* bq = (const float*)d_in[10];
    const float* wk = (const float*)d_in[11]; const float* bk = (const float*)d_in[12];
    const float* wv = (const float*)d_in[13]; const float* bv = (const float*)d_in[14];
    const float* wo = (const float*)d_in[15]; const float* bo = (const float*)d_in[16];
    const float* dist_raw = (const float*)d_in[17];
    const float* obs_raw  = (const float*)d_in[18];
    const float* dens_raw = (const float*)d_in[19];
    const float* ln_f_w = (const float*)d_in[20]; const float* ln_f_b = (const float*)d_in[21];
    const float* w1 = (const float*)d_in[22]; const float* b1 = (const float*)d_in[23];
    const float* w2 = (const float*)d_in[24]; const float* b2 = (const float*)d_in[25];
    float* out = (float*)d_out;

    float *x;
    f16 *biasc;
    cudaGetSymbolAddress((void**)&x,   g_x);
    cudaGetSymbolAddress((void**)&biasc, g_biasc);
    f16 *lnq, *lnkv, *att, *h1, *Qh, *Kh, *Vh;
    cudaGetSymbolAddress((void**)&lnq,  g_lnq);
    cudaGetSymbolAddress((void**)&lnkv, g_lnkv);
    cudaGetSymbolAddress((void**)&att,  g_att);
    cudaGetSymbolAddress((void**)&h1,   g_h1);
    cudaGetSymbolAddress((void**)&Qh, g_Qh);
    cudaGetSymbolAddress((void**)&Kh, g_Kh);
    cudaGetSymbolAddress((void**)&Vh, g_Vh);
    f16 *wt[6];
    cudaGetSymbolAddress((void**)&wt[0], g_wqt);
    cudaGetSymbolAddress((void**)&wt[1], g_wkt);
    cudaGetSymbolAddress((void**)&wt[2], g_wvt);
    cudaGetSymbolAddress((void**)&wt[3], g_wot);
    cudaGetSymbolAddress((void**)&wt[4], g_w1t);
    cudaGetSymbolAddress((void**)&wt[5], g_w2t);

    cudaFuncSetAttribute(gemm_g,     cudaFuncAttributeMaxDynamicSharedMemorySize, GT_SMEM4);
    cudaFuncSetAttribute(qkv_k,      cudaFuncAttributeMaxDynamicSharedMemorySize, GT_SMEM4);
    cudaFuncSetAttribute(attn_mma_k, cudaFuncAttributeMaxDynamicSharedMemorySize, ATT_SMEM);

    // [0] prep: weight transpose -> fp16 + combined bias (f16)
    PrepArgs pa;
    pa.wsrc[0] = wq; pa.wsrc[1] = wk; pa.wsrc[2] = wv; pa.wsrc[3] = wo; pa.wsrc[4] = w1; pa.wsrc[5] = w2;
    for (int i = 0; i < 6; i++) pa.wdst[i] = wt[i];
    pa.K[0]=1024; pa.K[1]=1024; pa.K[2]=1024; pa.K[3]=1024; pa.K[4]=1024; pa.K[5]=2048;
    pa.N[0]=1024; pa.N[1]=1024; pa.N[2]=1024; pa.N[3]=1024; pa.N[4]=2048; pa.N[5]=1024;
    pa.ab = attn_b; pa.ob = obs_b; pa.pd = dist_raw; pa.po = obs_raw; pa.biasc = biasc;
    prep_k<<<dim3(64, 64, 7), dim3(32, 8)>>>(pa);

    // [1] both input LayerNorms -> fp16
    ln_all_k<<<B_*(KQ + SQ), 256>>>(q, kv, ln_q_w, ln_q_b, ln_kv_w, ln_kv_b, lnq, lnkv);

    // [2] fused Q/K/V projections (all hi-only fp16)
    qkv_k<<<dim3(8, 144), 256, GT_SMEM4>>>(lnq, lnkv, wt[0], wt[1], wt[2],
                                           bq, bk, bv, Qh, Kh, Vh);

    // [3] flash attention -> att fp16   (captured by ncu)
    attn_mma_k<<<dim3(KQ/128, H_, B_), 256, ATT_SMEM>>>(
        Qh, Kh, Vh, biasc, density, dens_raw, att);

    // [4] O projection + residual: x = q + att @ wo + bo
    gemm_g<<<dim3(8, 16), 256, GT_SMEM4>>>(2, att, wt[3], bo, q, x, nullptr, D_, D_);

    // [5] final LN
    ln_one_k<<<B_*KQ, 256>>>(x, ln_f_w, ln_f_b, lnq);

    // [6] MLP1 with GELU -> h1 fp16
    gemm_g<<<dim3(16, 16), 256, GT_SMEM4>>>(1, lnq, wt[4], b1, nullptr, nullptr, h1, 2*D_, D_);

    // [7] MLP2 + residual -> out
    gemm_g<<<dim3(8, 16), 256, GT_SMEM4>>>(2, h1, wt[5], b2, x, out, nullptr, D_, 2*D_);
}

// round 12
// speedup vs baseline: 7.6225x; 1.0598x over previous
#include <cuda_runtime.h>
#include <cuda_fp16.h>
#include <math.h>
#include <cstdint>

typedef __half f16;

// Problem constants
#define B_  2
#define KQ  1024
#define SQ  4096
#define D_  1024
#define H_  16
#define HD_ 64
#define EPSV 1e-5f

// ================= scratch (static device globals) =================
__device__ float g_x  [B_*KQ*D_];
__device__ f16   g_biasc[B_*KQ*SQ];

__device__ f16 g_lnq [B_*KQ*D_];
__device__ f16 g_lnkv[B_*SQ*D_];
__device__ f16 g_Qh[B_*KQ*D_];
__device__ f16 g_Kh[B_*SQ*D_];
__device__ f16 g_Vh[B_*SQ*D_];
__device__ f16 g_att[B_*KQ*D_];
__device__ f16 g_h1 [B_*KQ*2*D_];
__device__ f16 g_wqt[D_*D_];
__device__ f16 g_wkt[D_*D_];
__device__ f16 g_wvt[D_*D_];
__device__ f16 g_wot[D_*D_];
__device__ f16 g_w1t[2*D_*D_];
__device__ f16 g_w2t[2*D_*D_];

__device__ __forceinline__ float softplus_f(float x) {
    return fmaxf(x, 0.f) + log1pf(__expf(-fabsf(x)));
}
__device__ __forceinline__ float gelu_f(float x) {
    return 0.5f * x * (1.f + erff(x * 0.70710678118654752f));
}
__device__ __forceinline__ uint32_t smem_to_u32(const void* p) {
    uint32_t a;
    asm("{ .reg .u64 t; cvta.to.shared.u64 t, %1; cvt.u32.u64 %0, t; }" : "=r"(a) : "l"(p));
    return a;
}
__device__ __forceinline__ uint32_t cvt2_f16(float lo, float hi) {
    uint32_t r; asm("cvt.rn.f16x2.f32 %0, %1, %2;" : "=r"(r) : "f"(hi), "f"(lo)); return r;
}
__device__ __forceinline__ uint32_t ex2_h2(uint32_t t) {
    uint32_t r; asm("ex2.approx.f16x2 %0, %1;" : "=r"(r) : "r"(t)); return r;
}

// cp.async helpers
#define CP_ASYNC16(dst, src) \
    asm volatile("cp.async.cg.shared.global [%0], [%1], 16;" :: "r"(dst), "l"(src))
#define CP_COMMIT() asm volatile("cp.async.commit_group;" ::: "memory")
#define CP_WAIT3()  asm volatile("cp.async.wait_group 3;" ::: "memory")
#define CP_WAIT2()  asm volatile("cp.async.wait_group 2;" ::: "memory")
#define CP_WAIT1()  asm volatile("cp.async.wait_group 1;" ::: "memory")
#define CP_WAIT0()  asm volatile("cp.async.wait_group 0;" ::: "memory")

#define LDSM_X4(r0, r1, r2, r3, addr) \
    asm volatile("ldmatrix.sync.aligned.m8n8.x4.shared.b16 {%0,%1,%2,%3}, [%4];" \
        : "=r"(r0), "=r"(r1), "=r"(r2), "=r"(r3) : "r"(addr))
#define LDSM_X4_T(r0, r1, r2, r3, addr) \
    asm volatile("ldmatrix.sync.aligned.m8n8.x4.trans.shared.b16 {%0,%1,%2,%3}, [%4];" \
        : "=r"(r0), "=r"(r1), "=r"(r2), "=r"(r3) : "r"(addr))

#define MMA_16816(c, a, b) \
    asm volatile("mma.sync.aligned.m16n8k16.row.col.f32.f16.f16.f32 " \
        "{%0,%1,%2,%3}, {%4,%5,%6,%7}, {%8,%9}, {%0,%1,%2,%3};" \
        : "+f"((c)[0]), "+f"((c)[1]), "+f"((c)[2]), "+f"((c)[3]) \
        : "r"((a)[0]), "r"((a)[1]), "r"((a)[2]), "r"((a)[3]), "r"((b)[0]), "r"((b)[1]))

// ================= prep: weight transpose->fp16 + combined bias (f16) =========
struct PrepArgs {
    const float* wsrc[6];
    f16* wdst[6];
    int K[6]; int N[6];
    const float* ab; const float* ob; const float* pd; const float* po;
    f16* biasc;
};
__global__ void prep_k(PrepArgs a) {
    int z = blockIdx.z;
    int tx = threadIdx.x, ty = threadIdx.y;
    if (z < 6) {
        int Kd = a.K[z], Nd = a.N[z];
        int n0 = blockIdx.x * 32, k0 = blockIdx.y * 32;
        if (n0 >= Nd || k0 >= Kd) return;
        __shared__ float t[32][33];
        const float* s = a.wsrc[z];
#pragma unroll
        for (int i = 0; i < 4; i++)
            t[ty + i*8][tx] = s[(size_t)(k0 + ty + i*8) * Nd + n0 + tx];
        __syncthreads();
#pragma unroll
        for (int i = 0; i < 4; i++) {
            float v = t[tx][ty + i*8];
            a.wdst[z][(size_t)(n0 + ty + i*8) * Kd + k0 + tx] = __float2half_rn(v);
        }
    } else {
        int cta = blockIdx.y * 64 + blockIdx.x;
        int tid = ty * 32 + tx;
        float spd = softplus_f(a.pd[0]);
        float spo = softplus_f(a.po[0]);
        size_t base = (size_t)cta * 512 + tid * 2;
#pragma unroll
        for (int j = 0; j < 2; j++) {
            float4 av = ((const float4*)a.ab)[base + j];
            float4 ov = ((const float4*)a.ob)[base + j];
            __half2 h0 = __floats2half2_rn(spd*av.x + spo*ov.x, spd*av.y + spo*ov.y);
            __half2 h1 = __floats2half2_rn(spd*av.z + spo*ov.z, spd*av.w + spo*ov.w);
            ((__half2*)a.biasc)[(base + j)*2 + 0] = h0;
            ((__half2*)a.biasc)[(base + j)*2 + 1] = h1;
        }
    }
}

// ================= LayerNorm -> fp16 =================
__device__ __forceinline__ void ln_body(const float* xr, const float* w, const float* bb,
                                        f16* yr) {
    __shared__ float r0[8], r1[8];
    __shared__ float mu_s, rs_s;
    int t = threadIdx.x;
    float v[4]; float s = 0.f, s2 = 0.f;
#pragma unroll
    for (int i = 0; i < 4; i++) { float a = xr[t + i*256]; v[i] = a; s += a; s2 += a*a; }
    int lane = t & 31, wp = t >> 5;
#pragma unroll
    for (int o = 16; o; o >>= 1) {
        s  += __shfl_xor_sync(0xffffffffu, s,  o);
        s2 += __shfl_xor_sync(0xffffffffu, s2, o);
    }
    if (lane == 0) { r0[wp] = s; r1[wp] = s2; }
    __syncthreads();
    if (t == 0) {
        float ts = 0.f, t2 = 0.f;
        for (int i = 0; i < 8; i++) { ts += r0[i]; t2 += r1[i]; }
        float mu = ts * (1.f / D_);
        float var = t2 * (1.f / D_) - mu * mu;
        mu_s = mu; rs_s = rsqrtf(var + EPSV);
    }
    __syncthreads();
    float mu = mu_s, rs = rs_s;
#pragma unroll
    for (int i = 0; i < 4; i++) {
        int c = t + i*256;
        yr[c] = __float2half_rn((v[i] - mu) * rs * w[c] + bb[c]);
    }
}

__global__ void ln_all_k(const float* __restrict__ q, const float* __restrict__ kv,
                         const float* __restrict__ wq, const float* __restrict__ bq,
                         const float* __restrict__ wkv, const float* __restrict__ bkv,
                         f16* __restrict__ oq, f16* __restrict__ okv) {
    int row = blockIdx.x;
    if (row < B_*KQ) ln_body(q + (size_t)row * D_, wq, bq, oq + (size_t)row * D_);
    else {
        row -= B_*KQ;
        ln_body(kv + (size_t)row * D_, wkv, bkv, okv + (size_t)row * D_);
    }
}

__global__ void ln_one_k(const float* __restrict__ x, const float* __restrict__ w,
                         const float* __restrict__ bb, f16* __restrict__ y) {
    int row = blockIdx.x;
    ln_body(x + (size_t)row * D_, w, bb, y + (size_t)row * D_);
}

// ================= HMMA fp16 GEMM core (single-pass) ==========
#define GPAD 40
#define GSTG 4
#define GABUF (128*GPAD)
#define GSTRIDE (2*GABUF*2)
#define GT_SMEM4 (GSTG*GSTRIDE)

__device__ __forceinline__ void gemm_core(
        int mode, char* gsm,
        const f16* __restrict__ Ag, const f16* __restrict__ Bg,
        const float* __restrict__ bias, const float* __restrict__ R,
        float* __restrict__ Cf, f16* __restrict__ Chi,
        int m0, int n0, int N, int Kd) {
    int tid = threadIdx.x, lane = tid & 31, wid = tid >> 5;
    int wm = wid & 3, wn = wid >> 2;
    uint32_t sbase = smem_to_u32(gsm);

    float c[2][8][4];
#pragma unroll
    for (int i = 0; i < 2; i++)
#pragma unroll
        for (int j = 0; j < 8; j++)
#pragma unroll
            for (int q = 0; q < 4; q++) c[i][j][q] = 0.f;

    int nch = Kd >> 5;
    int lr = tid >> 2;
    int ls = (tid & 3) << 3;

    auto prefetch = [&](int ch, int buf) {
        int kc = ch << 5;
        uint32_t st = sbase + (uint32_t)buf * GSTRIDE;
        uint32_t db = st + GABUF*2;
        CP_ASYNC16(st + (lr*GPAD + ls)*2,      Ag + (size_t)(m0 + lr)      * Kd + kc + ls);
        CP_ASYNC16(st + ((lr+64)*GPAD + ls)*2, Ag + (size_t)(m0 + lr + 64) * Kd + kc + ls);
        CP_ASYNC16(db + (lr*GPAD + ls)*2,      Bg + (size_t)(n0 + lr)      * Kd + kc + ls);
        CP_ASYNC16(db + ((lr+64)*GPAD + ls)*2, Bg + (size_t)(n0 + lr + 64) * Kd + kc + ls);
    };

#pragma unroll
    for (int s = 0; s < GSTG; s++) { prefetch(s, s); CP_COMMIT(); }

    for (int it = 0; it < nch; ++it) {
        int cur = it & (GSTG - 1);
        int rem = nch - 1 - it;
        if (rem >= 3) CP_WAIT3();
        else if (rem == 2) CP_WAIT2();
        else if (rem == 1) CP_WAIT1();
        else CP_WAIT0();
        __syncthreads();

        uint32_t st = sbase + (uint32_t)cur * GSTRIDE;
        uint32_t bb = st + GABUF*2;
#pragma unroll
        for (int kk = 0; kk < 32; kk += 16) {
            uint32_t a[2][4];
#pragma unroll
            for (int mi = 0; mi < 2; mi++) {
                int row = wm*32 + mi*16 + ((lane >> 3) & 1)*8 + (lane & 7);
                int col = kk + (lane >> 4)*8;
                LDSM_X4(a[mi][0], a[mi][1], a[mi][2], a[mi][3],
                        st + (uint32_t)(row*GPAD + col)*2);
            }
            uint32_t b[8][2];
#pragma unroll
            for (int g = 0; g < 4; g++) {
                int row = wn*64 + g*16 + (lane >> 4)*8 + (lane & 7);
                int col = kk + ((lane >> 3) & 1)*8;
                uint32_t r0, r1, r2, r3;
                LDSM_X4(r0, r1, r2, r3, bb + (uint32_t)(row*GPAD + col)*2);
                b[2*g][0] = r0; b[2*g][1] = r1;
                b[2*g+1][0] = r2; b[2*g+1][1] = r3;
            }
#pragma unroll
            for (int mi = 0; mi < 2; mi++)
#pragma unroll
                for (int ni = 0; ni < 8; ni++)
                    MMA_16816(c[mi][ni], a[mi], b[ni]);
        }
        __syncthreads();
        if (it + GSTG < nch) { prefetch(it + GSTG, cur); CP_COMMIT(); }
    }

#pragma unroll
    for (int mi = 0; mi < 2; mi++) {
#pragma unroll
        for (int half = 0; half < 2; half++) {
            int row = m0 + wm*32 + mi*16 + half*8 + (lane >> 2);
#pragma unroll
            for (int ni = 0; ni < 8; ni++) {
                int col = n0 + wn*64 + ni*8 + (lane & 3)*2;
                float v0 = c[mi][ni][half*2 + 0] + bias[col];
                float v1 = c[mi][ni][half*2 + 1] + bias[col + 1];
                size_t idx = (size_t)row * N + col;
                if (mode == 1) {
                    v0 = gelu_f(v0); v1 = gelu_f(v1);
                    *(uint32_t*)(Chi + idx) = cvt2_f16(v0, v1);
                } else if (mode == 4) {
                    *(uint32_t*)(Chi + idx) = cvt2_f16(v0, v1);
                } else {  // mode 2
                    float2 r2 = *(const float2*)(R + idx);
                    float2 o2; o2.x = v0 + r2.x; o2.y = v1 + r2.y;
                    *(float2*)(Cf + idx) = o2;
                }
            }
        }
    }
}

__global__ void __launch_bounds__(256, 2) gemm_g(
        int mode, const f16* Ag, const f16* Bg,
        const float* bias, const float* R,
        float* Cf, f16* Chi, int N, int Kd) {
    extern __shared__ char gsm[];
    gemm_core(mode, gsm, Ag, Bg, bias, R, Cf, Chi,
              blockIdx.y * 128, blockIdx.x * 128, N, Kd);
}

__global__ void __launch_bounds__(256, 2) qkv_k(
        const f16* lnq, const f16* lnkv,
        const f16* wq, const f16* wk, const f16* wv,
        const float* bq, const float* bk, const float* bv,
        f16* Qh, f16* Kh, f16* Vh) {
    extern __shared__ char gsm[];
    int y = blockIdx.y;
    const f16 *A, *Bw; const float* bias; f16 *Ch; int m0;
    if (y < 16)      { A = lnq;  Bw = wq; bias = bq; Ch = Qh; m0 = y * 128; }
    else if (y < 80) { A = lnkv; Bw = wk; bias = bk; Ch = Kh; m0 = (y - 16) * 128; }
    else             { A = lnkv; Bw = wv; bias = bv; Ch = Vh; m0 = (y - 80) * 128; }
    gemm_core(4, gsm, A, Bw, bias, nullptr, nullptr, Ch,
              m0, blockIdx.x * 128, D_, D_);
}

// ================= Flash attention: fixed-shift softmax, ex2.f16x2 ==========
// p = 2^((score-4)*log2e) unnormalized; l accumulated from realized f16 p.
#define NIT   (SQ/64)
#define APCH  144
#define AQ_H  0
#define AKV   (128*APCH)          // 18432
#define AKVARR (64*APCH)          // 9216 per array
#define AKVBUF (2*AKVARR)         // per stage (Kh,Vh)
#define ASTG  4
#define AGATE (AKV + ASTG*AKVBUF) // 92160
#define ATT_SMEM (AGATE + 512)

#define LOG2E 1.4426950408889634f
#define MSHIFT (-4.0f * LOG2E)

__global__ void __launch_bounds__(256, 2) attn_mma_k(
        const f16* __restrict__ Qhg,
        const f16* __restrict__ Khg,
        const f16* __restrict__ Vhg,
        const f16* __restrict__ bcp, const float* __restrict__ dens,
        const float* __restrict__ p_dens,
        f16* __restrict__ Oh) {
    extern __shared__ char smem[];
    uint32_t sb = smem_to_u32(smem);
    int tid = threadIdx.x, lane = tid & 31, w = tid >> 5;
    int qt = blockIdx.x, h = blockIdx.y, b = blockIdx.z;
    int q0 = qt * 128;
    size_t qrow0 = (size_t)(b * KQ + q0);
    size_t srow0 = (size_t)(b * SQ);
    int hoff = h * 64;

    // load Q tile 128x64 into smem
#pragma unroll
    for (int i = 0; i < 4; i++) {
        int idx = tid + i*256;
        int r = idx >> 3, cc = idx & 7;
        *(uint4*)(smem + AQ_H + r*APCH + cc*16) = *(const uint4*)(Qhg + (qrow0 + r)*D_ + hoff + cc*8);
    }
    if (tid < 128) {
        float* gp = (float*)(smem + AGATE);
        gp[tid] = 1.f + tanhf(p_dens[0]) * dens[b*KQ + q0 + tid];
    }

    auto pf = [&](int s0, int buf) {
        uint32_t base = sb + AKV + buf*AKVBUF;
#pragma unroll
        for (int j = 0; j < 2; j++) {
            int rem = tid + j*256;
            int row = rem >> 3, cc = rem & 7;
            size_t goff = (srow0 + s0 + row)*D_ + hoff + cc*8;
            uint32_t soff = (uint32_t)(row*APCH + cc*16);
            CP_ASYNC16(base + 0*AKVARR + soff, Khg + goff);
            CP_ASYNC16(base + 1*AKVARR + soff, Vhg + goff);
        }
    };
    pf(0, 0);   CP_COMMIT();
    pf(64, 1);  CP_COMMIT();
    pf(128, 2); CP_COMMIT();
    pf(192, 3); CP_COMMIT();
    __syncthreads();   // Q tile + gate visible

    // preload Q fragments into registers (constant across iterations)
    uint32_t qf[4][4];
#pragma unroll
    for (int ki = 0; ki < 4; ki++) {
        uint32_t qaddr = sb + AQ_H + (uint32_t)((w*16 + (lane & 15))*APCH + (ki*16 + (lane >> 4)*8)*2);
        LDSM_X4(qf[ki][0], qf[ki][1], qf[ki][2], qf[ki][3], qaddr);
    }
    int r0 = w*16 + (lane >> 2), r1 = r0 + 8;
    float g0, g1;
    {
        float* gp = (float*)(smem + AGATE);
        g0 = gp[r0]; g1 = gp[r1];
    }
    // per-row constants: t = c*ga + (b*gb + MSHIFT)
    float ga0 = g0 * 0.125f * LOG2E, gb0 = g0 * LOG2E;
    float ga1 = g1 * 0.125f * LOG2E, gb1 = g1 * LOG2E;

    float o[8][4];
#pragma unroll
    for (int i = 0; i < 8; i++)
#pragma unroll
        for (int j = 0; j < 4; j++) o[i][j] = 0.f;
    float2 l0f = {0.f, 0.f}, l1f = {0.f, 0.f};
    const f16* bp0 = bcp + (qrow0 + r0)*SQ + (lane & 3)*2;
    const f16* bp1 = bcp + (qrow0 + r1)*SQ + (lane & 3)*2;
    int cur = 0;

    for (int it = 0; it < NIT; it++) {
        int rem = NIT - 1 - it;
        if (rem >= 3) CP_WAIT3();
        else if (rem == 2) CP_WAIT2();
        else if (rem == 1) CP_WAIT1();
        else CP_WAIT0();
        __syncthreads();
        uint32_t kvb = sb + AKV + cur*AKVBUF;

#pragma unroll
        for (int sc = 0; sc < 4; sc++) {   // s-chunks of 16
            // ---- S chunk = Qh Kh ----
            float c2[2][4];
#pragma unroll
            for (int i = 0; i < 2; i++)
#pragma unroll
                for (int j = 0; j < 4; j++) c2[i][j] = 0.f;
#pragma unroll
            for (int ki = 0; ki < 4; ki++) {
                uint32_t kf[4];
                uint32_t kaddr = kvb + (uint32_t)((sc*16 + (lane & 15))*APCH + (ki*16 + (lane >> 4)*8)*2);
                LDSM_X4(kf[0], kf[1], kf[2], kf[3], kaddr);
                uint32_t B0[2] = { kf[0], kf[2] };
                uint32_t B1[2] = { kf[1], kf[3] };
                MMA_16816(c2[0], qf[ki], B0);
                MMA_16816(c2[1], qf[ki], B1);
            }
            // ---- bias + gate -> log2 domain -> ex2.f16x2 ----
            uint32_t pa[4];
#pragma unroll
            for (int half = 0; half < 2; half++) {
                int cb = it*64 + sc*16 + half*8;
                uint32_t u0 = *(const uint32_t*)(bp0 + cb);
                uint32_t u1 = *(const uint32_t*)(bp1 + cb);
                float2 b0 = __half22float2(*(const __half2*)&u0);
                float2 b1 = __half22float2(*(const __half2*)&u1);
                float t00 = fminf(fmaf(c2[half][0], ga0, fmaf(b0.x, gb0, MSHIFT)), 15.5f);
                float t01 = fminf(fmaf(c2[half][1], ga0, fmaf(b0.y, gb0, MSHIFT)), 15.5f);
                float t10 = fminf(fmaf(c2[half][2], ga1, fmaf(b1.x, gb1, MSHIFT)), 15.5f);
                float t11 = fminf(fmaf(c2[half][3], ga1, fmaf(b1.y, gb1, MSHIFT)), 15.5f);
                uint32_t p0 = ex2_h2(cvt2_f16(t00, t01));
                uint32_t p1 = ex2_h2(cvt2_f16(t10, t11));
                pa[half*2]     = p0;
                pa[half*2 + 1] = p1;
                float2 e0 = __half22float2(*(const __half2*)&p0);
                float2 e1 = __half22float2(*(const __half2*)&p1);
                l0f.x += e0.x; l0f.y += e0.y;
                l1f.x += e1.x; l1f.y += e1.y;
            }
            // ---- O += P V for this s-chunk ----
#pragma unroll
            for (int db = 0; db < 4; db++) {
                uint32_t vaddr = kvb + 1*AKVARR +
                    (uint32_t)((sc*16 + ((lane >> 3) & 1)*8 + (lane & 7))*APCH + (db*16 + (lane >> 4)*8)*2);
                uint32_t vh4[4];
                LDSM_X4_T(vh4[0], vh4[1], vh4[2], vh4[3], vaddr);
                uint32_t B0[2] = { vh4[0], vh4[1] };
                uint32_t B1[2] = { vh4[2], vh4[3] };
                MMA_16816(o[db*2],     pa, B0);
                MMA_16816(o[db*2 + 1], pa, B1);
            }
        }
        __syncthreads();
        if (it + ASTG < NIT) { pf((it + ASTG)*64, cur); CP_COMMIT(); }
        cur = (cur + 1) & (ASTG - 1);
    }

    // ---- epilogue: reduce l across the quad, normalize, store ----
    float l0 = l0f.x + l0f.y, l1 = l1f.x + l1f.y;
    l0 += __shfl_xor_sync(0xffffffffu, l0, 1);
    l0 += __shfl_xor_sync(0xffffffffu, l0, 2);
    l1 += __shfl_xor_sync(0xffffffffu, l1, 1);
    l1 += __shfl_xor_sync(0xffffffffu, l1, 2);
    float inv0 = 1.f / l0, inv1 = 1.f / l1;
#pragma unroll
    for (int nf = 0; nf < 8; nf++) {
        int d = nf*8 + (lane & 3)*2;
        size_t i0 = (qrow0 + r0)*D_ + hoff + d;
        size_t i1 = (qrow0 + r1)*D_ + hoff + d;
        *(uint32_t*)(Oh + i0) = cvt2_f16(o[nf][0]*inv0, o[nf][1]*inv0);
        *(uint32_t*)(Oh + i1) = cvt2_f16(o[nf][2]*inv1, o[nf][3]*inv1);
    }
}

// ================= launch =================
extern "C" void kernel_launch(void* const* d_in, const int* in_sizes, int n_in,
                              void* d_out, int out_size) {
    const float* q        = (const float*)d_in[0];
    const float* kv       = (const float*)d_in[1];
    const float* attn_b   = (const float*)d_in[2];
    const float* obs_b    = (const float*)d_in[3];
    const float* density  = (const float*)d_in[4];
    const float* ln_q_w   = (const float*)d_in[5];
    const float* ln_q_b   = (const float*)d_in[6];
    const float* ln_kv_w  = (const float*)d_in[7];
    const float* ln_kv_b  = (const float*)d_in[8];
    const float* wq = (const float*)d_in[9];  const float* bq = (const float*)d_in[10];
    const float* wk = (const float*)d_in[11]; const float* bk = (const float*)d_in[12];
    const float* wv = (const float*)d_in[13]; const float* bv = (const float*)d_in[14];
    const float* wo = (const float*)d_in[15]; const float* bo = (const float*)d_in[16];
    const float* dist_raw = (const float*)d_in[17];
    const float* obs_raw  = (const float*)d_in[18];
    const float* dens_raw = (const float*)d_in[19];
    const float* ln_f_w = (const float*)d_in[20]; const float* ln_f_b = (const float*)d_in[21];
    const float* w1 = (const float*)d_in[22]; const float* b1 = (const float*)d_in[23];
    const float* w2 = (const float*)d_in[24]; const float* b2 = (const float*)d_in[25];
    float* out = (float*)d_out;

    float *x;
    f16 *biasc;
    cudaGetSymbolAddress((void**)&x,   g_x);
    cudaGetSymbolAddress((void**)&biasc, g_biasc);
    f16 *lnq, *lnkv, *att, *h1, *Qh, *Kh, *Vh;
    cudaGetSymbolAddress((void**)&lnq,  g_lnq);
    cudaGetSymbolAddress((void**)&lnkv, g_lnkv);
    cudaGetSymbolAddress((void**)&att,  g_att);
    cudaGetSymbolAddress((void**)&h1,   g_h1);
    cudaGetSymbolAddress((void**)&Qh, g_Qh);
    cudaGetSymbolAddress((void**)&Kh, g_Kh);
    cudaGetSymbolAddress((void**)&Vh, g_Vh);
    f16 *wt[6];
    cudaGetSymbolAddress((void**)&wt[0], g_wqt);
    cudaGetSymbolAddress((void**)&wt[1], g_wkt);
    cudaGetSymbolAddress((void**)&wt[2], g_wvt);
    cudaGetSymbolAddress((void**)&wt[3], g_wot);
    cudaGetSymbolAddress((void**)&wt[4], g_w1t);
    cudaGetSymbolAddress((void**)&wt[5], g_w2t);

    cudaFuncSetAttribute(gemm_g,     cudaFuncAttributeMaxDynamicSharedMemorySize, GT_SMEM4);
    cudaFuncSetAttribute(qkv_k,      cudaFuncAttributeMaxDynamicSharedMemorySize, GT_SMEM4);
    cudaFuncSetAttribute(attn_mma_k, cudaFuncAttributeMaxDynamicSharedMemorySize, ATT_SMEM);

    // [0] prep: weight transpose -> fp16 + combined bias (f16)
    PrepArgs pa;
    pa.wsrc[0] = wq; pa.wsrc[1] = wk; pa.wsrc[2] = wv; pa.wsrc[3] = wo; pa.wsrc[4] = w1; pa.wsrc[5] = w2;
    for (int i = 0; i < 6; i++) pa.wdst[i] = wt[i];
    pa.K[0]=1024; pa.K[1]=1024; pa.K[2]=1024; pa.K[3]=1024; pa.K[4]=1024; pa.K[5]=2048;
    pa.N[0]=1024; pa.N[1]=1024; pa.N[2]=1024; pa.N[3]=1024; pa.N[4]=2048; pa.N[5]=1024;
    pa.ab = attn_b; pa.ob = obs_b; pa.pd = dist_raw; pa.po = obs_raw; pa.biasc = biasc;
    prep_k<<<dim3(64, 64, 7), dim3(32, 8)>>>(pa);

    // [1] both input LayerNorms -> fp16
    ln_all_k<<<B_*(KQ + SQ), 256>>>(q, kv, ln_q_w, ln_q_b, ln_kv_w, ln_kv_b, lnq, lnkv);

    // [2] fused Q/K/V projections
    qkv_k<<<dim3(8, 144), 256, GT_SMEM4>>>(lnq, lnkv, wt[0], wt[1], wt[2],
                                           bq, bk, bv, Qh, Kh, Vh);

    // [3] flash attention -> att fp16   (captured by ncu)
    attn_mma_k<<<dim3(KQ/128, H_, B_), 256, ATT_SMEM>>>(
        Qh, Kh, Vh, biasc, density, dens_raw, att);

    // [4] O projection + residual: x = q + att @ wo + bo
    gemm_g<<<dim3(8, 16), 256, GT_SMEM4>>>(2, att, wt[3], bo, q, x, nullptr, D_, D_);

    // [5] final LN
    ln_one_k<<<B_*KQ, 256>>>(x, ln_f_w, ln_f_b, lnq);

    // [6] MLP1 with GELU -> h1 fp16
    gemm_g<<<dim3(16, 16), 256, GT_SMEM4>>>(1, lnq, wt[4], b1, nullptr, nullptr, h1, 2*D_, D_);

    // [7] MLP2 + residual -> out
    gemm_g<<<dim3(8, 16), 256, GT_SMEM4>>>(2, h1, wt[5], b2, x, out, nullptr, D_, 2*D_);
}